// round 1
// baseline (speedup 1.0000x reference)
#include <cuda_runtime.h>
#include <math.h>

#define HW 784
#define EPS 1e-5f

// ---------------- scratch (device globals; no allocation) ----------------
__device__ float g_out[64 * 64 * HW];      // bn1(conv_down(x))
__device__ float g_S[8 * 64 * HW];         // sum over T frames
__device__ float g_off3[56 * 18 * HW];
__device__ float g_off5[56 * 50 * HW];
__device__ float g_d[56 * 64 * HW];        // d3 then += d5
__device__ float g_tstats[3 * 8 * 64 * 9]; // region-sum stats
__device__ float g_cats[64 * 64];          // per (cat-frame, channel) spatial SUM
__device__ float g_gate[64 * 256];         // 1 + gate

// ---------------- K0: zero the reduction buffer ----------------
__global__ void k_init() {
    int i = blockIdx.x * 256 + threadIdx.x;
    if (i < 64 * 64) g_cats[i] = 0.f;
}

// ---------------- K1: 1x1 conv 256->64 + bn1 (tiled GEMM) ----------------
__global__ void k_down(const float* __restrict__ x, const float* __restrict__ wd,
                       const float* __restrict__ bd, const float* __restrict__ g1,
                       const float* __restrict__ b1, const float* __restrict__ m1,
                       const float* __restrict__ v1) {
    __shared__ float As[32 * 64];
    __shared__ float Bs[32 * 68];
    int nt = blockIdx.x, p0 = blockIdx.y * 64;
    int tid = threadIdx.x, r = tid >> 4, c = tid & 15;
    float acc[4][4] = {};
    const float* xb = x + (size_t)nt * 256 * HW;
    for (int kc = 0; kc < 256; kc += 32) {
        for (int i = tid; i < 2048; i += 256) {
            int kk = i & 31, co = i >> 5;
            As[kk * 64 + co] = wd[co * 256 + kc + kk];
        }
        for (int i = tid; i < 2048; i += 256) {
            int kk = i >> 6, px = i & 63, p = p0 + px;
            Bs[kk * 68 + px] = (p < HW) ? xb[(kc + kk) * HW + p] : 0.f;
        }
        __syncthreads();
#pragma unroll
        for (int kk = 0; kk < 32; kk++) {
            float a[4], b[4];
#pragma unroll
            for (int i = 0; i < 4; i++) a[i] = As[kk * 64 + r * 4 + i];
#pragma unroll
            for (int j = 0; j < 4; j++) b[j] = Bs[kk * 68 + c * 4 + j];
#pragma unroll
            for (int i = 0; i < 4; i++)
#pragma unroll
                for (int j = 0; j < 4; j++) acc[i][j] += a[i] * b[j];
        }
        __syncthreads();
    }
#pragma unroll
    for (int i = 0; i < 4; i++) {
        int co = r * 4 + i;
        float sc = g1[co] * rsqrtf(v1[co] + EPS);
        float sh = (bd[co] - m1[co]) * sc + b1[co];
#pragma unroll
        for (int j = 0; j < 4; j++) {
            int p = p0 + c * 4 + j;
            if (p < HW) g_out[((size_t)nt * 64 + co) * HW + p] = acc[i][j] * sc + sh;
        }
    }
}

// ---------------- K2: sum over T frames ----------------
__global__ void k_tsum() {
    int i = blockIdx.x * 256 + threadIdx.x;
    if (i >= 8 * 64 * HW) return;
    int p = i % HW, ci = (i / HW) % 64, b = i / (HW * 64);
    float s = 0.f;
#pragma unroll
    for (int t = 0; t < 8; t++) s += g_out[((size_t)(b * 8 + t) * 64 + ci) * HW + p];
    g_S[i] = s;
}

// ---------------- K3: border stats for region sums ----------------
__global__ void k_tstats() {
    int id = blockIdx.x;                 // 3*8*64 blocks of 32 threads
    int ci = id & 63, b = (id >> 6) & 7, s = id >> 9;
    const float* src;
    if (s == 0) src = &g_S[((size_t)b * 64 + ci) * HW];
    else src = &g_out[((size_t)(b * 8 + (s == 1 ? 0 : 7)) * 64 + ci) * HW];
    int lane = threadIdx.x;
    float t = 0, r0 = 0, r27 = 0, c0 = 0, c27 = 0;
    for (int p = lane; p < HW; p += 32) {
        float v = src[p];
        int y = p / 28, x = p % 28;
        t += v;
        if (y == 0) r0 += v;
        if (y == 27) r27 += v;
        if (x == 0) c0 += v;
        if (x == 27) c27 += v;
    }
#pragma unroll
    for (int o = 16; o; o >>= 1) {
        t += __shfl_down_sync(0xffffffffu, t, o);
        r0 += __shfl_down_sync(0xffffffffu, r0, o);
        r27 += __shfl_down_sync(0xffffffffu, r27, o);
        c0 += __shfl_down_sync(0xffffffffu, c0, o);
        c27 += __shfl_down_sync(0xffffffffu, c27, o);
    }
    if (lane == 0) {
        float* o = &g_tstats[(size_t)id * 9];
        o[0] = t; o[1] = r0; o[2] = r27; o[3] = c0; o[4] = c27;
        o[5] = src[0]; o[6] = src[27]; o[7] = src[27 * 28]; o[8] = src[27 * 28 + 27];
    }
}

// ---------------- K4: temporal branch -> gate contribution (slot 7) ----------------
__global__ void k_tgate(const float* __restrict__ tw, const float* __restrict__ tb,
                        const float* __restrict__ g, const float* __restrict__ bb,
                        const float* __restrict__ m, const float* __restrict__ v) {
    int b = blockIdx.x;       // 8
    int co = threadIdx.x;     // 64
    float acc = 0.f;
    for (int s = 0; s < 3; s++) {
        for (int ci = 0; ci < 64; ci++) {
            const float* st = &g_tstats[((size_t)(s * 8 + b) * 64 + ci) * 9];
            const float* w = &tw[((size_t)(co * 64 + ci) * 3) * 9]; // [dt][9]
#pragma unroll
            for (int k = 0; k < 9; k++) {
                int ky = k / 3, kx = k % 3;
                float rs = st[0];
                if (ky == 2) rs -= st[1];
                if (ky == 0) rs -= st[2];
                if (kx == 2) rs -= st[3];
                if (kx == 0) rs -= st[4];
                if (ky == 2 && kx == 2) rs += st[5];
                if (ky == 2 && kx == 0) rs += st[6];
                if (ky == 0 && kx == 2) rs += st[7];
                if (ky == 0 && kx == 0) rs += st[8];
                float we = (s == 0) ? (w[k] + w[9 + k] + w[18 + k])
                                    : (s == 1 ? -w[18 + k] : -w[k]);
                acc += we * rs;
            }
        }
    }
    float mean_raw = acc * (1.f / (8.f * 784.f));
    float val = mean_raw + tb[co];
    float sc = g[co] * rsqrtf(v[co] + EPS);
    float tm = (val - m[co]) * sc + bb[co];
    g_cats[(b * 8 + 7) * 64 + co] = tm * 784.f; // store as spatial SUM
}

// ---------------- K5: 3x3 conv 64->18 (offset field, pad 1) ----------------
__global__ void k_off3(const float* __restrict__ w, const float* __restrict__ bias) {
    __shared__ float As[32 * 32];
    __shared__ float Bs[32 * 68];
    int n = blockIdx.x, p0 = blockIdx.y * 64;
    int f = (n / 7) * 8 + (n % 7) + 1;
    const float* src = &g_out[(size_t)f * 64 * HW];
    int tid = threadIdx.x, r = tid >> 4, c = tid & 15;
    float acc[2][4] = {};
    for (int kc = 0; kc < 576; kc += 32) {
        for (int i = tid; i < 1024; i += 256) {
            int kk = i & 31, co = i >> 5;
            As[kk * 32 + co] = (co < 18) ? w[co * 576 + kc + kk] : 0.f;
        }
        for (int i = tid; i < 2048; i += 256) {
            int kk = i >> 6, px = i & 63, p = p0 + px;
            float vv = 0.f;
            if (p < HW) {
                int K = kc + kk, ci = K / 9, k = K % 9;
                int y = p / 28 + k / 3 - 1, xx = p % 28 + k % 3 - 1;
                if (y >= 0 && y < 28 && xx >= 0 && xx < 28) vv = src[ci * HW + y * 28 + xx];
            }
            Bs[kk * 68 + px] = vv;
        }
        __syncthreads();
#pragma unroll
        for (int kk = 0; kk < 32; kk++) {
            float a0 = As[kk * 32 + r * 2], a1 = As[kk * 32 + r * 2 + 1];
            float b[4];
#pragma unroll
            for (int j = 0; j < 4; j++) b[j] = Bs[kk * 68 + c * 4 + j];
#pragma unroll
            for (int j = 0; j < 4; j++) { acc[0][j] += a0 * b[j]; acc[1][j] += a1 * b[j]; }
        }
        __syncthreads();
    }
#pragma unroll
    for (int i = 0; i < 2; i++) {
        int co = r * 2 + i;
        if (co < 18)
#pragma unroll
            for (int j = 0; j < 4; j++) {
                int p = p0 + c * 4 + j;
                if (p < HW) g_off3[((size_t)n * 18 + co) * HW + p] = acc[i][j] + bias[co];
            }
    }
}

// ---------------- K6: 5x5 conv 64->50 (offset field, pad 2) ----------------
__global__ void k_off5(const float* __restrict__ w, const float* __restrict__ bias) {
    __shared__ float As[32 * 64];
    __shared__ float Bs[32 * 68];
    int n = blockIdx.x, p0 = blockIdx.y * 64;
    int f = (n / 7) * 8 + (n % 7) + 1;
    const float* src = &g_out[(size_t)f * 64 * HW];
    int tid = threadIdx.x, r = tid >> 4, c = tid & 15;
    float acc[4][4] = {};
    for (int kc = 0; kc < 1600; kc += 32) {
        for (int i = tid; i < 2048; i += 256) {
            int kk = i & 31, co = i >> 5;
            As[kk * 64 + co] = (co < 50) ? w[co * 1600 + kc + kk] : 0.f;
        }
        for (int i = tid; i < 2048; i += 256) {
            int kk = i >> 6, px = i & 63, p = p0 + px;
            float vv = 0.f;
            if (p < HW) {
                int K = kc + kk, ci = K / 25, k = K % 25;
                int y = p / 28 + k / 5 - 2, xx = p % 28 + k % 5 - 2;
                if (y >= 0 && y < 28 && xx >= 0 && xx < 28) vv = src[ci * HW + y * 28 + xx];
            }
            Bs[kk * 68 + px] = vv;
        }
        __syncthreads();
#pragma unroll
        for (int kk = 0; kk < 32; kk++) {
            float a[4], b[4];
#pragma unroll
            for (int i = 0; i < 4; i++) a[i] = As[kk * 64 + r * 4 + i];
#pragma unroll
            for (int j = 0; j < 4; j++) b[j] = Bs[kk * 68 + c * 4 + j];
#pragma unroll
            for (int i = 0; i < 4; i++)
#pragma unroll
                for (int j = 0; j < 4; j++) acc[i][j] += a[i] * b[j];
        }
        __syncthreads();
    }
#pragma unroll
    for (int i = 0; i < 4; i++) {
        int co = r * 4 + i;
        if (co < 50)
#pragma unroll
            for (int j = 0; j < 4; j++) {
                int p = p0 + c * 4 + j;
                if (p < HW) g_off5[((size_t)n * 50 + co) * HW + p] = acc[i][j] + bias[co];
            }
    }
}

// ---------------- K7/K8: deformable conv (bilinear im2col GEMM) ----------------
template <int KS, bool ACC>
__global__ void k_deform(const float* __restrict__ dw) {
    constexpr int K2 = KS * KS, PAD = KS / 2, KTOT = K2 * 64;
    __shared__ float As[32 * 64];
    __shared__ float Bs[32 * 68];
    __shared__ float bwv[64][4];
    __shared__ int bix[64][4];
    int n = blockIdx.x, p0 = blockIdx.y * 64;
    int f = (n / 7) * 8 + (n % 7) + 1;
    const float* src = &g_out[(size_t)f * 64 * HW];
    const float* off = (KS == 3 ? g_off3 : g_off5) + (size_t)n * (2 * K2) * HW;
    int tid = threadIdx.x, r = tid >> 4, c = tid & 15;
    float acc[4][4] = {};
    int kprev = -1;
    for (int kc = 0; kc < KTOT; kc += 32) {
        int k = kc >> 6, ci0 = kc & 63;
        if (k != kprev) {
            if (tid < 64) {
                int p = p0 + tid;
                float py = -100.f, pxx = -100.f;
                if (p < HW) {
                    int y = p / 28, xq = p % 28;
                    py = (float)(y + k / KS - PAD) + off[(size_t)(2 * k) * HW + p];
                    pxx = (float)(xq + k % KS - PAD) + off[(size_t)(2 * k + 1) * HW + p];
                }
                float fy = floorf(py), fx = floorf(pxx);
                int y0 = (int)fy, x0 = (int)fx;
                float ly = py - fy, lx = pxx - fx;
#pragma unroll
                for (int t = 0; t < 4; t++) {
                    int iy = y0 + (t >> 1), ix = x0 + (t & 1);
                    float wt = ((t >> 1) ? ly : 1.f - ly) * ((t & 1) ? lx : 1.f - lx);
                    bool valid = (iy >= 0) && (iy < 28) && (ix >= 0) && (ix < 28);
                    bwv[tid][t] = valid ? wt : 0.f;
                    int cy = min(max(iy, 0), 27), cx = min(max(ix, 0), 27);
                    bix[tid][t] = cy * 28 + cx;
                }
            }
            kprev = k;
            __syncthreads();
        }
        for (int i = tid; i < 2048; i += 256) {
            int kk = i & 31, co = i >> 5;
            As[kk * 64 + co] = dw[((size_t)co * 64 + (ci0 + kk)) * K2 + k];
        }
        for (int i = tid; i < 2048; i += 256) {
            int kk = i >> 6, px = i & 63, ci = ci0 + kk;
            const float* sc = src + ci * HW;
            Bs[kk * 68 + px] = bwv[px][0] * sc[bix[px][0]] + bwv[px][1] * sc[bix[px][1]] +
                               bwv[px][2] * sc[bix[px][2]] + bwv[px][3] * sc[bix[px][3]];
        }
        __syncthreads();
#pragma unroll
        for (int kk = 0; kk < 32; kk++) {
            float a[4], b[4];
#pragma unroll
            for (int i = 0; i < 4; i++) a[i] = As[kk * 64 + r * 4 + i];
#pragma unroll
            for (int j = 0; j < 4; j++) b[j] = Bs[kk * 68 + c * 4 + j];
#pragma unroll
            for (int i = 0; i < 4; i++)
#pragma unroll
                for (int j = 0; j < 4; j++) acc[i][j] += a[i] * b[j];
        }
        __syncthreads();
    }
#pragma unroll
    for (int i = 0; i < 4; i++) {
        int co = r * 4 + i;
#pragma unroll
        for (int j = 0; j < 4; j++) {
            int p = p0 + c * 4 + j;
            if (p < HW) {
                size_t idx = ((size_t)n * 64 + co) * HW + p;
                if (ACC) g_d[idx] += acc[i][j]; else g_d[idx] = acc[i][j];
            }
        }
    }
}

// ---------------- K9: maxpool + 1x1 conv + bn3 + |diff| spatial reduce ----------------
__global__ void k_davg(const float* __restrict__ w1, const float* __restrict__ b1,
                       const float* __restrict__ g3, const float* __restrict__ bb3,
                       const float* __restrict__ m3, const float* __restrict__ v3) {
    __shared__ float MP[64 * 68];
    int n = blockIdx.x, p0 = blockIdx.y * 64;
    int b = n / 7, t = n % 7;
    int f = b * 8 + t + 1, fp = b * 8 + t;
    const float* src = &g_out[(size_t)f * 64 * HW];
    const float* pre = &g_out[(size_t)fp * 64 * HW];
    int tid = threadIdx.x;
    for (int i = tid; i < 4096; i += 256) {
        int ci = i >> 6, px = i & 63, p = p0 + px;
        float mv = 0.f;
        if (p < HW) {
            int y = p / 28, x = p % 28;
            const float* s = src + ci * HW;
            mv = -1e30f;
            for (int dy = -1; dy <= 1; dy++) {
                int yy = y + dy;
                if (yy < 0 || yy >= 28) continue;
                for (int dx = -1; dx <= 1; dx++) {
                    int xx = x + dx;
                    if (xx < 0 || xx >= 28) continue;
                    mv = fmaxf(mv, s[yy * 28 + xx]);
                }
            }
        }
        MP[ci * 68 + px] = mv;
    }
    __syncthreads();
    int r = tid >> 4, c = tid & 15;
    float acc[4][4] = {};
    for (int ci = 0; ci < 64; ci++) {
        float a[4], bv[4];
#pragma unroll
        for (int i = 0; i < 4; i++) a[i] = w1[(r * 4 + i) * 64 + ci];
#pragma unroll
        for (int j = 0; j < 4; j++) bv[j] = MP[ci * 68 + c * 4 + j];
#pragma unroll
        for (int i = 0; i < 4; i++)
#pragma unroll
            for (int j = 0; j < 4; j++) acc[i][j] += a[i] * bv[j];
    }
    float sums[4];
#pragma unroll
    for (int i = 0; i < 4; i++) {
        int co = r * 4 + i;
        float sc = g3[co] * rsqrtf(v3[co] + EPS);
        float sh = (b1[co] - m3[co]) * sc + bb3[co];
        float s = 0.f;
#pragma unroll
        for (int j = 0; j < 4; j++) {
            int p = p0 + c * 4 + j;
            if (p < HW) {
                float davg = acc[i][j] * sc + sh;
                s += fabsf(g_d[((size_t)n * 64 + co) * HW + p] + davg - 3.f * pre[co * HW + p]);
            }
        }
        sums[i] = s;
    }
#pragma unroll
    for (int o = 8; o; o >>= 1)
#pragma unroll
        for (int i = 0; i < 4; i++) sums[i] += __shfl_down_sync(0xffffffffu, sums[i], o);
    if (c == 0)
#pragma unroll
        for (int i = 0; i < 4; i++) atomicAdd(&g_cats[(b * 8 + t) * 64 + r * 4 + i], sums[i]);
}

// ---------------- K10: gate ----------------
__global__ void k_gate(const float* __restrict__ cw, const float* __restrict__ cb,
                       const float* __restrict__ g2, const float* __restrict__ b2,
                       const float* __restrict__ m2, const float* __restrict__ v2) {
    int nt = blockIdx.x;
    int co = threadIdx.x; // 256
    __shared__ float mvec[64];
    if (co < 64) mvec[co] = g_cats[nt * 64 + co] * (1.f / 784.f);
    __syncthreads();
    float y = cb[co];
#pragma unroll 8
    for (int ci = 0; ci < 64; ci++) y += mvec[ci] * cw[co * 64 + ci];
    float sc = g2[co] * rsqrtf(v2[co] + EPS);
    y = (y - m2[co]) * sc + b2[co];
    float gate = 1.f / (1.f + expf(-y)) - 0.5f;
    g_gate[nt * 256 + co] = 1.f + gate;
}

// ---------------- K11: final elementwise ----------------
__global__ void k_final(const float* __restrict__ x, float* __restrict__ out) {
    int i = blockIdx.x * 256 + threadIdx.x;  // float4 index
    if (i >= 64 * 256 * (HW / 4)) return;
    int ch = i / (HW / 4);  // nt*256 + c
    float gm = g_gate[ch];
    const float4* x4 = (const float4*)x;
    float4 v = x4[i];
    v.x *= gm; v.y *= gm; v.z *= gm; v.w *= gm;
    ((float4*)out)[i] = v;
}

// ---------------- launch ----------------
extern "C" void kernel_launch(void* const* d_in, const int* in_sizes, int n_in,
                              void* d_out, int out_size) {
    const float* x = (const float*)d_in[0];
    const float* w_down = (const float*)d_in[1];
    const float* b_down = (const float*)d_in[2];
    const float* bn1_g = (const float*)d_in[3];
    const float* bn1_b = (const float*)d_in[4];
    const float* bn1_m = (const float*)d_in[5];
    const float* bn1_v = (const float*)d_in[6];
    const float* tconv_w = (const float*)d_in[7];
    const float* tconv_b = (const float*)d_in[8];
    const float* bnt_g = (const float*)d_in[9];
    const float* bnt_b = (const float*)d_in[10];
    const float* bnt_m = (const float*)d_in[11];
    const float* bnt_v = (const float*)d_in[12];
    const float* off3_w = (const float*)d_in[13];
    const float* off3_b = (const float*)d_in[14];
    const float* def3_w = (const float*)d_in[15];
    const float* off5_w = (const float*)d_in[16];
    const float* off5_b = (const float*)d_in[17];
    const float* def5_w = (const float*)d_in[18];
    const float* conv1_w = (const float*)d_in[19];
    const float* conv1_b = (const float*)d_in[20];
    const float* bn3_g = (const float*)d_in[21];
    const float* bn3_b = (const float*)d_in[22];
    const float* bn3_m = (const float*)d_in[23];
    const float* bn3_v = (const float*)d_in[24];
    const float* conv_w = (const float*)d_in[25];
    const float* conv_b = (const float*)d_in[26];
    const float* bn2_g = (const float*)d_in[27];
    const float* bn2_b = (const float*)d_in[28];
    const float* bn2_m = (const float*)d_in[29];
    const float* bn2_v = (const float*)d_in[30];
    float* out = (float*)d_out;

    k_init<<<16, 256>>>();
    k_down<<<dim3(64, 13), 256>>>(x, w_down, b_down, bn1_g, bn1_b, bn1_m, bn1_v);
    k_tsum<<<(8 * 64 * HW + 255) / 256, 256>>>();
    k_tstats<<<3 * 8 * 64, 32>>>();
    k_tgate<<<8, 64>>>(tconv_w, tconv_b, bnt_g, bnt_b, bnt_m, bnt_v);
    k_off3<<<dim3(56, 13), 256>>>(off3_w, off3_b);
    k_deform<3, false><<<dim3(56, 13), 256>>>(def3_w);
    k_off5<<<dim3(56, 13), 256>>>(off5_w, off5_b);
    k_deform<5, true><<<dim3(56, 13), 256>>>(def5_w);
    k_davg<<<dim3(56, 13), 256>>>(conv1_w, conv1_b, bn3_g, bn3_b, bn3_m, bn3_v);
    k_gate<<<64, 256>>>(conv_w, conv_b, bn2_g, bn2_b, bn2_m, bn2_v);
    k_final<<<(64 * 256 * (HW / 4) + 255) / 256, 256>>>(x, out);
}

// round 2
// speedup vs baseline: 1.7776x; 1.7776x over previous
#include <cuda_runtime.h>
#include <math.h>
#include <stdint.h>

#define HW 784
#define EPS 1e-5f
#define APAD 72    // A smem row stride (mod 32 == 8 -> conflict-free frag loads)
#define NPAD 136   // B smem row stride (mod 32 == 8)

// ---------------- scratch (device globals; no allocation) ----------------
__device__ float g_out[64 * 64 * HW];      // bn1(conv_down(x))
__device__ float g_S[8 * 64 * HW];         // sum over T frames
__device__ float g_off3[56 * 18 * HW];
__device__ float g_off5[56 * 50 * HW];
__device__ float g_d[56 * 64 * HW];        // d3 then += d5
__device__ float g_tstats[3 * 8 * 64 * 9]; // region-sum stats
__device__ float g_cats[64 * 64];          // per (cat-frame, channel) spatial SUM
__device__ float g_gate[64 * 256];         // 1 + gate

__device__ __forceinline__ float to_tf32(float x) {
    float y;
    asm("cvt.rna.tf32.f32 %0, %1;" : "=f"(y) : "f"(x));
    return y;
}

// ---- warp-mma core: one K-chunk of 32 (4 x k8) ----
// As: [32][APAD] k-major (As[k][m]); Bs: [32][NPAD] (Bs[k][n])
template <int MT, int NT>
__device__ __forceinline__ void mma_chunk(const float* As, const float* Bs,
                                          int lane, int wm, int wn,
                                          float (*acc)[NT][4]) {
    int g = lane >> 2, tg = lane & 3;
#pragma unroll
    for (int ks = 0; ks < 4; ks++) {
        const float* Ab = As + (ks * 8) * APAD;
        const float* Bb = Bs + (ks * 8) * NPAD;
        uint32_t a[MT][4], b[NT][2];
#pragma unroll
        for (int mt = 0; mt < MT; mt++) {
            int m = wm * (MT * 16) + mt * 16 + g;
            a[mt][0] = __float_as_uint(Ab[tg * APAD + m]);
            a[mt][1] = __float_as_uint(Ab[tg * APAD + m + 8]);
            a[mt][2] = __float_as_uint(Ab[(tg + 4) * APAD + m]);
            a[mt][3] = __float_as_uint(Ab[(tg + 4) * APAD + m + 8]);
        }
#pragma unroll
        for (int nt = 0; nt < NT; nt++) {
            int n = wn * (NT * 8) + nt * 8 + g;
            b[nt][0] = __float_as_uint(Bb[tg * NPAD + n]);
            b[nt][1] = __float_as_uint(Bb[(tg + 4) * NPAD + n]);
        }
#pragma unroll
        for (int mt = 0; mt < MT; mt++)
#pragma unroll
            for (int nt = 0; nt < NT; nt++)
                asm volatile(
                    "mma.sync.aligned.m16n8k8.row.col.f32.tf32.tf32.f32 "
                    "{%0,%1,%2,%3},{%4,%5,%6,%7},{%8,%9},{%0,%1,%2,%3};"
                    : "+f"(acc[mt][nt][0]), "+f"(acc[mt][nt][1]),
                      "+f"(acc[mt][nt][2]), "+f"(acc[mt][nt][3])
                    : "r"(a[mt][0]), "r"(a[mt][1]), "r"(a[mt][2]), "r"(a[mt][3]),
                      "r"(b[nt][0]), "r"(b[nt][1]));
    }
}

// ---------------- K0: zero the reduction buffer ----------------
__global__ void k_init() {
    int i = blockIdx.x * 256 + threadIdx.x;
    if (i < 64 * 64) g_cats[i] = 0.f;
}

// ---------------- K1: 1x1 conv 256->64 + bn1 (tf32 mma) ----------------
__global__ void k_down(const float* __restrict__ x, const float* __restrict__ wd,
                       const float* __restrict__ bd, const float* __restrict__ g1,
                       const float* __restrict__ b1, const float* __restrict__ m1,
                       const float* __restrict__ v1) {
    __shared__ float As[32 * APAD];
    __shared__ float Bs[32 * NPAD];
    int nt = blockIdx.x, p0 = blockIdx.y * 128;
    int tid = threadIdx.x, lane = tid & 31, w = tid >> 5, wm = w & 1, wn = w >> 1;
    float acc[2][4][4] = {};
    const float* xb = x + (size_t)nt * 256 * HW;
    for (int kc = 0; kc < 256; kc += 32) {
        for (int i = tid; i < 2048; i += 256) {
            int kk = i >> 6, m = i & 63;
            As[kk * APAD + m] = to_tf32(wd[m * 256 + kc + kk]);
        }
        for (int i = tid; i < 4096; i += 256) {
            int kk = i >> 7, n = i & 127, p = p0 + n;
            Bs[kk * NPAD + n] = (p < HW) ? to_tf32(xb[(kc + kk) * HW + p]) : 0.f;
        }
        __syncthreads();
        mma_chunk<2, 4>(As, Bs, lane, wm, wn, acc);
        __syncthreads();
    }
    int g = lane >> 2, tg = lane & 3;
#pragma unroll
    for (int mt = 0; mt < 2; mt++)
#pragma unroll
        for (int nq = 0; nq < 4; nq++) {
            int p = p0 + wn * 32 + nq * 8 + tg * 2;
            if (p >= HW) continue;
#pragma unroll
            for (int h = 0; h < 2; h++) {
                int co = wm * 32 + mt * 16 + g + h * 8;
                float sc = g1[co] * rsqrtf(v1[co] + EPS);
                float sh = (bd[co] - m1[co]) * sc + b1[co];
                float2 v;
                v.x = acc[mt][nq][h * 2] * sc + sh;
                v.y = acc[mt][nq][h * 2 + 1] * sc + sh;
                *(float2*)&g_out[((size_t)nt * 64 + co) * HW + p] = v;
            }
        }
}

// ---------------- K2: sum over T frames ----------------
__global__ void k_tsum() {
    int i = blockIdx.x * 256 + threadIdx.x;
    if (i >= 8 * 64 * HW) return;
    int p = i % HW, ci = (i / HW) % 64, b = i / (HW * 64);
    float s = 0.f;
#pragma unroll
    for (int t = 0; t < 8; t++) s += g_out[((size_t)(b * 8 + t) * 64 + ci) * HW + p];
    g_S[i] = s;
}

// ---------------- K3: border stats for region sums ----------------
__global__ void k_tstats() {
    int id = blockIdx.x;
    int ci = id & 63, b = (id >> 6) & 7, s = id >> 9;
    const float* src;
    if (s == 0) src = &g_S[((size_t)b * 64 + ci) * HW];
    else src = &g_out[((size_t)(b * 8 + (s == 1 ? 0 : 7)) * 64 + ci) * HW];
    int lane = threadIdx.x;
    float t = 0, r0 = 0, r27 = 0, c0 = 0, c27 = 0;
    for (int p = lane; p < HW; p += 32) {
        float v = src[p];
        int y = p / 28, x = p % 28;
        t += v;
        if (y == 0) r0 += v;
        if (y == 27) r27 += v;
        if (x == 0) c0 += v;
        if (x == 27) c27 += v;
    }
#pragma unroll
    for (int o = 16; o; o >>= 1) {
        t += __shfl_down_sync(0xffffffffu, t, o);
        r0 += __shfl_down_sync(0xffffffffu, r0, o);
        r27 += __shfl_down_sync(0xffffffffu, r27, o);
        c0 += __shfl_down_sync(0xffffffffu, c0, o);
        c27 += __shfl_down_sync(0xffffffffu, c27, o);
    }
    if (lane == 0) {
        float* o = &g_tstats[(size_t)id * 9];
        o[0] = t; o[1] = r0; o[2] = r27; o[3] = c0; o[4] = c27;
        o[5] = src[0]; o[6] = src[27]; o[7] = src[27 * 28]; o[8] = src[27 * 28 + 27];
    }
}

// ---------------- K4: temporal branch -> gate contribution (slot 7) ----------------
__global__ void k_tgate(const float* __restrict__ tw, const float* __restrict__ tb,
                        const float* __restrict__ g, const float* __restrict__ bb,
                        const float* __restrict__ m, const float* __restrict__ v) {
    int b = blockIdx.x;
    int co = threadIdx.x;
    float acc = 0.f;
    for (int s = 0; s < 3; s++) {
        for (int ci = 0; ci < 64; ci++) {
            const float* st = &g_tstats[((size_t)(s * 8 + b) * 64 + ci) * 9];
            const float* w = &tw[((size_t)(co * 64 + ci) * 3) * 9];
#pragma unroll
            for (int k = 0; k < 9; k++) {
                int ky = k / 3, kx = k % 3;
                float rs = st[0];
                if (ky == 2) rs -= st[1];
                if (ky == 0) rs -= st[2];
                if (kx == 2) rs -= st[3];
                if (kx == 0) rs -= st[4];
                if (ky == 2 && kx == 2) rs += st[5];
                if (ky == 2 && kx == 0) rs += st[6];
                if (ky == 0 && kx == 2) rs += st[7];
                if (ky == 0 && kx == 0) rs += st[8];
                float we = (s == 0) ? (w[k] + w[9 + k] + w[18 + k])
                                    : (s == 1 ? -w[18 + k] : -w[k]);
                acc += we * rs;
            }
        }
    }
    float mean_raw = acc * (1.f / (8.f * 784.f));
    float val = mean_raw + tb[co];
    float sc = g[co] * rsqrtf(v[co] + EPS);
    float tm = (val - m[co]) * sc + bb[co];
    g_cats[(b * 8 + 7) * 64 + co] = tm * 784.f;
}

// ---------------- K5: 3x3 conv 64->18 offset field (tf32 mma, M padded 32) --------
__global__ void k_off3(const float* __restrict__ w, const float* __restrict__ bias) {
    __shared__ float As[32 * APAD];
    __shared__ float Bs[32 * NPAD];
    int n = blockIdx.x, p0 = blockIdx.y * 128;
    int f = (n / 7) * 8 + (n % 7) + 1;
    const float* src = &g_out[(size_t)f * 64 * HW];
    int tid = threadIdx.x, lane = tid & 31, wn = tid >> 5;  // wm = 0
    float acc[2][2][4] = {};
    for (int kc = 0; kc < 576; kc += 32) {
        for (int i = tid; i < 1024; i += 256) {
            int kk = i >> 5, m = i & 31;
            As[kk * APAD + m] = (m < 18) ? to_tf32(w[m * 576 + kc + kk]) : 0.f;
        }
        for (int i = tid; i < 4096; i += 256) {
            int kk = i >> 7, px = i & 127, p = p0 + px;
            float vv = 0.f;
            if (p < HW) {
                int K = kc + kk, ci = K / 9, k = K % 9;
                int y = p / 28 + k / 3 - 1, xx = p % 28 + k % 3 - 1;
                if (y >= 0 && y < 28 && xx >= 0 && xx < 28) vv = to_tf32(src[ci * HW + y * 28 + xx]);
            }
            Bs[kk * NPAD + px] = vv;
        }
        __syncthreads();
        mma_chunk<2, 2>(As, Bs, lane, 0, wn, acc);
        __syncthreads();
    }
    int g = lane >> 2, tg = lane & 3;
#pragma unroll
    for (int mt = 0; mt < 2; mt++)
#pragma unroll
        for (int nq = 0; nq < 2; nq++) {
            int p = p0 + wn * 16 + nq * 8 + tg * 2;
            if (p >= HW) continue;
#pragma unroll
            for (int h = 0; h < 2; h++) {
                int co = mt * 16 + g + h * 8;
                if (co >= 18) continue;
                float2 v;
                v.x = acc[mt][nq][h * 2] + bias[co];
                v.y = acc[mt][nq][h * 2 + 1] + bias[co];
                *(float2*)&g_off3[((size_t)n * 18 + co) * HW + p] = v;
            }
        }
}

// ---------------- K6: 5x5 conv 64->50 offset field (tf32 mma, M padded 64) --------
__global__ void k_off5(const float* __restrict__ w, const float* __restrict__ bias) {
    __shared__ float As[32 * APAD];
    __shared__ float Bs[32 * NPAD];
    int n = blockIdx.x, p0 = blockIdx.y * 128;
    int f = (n / 7) * 8 + (n % 7) + 1;
    const float* src = &g_out[(size_t)f * 64 * HW];
    int tid = threadIdx.x, lane = tid & 31, wq = tid >> 5, wm = wq & 1, wn = wq >> 1;
    float acc[2][4][4] = {};
    for (int kc = 0; kc < 1600; kc += 32) {
        for (int i = tid; i < 2048; i += 256) {
            int kk = i >> 6, m = i & 63;
            As[kk * APAD + m] = (m < 50) ? to_tf32(w[m * 1600 + kc + kk]) : 0.f;
        }
        for (int i = tid; i < 4096; i += 256) {
            int kk = i >> 7, px = i & 127, p = p0 + px;
            float vv = 0.f;
            if (p < HW) {
                int K = kc + kk, ci = K / 25, k = K % 25;
                int y = p / 28 + k / 5 - 2, xx = p % 28 + k % 5 - 2;
                if (y >= 0 && y < 28 && xx >= 0 && xx < 28) vv = to_tf32(src[ci * HW + y * 28 + xx]);
            }
            Bs[kk * NPAD + px] = vv;
        }
        __syncthreads();
        mma_chunk<2, 4>(As, Bs, lane, wm, wn, acc);
        __syncthreads();
    }
    int g = lane >> 2, tg = lane & 3;
#pragma unroll
    for (int mt = 0; mt < 2; mt++)
#pragma unroll
        for (int nq = 0; nq < 4; nq++) {
            int p = p0 + wn * 32 + nq * 8 + tg * 2;
            if (p >= HW) continue;
#pragma unroll
            for (int h = 0; h < 2; h++) {
                int co = wm * 32 + mt * 16 + g + h * 8;
                if (co >= 50) continue;
                float2 v;
                v.x = acc[mt][nq][h * 2] + bias[co];
                v.y = acc[mt][nq][h * 2 + 1] + bias[co];
                *(float2*)&g_off5[((size_t)n * 50 + co) * HW + p] = v;
            }
        }
}

// ---------------- K7/K8: deformable conv (bilinear im2col + tf32 mma) -------------
template <int KS, bool ACC>
__global__ void k_deform(const float* __restrict__ dw) {
    constexpr int K2 = KS * KS, PAD = KS / 2, KTOT = K2 * 64;
    __shared__ float As[32 * APAD];
    __shared__ float Bs[32 * NPAD];
    __shared__ float bwv[128][4];
    __shared__ int bix[128][4];
    int n = blockIdx.x, p0 = blockIdx.y * 128;
    int f = (n / 7) * 8 + (n % 7) + 1;
    const float* src = &g_out[(size_t)f * 64 * HW];
    const float* off = (KS == 3 ? g_off3 : g_off5) + (size_t)n * (2 * K2) * HW;
    int tid = threadIdx.x, lane = tid & 31, wq = tid >> 5, wm = wq & 1, wn = wq >> 1;
    float acc[2][4][4] = {};
    int kprev = -1;
    for (int kc = 0; kc < KTOT; kc += 32) {
        int k = kc >> 6, ci0 = kc & 63;
        if (k != kprev) {
            if (tid < 128) {
                int p = p0 + tid;
                float py = -100.f, pxx = -100.f;
                if (p < HW) {
                    int y = p / 28, xq = p % 28;
                    py = (float)(y + k / KS - PAD) + off[(size_t)(2 * k) * HW + p];
                    pxx = (float)(xq + k % KS - PAD) + off[(size_t)(2 * k + 1) * HW + p];
                }
                float fy = floorf(py), fx = floorf(pxx);
                int y0 = (int)fy, x0 = (int)fx;
                float ly = py - fy, lx = pxx - fx;
#pragma unroll
                for (int t = 0; t < 4; t++) {
                    int iy = y0 + (t >> 1), ix = x0 + (t & 1);
                    float wt = ((t >> 1) ? ly : 1.f - ly) * ((t & 1) ? lx : 1.f - lx);
                    bool valid = (iy >= 0) && (iy < 28) && (ix >= 0) && (ix < 28);
                    bwv[tid][t] = valid ? wt : 0.f;
                    int cy = min(max(iy, 0), 27), cx = min(max(ix, 0), 27);
                    bix[tid][t] = cy * 28 + cx;
                }
            }
            kprev = k;
            __syncthreads();
        }
        for (int i = tid; i < 2048; i += 256) {
            int kk = i >> 6, m = i & 63;
            As[kk * APAD + m] = to_tf32(dw[((size_t)m * 64 + (ci0 + kk)) * K2 + k]);
        }
        for (int i = tid; i < 4096; i += 256) {
            int kk = i >> 7, px = i & 127, ci = ci0 + kk;
            const float* sc = src + ci * HW;
            float vv = bwv[px][0] * sc[bix[px][0]] + bwv[px][1] * sc[bix[px][1]] +
                       bwv[px][2] * sc[bix[px][2]] + bwv[px][3] * sc[bix[px][3]];
            Bs[kk * NPAD + px] = to_tf32(vv);
        }
        __syncthreads();
        mma_chunk<2, 4>(As, Bs, lane, wm, wn, acc);
        __syncthreads();
    }
    int g = lane >> 2, tg = lane & 3;
#pragma unroll
    for (int mt = 0; mt < 2; mt++)
#pragma unroll
        for (int nq = 0; nq < 4; nq++) {
            int p = p0 + wn * 32 + nq * 8 + tg * 2;
            if (p >= HW) continue;
#pragma unroll
            for (int h = 0; h < 2; h++) {
                int co = wm * 32 + mt * 16 + g + h * 8;
                size_t idx = ((size_t)n * 64 + co) * HW + p;
                float2 v;
                v.x = acc[mt][nq][h * 2];
                v.y = acc[mt][nq][h * 2 + 1];
                if (ACC) {
                    float2 o = *(float2*)&g_d[idx];
                    v.x += o.x; v.y += o.y;
                }
                *(float2*)&g_d[idx] = v;
            }
        }
}

// ---------------- K9: maxpool + 1x1 conv + bn3 + |diff| spatial reduce ------------
__global__ void k_davg(const float* __restrict__ w1, const float* __restrict__ b1,
                       const float* __restrict__ g3, const float* __restrict__ bb3,
                       const float* __restrict__ m3, const float* __restrict__ v3) {
    __shared__ float MP[64 * 68];
    int n = blockIdx.x, p0 = blockIdx.y * 64;
    int b = n / 7, t = n % 7;
    int f = b * 8 + t + 1, fp = b * 8 + t;
    const float* src = &g_out[(size_t)f * 64 * HW];
    const float* pre = &g_out[(size_t)fp * 64 * HW];
    int tid = threadIdx.x;
    for (int i = tid; i < 4096; i += 256) {
        int ci = i >> 6, px = i & 63, p = p0 + px;
        float mv = 0.f;
        if (p < HW) {
            int y = p / 28, x = p % 28;
            const float* s = src + ci * HW;
            mv = -1e30f;
            for (int dy = -1; dy <= 1; dy++) {
                int yy = y + dy;
                if (yy < 0 || yy >= 28) continue;
                for (int dx = -1; dx <= 1; dx++) {
                    int xx = x + dx;
                    if (xx < 0 || xx >= 28) continue;
                    mv = fmaxf(mv, s[yy * 28 + xx]);
                }
            }
        }
        MP[ci * 68 + px] = mv;
    }
    __syncthreads();
    int r = tid >> 4, c = tid & 15;
    float acc[4][4] = {};
    for (int ci = 0; ci < 64; ci++) {
        float a[4], bv[4];
#pragma unroll
        for (int i = 0; i < 4; i++) a[i] = w1[(r * 4 + i) * 64 + ci];
#pragma unroll
        for (int j = 0; j < 4; j++) bv[j] = MP[ci * 68 + c * 4 + j];
#pragma unroll
        for (int i = 0; i < 4; i++)
#pragma unroll
            for (int j = 0; j < 4; j++) acc[i][j] += a[i] * bv[j];
    }
    float sums[4];
#pragma unroll
    for (int i = 0; i < 4; i++) {
        int co = r * 4 + i;
        float sc = g3[co] * rsqrtf(v3[co] + EPS);
        float sh = (b1[co] - m3[co]) * sc + bb3[co];
        float s = 0.f;
#pragma unroll
        for (int j = 0; j < 4; j++) {
            int p = p0 + c * 4 + j;
            if (p < HW) {
                float davg = acc[i][j] * sc + sh;
                s += fabsf(g_d[((size_t)n * 64 + co) * HW + p] + davg - 3.f * pre[co * HW + p]);
            }
        }
        sums[i] = s;
    }
#pragma unroll
    for (int o = 8; o; o >>= 1)
#pragma unroll
        for (int i = 0; i < 4; i++) sums[i] += __shfl_down_sync(0xffffffffu, sums[i], o);
    if (c == 0)
#pragma unroll
        for (int i = 0; i < 4; i++) atomicAdd(&g_cats[(b * 8 + t) * 64 + r * 4 + i], sums[i]);
}

// ---------------- K10: gate ----------------
__global__ void k_gate(const float* __restrict__ cw, const float* __restrict__ cb,
                       const float* __restrict__ g2, const float* __restrict__ b2,
                       const float* __restrict__ m2, const float* __restrict__ v2) {
    int nt = blockIdx.x;
    int co = threadIdx.x;
    __shared__ float mvec[64];
    if (co < 64) mvec[co] = g_cats[nt * 64 + co] * (1.f / 784.f);
    __syncthreads();
    float y = cb[co];
#pragma unroll 8
    for (int ci = 0; ci < 64; ci++) y += mvec[ci] * cw[co * 64 + ci];
    float sc = g2[co] * rsqrtf(v2[co] + EPS);
    y = (y - m2[co]) * sc + b2[co];
    float gate = 1.f / (1.f + expf(-y)) - 0.5f;
    g_gate[nt * 256 + co] = 1.f + gate;
}

// ---------------- K11: final elementwise ----------------
__global__ void k_final(const float* __restrict__ x, float* __restrict__ out) {
    int i = blockIdx.x * 256 + threadIdx.x;
    if (i >= 64 * 256 * (HW / 4)) return;
    int ch = i / (HW / 4);
    float gm = g_gate[ch];
    const float4* x4 = (const float4*)x;
    float4 v = x4[i];
    v.x *= gm; v.y *= gm; v.z *= gm; v.w *= gm;
    ((float4*)out)[i] = v;
}

// ---------------- launch ----------------
extern "C" void kernel_launch(void* const* d_in, const int* in_sizes, int n_in,
                              void* d_out, int out_size) {
    const float* x = (const float*)d_in[0];
    const float* w_down = (const float*)d_in[1];
    const float* b_down = (const float*)d_in[2];
    const float* bn1_g = (const float*)d_in[3];
    const float* bn1_b = (const float*)d_in[4];
    const float* bn1_m = (const float*)d_in[5];
    const float* bn1_v = (const float*)d_in[6];
    const float* tconv_w = (const float*)d_in[7];
    const float* tconv_b = (const float*)d_in[8];
    const float* bnt_g = (const float*)d_in[9];
    const float* bnt_b = (const float*)d_in[10];
    const float* bnt_m = (const float*)d_in[11];
    const float* bnt_v = (const float*)d_in[12];
    const float* off3_w = (const float*)d_in[13];
    const float* off3_b = (const float*)d_in[14];
    const float* def3_w = (const float*)d_in[15];
    const float* off5_w = (const float*)d_in[16];
    const float* off5_b = (const float*)d_in[17];
    const float* def5_w = (const float*)d_in[18];
    const float* conv1_w = (const float*)d_in[19];
    const float* conv1_b = (const float*)d_in[20];
    const float* bn3_g = (const float*)d_in[21];
    const float* bn3_b = (const float*)d_in[22];
    const float* bn3_m = (const float*)d_in[23];
    const float* bn3_v = (const float*)d_in[24];
    const float* conv_w = (const float*)d_in[25];
    const float* conv_b = (const float*)d_in[26];
    const float* bn2_g = (const float*)d_in[27];
    const float* bn2_b = (const float*)d_in[28];
    const float* bn2_m = (const float*)d_in[29];
    const float* bn2_v = (const float*)d_in[30];
    float* out = (float*)d_out;

    k_init<<<16, 256>>>();
    k_down<<<dim3(64, 7), 256>>>(x, w_down, b_down, bn1_g, bn1_b, bn1_m, bn1_v);
    k_tsum<<<(8 * 64 * HW + 255) / 256, 256>>>();
    k_tstats<<<3 * 8 * 64, 32>>>();
    k_tgate<<<8, 64>>>(tconv_w, tconv_b, bnt_g, bnt_b, bnt_m, bnt_v);
    k_off3<<<dim3(56, 7), 256>>>(off3_w, off3_b);
    k_deform<3, false><<<dim3(56, 7), 256>>>(def3_w);
    k_off5<<<dim3(56, 7), 256>>>(off5_w, off5_b);
    k_deform<5, true><<<dim3(56, 7), 256>>>(def5_w);
    k_davg<<<dim3(56, 13), 256>>>(conv1_w, conv1_b, bn3_g, bn3_b, bn3_m, bn3_v);
    k_gate<<<64, 256>>>(conv_w, conv_b, bn2_g, bn2_b, bn2_m, bn2_v);
    k_final<<<(64 * 256 * (HW / 4) + 255) / 256, 256>>>(x, out);
}

// round 3
// speedup vs baseline: 3.3420x; 1.8801x over previous
#include <cuda_runtime.h>
#include <math.h>
#include <stdint.h>

#define HW 784
#define EPS 1e-5f
#define SP 72   // smem row stride (mod 32 == 8 -> conflict-free frag loads)

// transposed-weight buffer offsets
#define O_D   0
#define O_3O  16384
#define O_3D  53248
#define O_5O  90112
#define O_5D  192512
#define WT_TOT 294912

// ---------------- scratch (device globals; no allocation) ----------------
__device__ float g_out[64 * 64 * HW];
__device__ float g_S[8 * 64 * HW];
__device__ float g_off3[56 * 18 * HW];
__device__ float g_off5[56 * 50 * HW];
__device__ float g_d[56 * 64 * HW];
__device__ float g_tstats[3 * 8 * 64 * 9];
__device__ float g_cats[64 * 64];
__device__ float g_gate[64 * 256];
__device__ float g_wT[WT_TOT];

__device__ __forceinline__ float to_tf32(float x) {
    float y;
    asm("cvt.rna.tf32.f32 %0, %1;" : "=f"(y) : "f"(x));
    return y;
}

// ---- warp-mma core: 64(M) x 64(N) block tile, one K-chunk of 32 ----
__device__ __forceinline__ void mma64(const float* As, const float* Bs,
                                      int lane, int wm, int wn,
                                      float acc[2][2][4]) {
    int g = lane >> 2, tg = lane & 3;
#pragma unroll
    for (int ks = 0; ks < 4; ks++) {
        const float* Ab = As + (ks * 8) * SP;
        const float* Bb = Bs + (ks * 8) * SP;
        uint32_t a[2][4], b[2][2];
#pragma unroll
        for (int mt = 0; mt < 2; mt++) {
            int m = wm * 32 + mt * 16 + g;
            a[mt][0] = __float_as_uint(Ab[tg * SP + m]);
            a[mt][1] = __float_as_uint(Ab[tg * SP + m + 8]);
            a[mt][2] = __float_as_uint(Ab[(tg + 4) * SP + m]);
            a[mt][3] = __float_as_uint(Ab[(tg + 4) * SP + m + 8]);
        }
#pragma unroll
        for (int nt = 0; nt < 2; nt++) {
            int n = wn * 16 + nt * 8 + g;
            b[nt][0] = __float_as_uint(Bb[tg * SP + n]);
            b[nt][1] = __float_as_uint(Bb[(tg + 4) * SP + n]);
        }
#pragma unroll
        for (int mt = 0; mt < 2; mt++)
#pragma unroll
            for (int nt = 0; nt < 2; nt++)
                asm volatile(
                    "mma.sync.aligned.m16n8k8.row.col.f32.tf32.tf32.f32 "
                    "{%0,%1,%2,%3},{%4,%5,%6,%7},{%8,%9},{%0,%1,%2,%3};"
                    : "+f"(acc[mt][nt][0]), "+f"(acc[mt][nt][1]),
                      "+f"(acc[mt][nt][2]), "+f"(acc[mt][nt][3])
                    : "r"(a[mt][0]), "r"(a[mt][1]), "r"(a[mt][2]), "r"(a[mt][3]),
                      "r"(b[nt][0]), "r"(b[nt][1]));
    }
}

// ---------------- K-1: weight transpose/pad/tf32 prep ----------------
__global__ void k_prep(const float* __restrict__ wd, const float* __restrict__ o3,
                       const float* __restrict__ d3, const float* __restrict__ o5,
                       const float* __restrict__ d5) {
    int i = blockIdx.x * 256 + threadIdx.x;
    if (i >= WT_TOT) return;
    float v;
    if (i < O_3O) {
        int k = i >> 6, co = i & 63;
        v = wd[co * 256 + k];
    } else if (i < O_3D) {
        int j = i - O_3O, co = j & 63, ci = (j >> 6) & 63, k = j >> 12;
        v = (co < 18) ? o3[co * 576 + ci * 9 + k] : 0.f;
    } else if (i < O_5O) {
        int j = i - O_3D, co = j & 63, ci = (j >> 6) & 63, k = j >> 12;
        v = d3[(co * 64 + ci) * 9 + k];
    } else if (i < O_5D) {
        int j = i - O_5O, co = j & 63, ci = (j >> 6) & 63, k = j >> 12;
        v = (co < 50) ? o5[co * 1600 + ci * 25 + k] : 0.f;
    } else {
        int j = i - O_5D, co = j & 63, ci = (j >> 6) & 63, k = j >> 12;
        v = d5[(co * 64 + ci) * 25 + k];
    }
    g_wT[i] = to_tf32(v);
}

// ---------------- K0: zero the reduction buffer ----------------
__global__ void k_init() {
    int i = blockIdx.x * 256 + threadIdx.x;
    if (i < 64 * 64) g_cats[i] = 0.f;
}

// ---------------- K1: 1x1 conv 256->64 + bn1 ----------------
__global__ void k_down(const float* __restrict__ x, const float* __restrict__ g1,
                       const float* __restrict__ b1, const float* __restrict__ m1,
                       const float* __restrict__ v1, const float* __restrict__ bd) {
    __shared__ float As[2][32 * SP];
    __shared__ float Bs[2][32 * SP];
    int nt = blockIdx.x, p0 = blockIdx.y * 64;
    int tid = threadIdx.x, lane = tid & 31, w = tid >> 5, wm = w & 1, wn = w >> 1;
    int px = tid & 63, kk0 = tid >> 6;
    int p = p0 + px;
    const float* xb = x + (size_t)nt * 256 * HW;
    float acc[2][2][4] = {};

    auto buildA = [&](int c, int b) {
        const float* ws = &g_wT[O_D + c * 32 * 64];
#pragma unroll
        for (int j = 0; j < 8; j++) { int kk = kk0 + 4 * j; As[b][kk * SP + px] = ws[kk * 64 + px]; }
    };
    auto buildB = [&](int c, int b) {
#pragma unroll
        for (int j = 0; j < 8; j++) {
            int kk = kk0 + 4 * j;
            Bs[b][kk * SP + px] = (p < HW) ? to_tf32(xb[(c * 32 + kk) * HW + p]) : 0.f;
        }
    };
    buildA(0, 0); buildB(0, 0);
    __syncthreads();
    for (int c = 0; c < 8; c++) {
        int cb = c & 1, nb = cb ^ 1;
        if (c + 1 < 8) { buildA(c + 1, nb); buildB(c + 1, nb); }
        mma64(As[cb], Bs[cb], lane, wm, wn, acc);
        __syncthreads();
    }
    int g = lane >> 2, tg = lane & 3;
#pragma unroll
    for (int mt = 0; mt < 2; mt++)
#pragma unroll
        for (int nq = 0; nq < 2; nq++) {
            int pp = p0 + wn * 16 + nq * 8 + tg * 2;
            if (pp >= HW) continue;
#pragma unroll
            for (int h = 0; h < 2; h++) {
                int co = wm * 32 + mt * 16 + g + h * 8;
                float sc = g1[co] * rsqrtf(v1[co] + EPS);
                float sh = (bd[co] - m1[co]) * sc + b1[co];
                float2 v;
                v.x = acc[mt][nq][h * 2] * sc + sh;
                v.y = acc[mt][nq][h * 2 + 1] * sc + sh;
                *(float2*)&g_out[((size_t)nt * 64 + co) * HW + pp] = v;
            }
        }
}

// ---------------- K2: sum over T frames ----------------
__global__ void k_tsum() {
    int i = blockIdx.x * 256 + threadIdx.x;
    if (i >= 8 * 64 * HW) return;
    int p = i % HW, ci = (i / HW) % 64, b = i / (HW * 64);
    float s = 0.f;
#pragma unroll
    for (int t = 0; t < 8; t++) s += g_out[((size_t)(b * 8 + t) * 64 + ci) * HW + p];
    g_S[i] = s;
}

// ---------------- K3: border stats ----------------
__global__ void k_tstats() {
    int id = blockIdx.x;
    int ci = id & 63, b = (id >> 6) & 7, s = id >> 9;
    const float* src;
    if (s == 0) src = &g_S[((size_t)b * 64 + ci) * HW];
    else src = &g_out[((size_t)(b * 8 + (s == 1 ? 0 : 7)) * 64 + ci) * HW];
    int lane = threadIdx.x;
    float t = 0, r0 = 0, r27 = 0, c0 = 0, c27 = 0;
    for (int p = lane; p < HW; p += 32) {
        float v = src[p];
        int y = p / 28, x = p % 28;
        t += v;
        if (y == 0) r0 += v;
        if (y == 27) r27 += v;
        if (x == 0) c0 += v;
        if (x == 27) c27 += v;
    }
#pragma unroll
    for (int o = 16; o; o >>= 1) {
        t += __shfl_down_sync(0xffffffffu, t, o);
        r0 += __shfl_down_sync(0xffffffffu, r0, o);
        r27 += __shfl_down_sync(0xffffffffu, r27, o);
        c0 += __shfl_down_sync(0xffffffffu, c0, o);
        c27 += __shfl_down_sync(0xffffffffu, c27, o);
    }
    if (lane == 0) {
        float* o = &g_tstats[(size_t)id * 9];
        o[0] = t; o[1] = r0; o[2] = r27; o[3] = c0; o[4] = c27;
        o[5] = src[0]; o[6] = src[27]; o[7] = src[27 * 28]; o[8] = src[27 * 28 + 27];
    }
}

// ---------------- K4: temporal branch -> gate slot 7 ----------------
__global__ void k_tgate(const float* __restrict__ tw, const float* __restrict__ tb,
                        const float* __restrict__ g, const float* __restrict__ bb,
                        const float* __restrict__ m, const float* __restrict__ v) {
    int b = blockIdx.x;
    int co = threadIdx.x;
    float acc = 0.f;
    for (int s = 0; s < 3; s++) {
        for (int ci = 0; ci < 64; ci++) {
            const float* st = &g_tstats[((size_t)(s * 8 + b) * 64 + ci) * 9];
            const float* w = &tw[((size_t)(co * 64 + ci) * 3) * 9];
#pragma unroll
            for (int k = 0; k < 9; k++) {
                int ky = k / 3, kx = k % 3;
                float rs = st[0];
                if (ky == 2) rs -= st[1];
                if (ky == 0) rs -= st[2];
                if (kx == 2) rs -= st[3];
                if (kx == 0) rs -= st[4];
                if (ky == 2 && kx == 2) rs += st[5];
                if (ky == 2 && kx == 0) rs += st[6];
                if (ky == 0 && kx == 2) rs += st[7];
                if (ky == 0 && kx == 0) rs += st[8];
                float we = (s == 0) ? (w[k] + w[9 + k] + w[18 + k])
                                    : (s == 1 ? -w[18 + k] : -w[k]);
                acc += we * rs;
            }
        }
    }
    float val = acc * (1.f / (8.f * 784.f)) + tb[co];
    float sc = g[co] * rsqrtf(v[co] + EPS);
    float tm = (val - m[co]) * sc + bb[co];
    g_cats[(b * 8 + 7) * 64 + co] = tm * 784.f;
}

// ---------------- K5/K6: offset-field convs (k-major, reg shift tables) ----------
template <int KS>
__global__ void k_off(const float* __restrict__ bias) {
    constexpr int K2 = KS * KS, PAD = KS / 2, NC = K2 * 2;
    constexpr int MCO = (KS == 3) ? 18 : 50;
    const size_t WOFF = (KS == 3) ? O_3O : O_5O;
    float* dst = (KS == 3) ? g_off3 : g_off5;
    __shared__ float As[2][32 * SP];
    __shared__ float Bs[2][32 * SP];
    int n = blockIdx.x, p0 = blockIdx.y * 64;
    int f = (n / 7) * 8 + (n % 7) + 1;
    const float* src = &g_out[(size_t)f * 64 * HW];
    int tid = threadIdx.x, lane = tid & 31, w = tid >> 5, wm = w & 1, wn = w >> 1;
    int px = tid & 63, kk0 = tid >> 6;
    int p = p0 + px, py = p / 28, pxc = p % 28;
    float acc[2][2][4] = {};
    int si;
    auto tapcalc = [&](int k) {
        int yy = py + k / KS - PAD, xs = pxc + k % KS - PAD;
        si = (p < HW && yy >= 0 && yy < 28 && xs >= 0 && xs < 28) ? yy * 28 + xs : -1;
    };
    auto buildA = [&](int c, int b) {
        const float* ws = &g_wT[WOFF + (size_t)c * 32 * 64];
#pragma unroll
        for (int j = 0; j < 8; j++) { int kk = kk0 + 4 * j; As[b][kk * SP + px] = ws[kk * 64 + px]; }
    };
    auto buildB = [&](int c, int b) {
        int ci0 = (c & 1) * 32;
#pragma unroll
        for (int j = 0; j < 8; j++) {
            int kk = kk0 + 4 * j;
            Bs[b][kk * SP + px] = (si >= 0) ? to_tf32(src[(ci0 + kk) * HW + si]) : 0.f;
        }
    };
    tapcalc(0); buildA(0, 0); buildB(0, 0);
    __syncthreads();
    for (int c = 0; c < NC; c++) {
        int cb = c & 1, nb = cb ^ 1;
        if (c + 1 < NC) {
            if (((c + 1) & 1) == 0) tapcalc((c + 1) >> 1);
            buildA(c + 1, nb); buildB(c + 1, nb);
        }
        mma64(As[cb], Bs[cb], lane, wm, wn, acc);
        __syncthreads();
    }
    int g = lane >> 2, tg = lane & 3;
#pragma unroll
    for (int mt = 0; mt < 2; mt++)
#pragma unroll
        for (int nq = 0; nq < 2; nq++) {
            int pp = p0 + wn * 16 + nq * 8 + tg * 2;
            if (pp >= HW) continue;
#pragma unroll
            for (int h = 0; h < 2; h++) {
                int co = wm * 32 + mt * 16 + g + h * 8;
                if (co >= MCO) continue;
                float2 v;
                v.x = acc[mt][nq][h * 2] + bias[co];
                v.y = acc[mt][nq][h * 2 + 1] + bias[co];
                *(float2*)&dst[((size_t)n * MCO + co) * HW + pp] = v;
            }
        }
}

// ---------------- K7/K8: deformable conv (reg bilinear tables) ----------------
template <int KS, bool ACC>
__global__ void k_deform() {
    constexpr int K2 = KS * KS, PAD = KS / 2, NC = K2 * 2;
    const size_t WOFF = (KS == 3) ? O_3D : O_5D;
    __shared__ float As[2][32 * SP];
    __shared__ float Bs[2][32 * SP];
    int n = blockIdx.x, p0 = blockIdx.y * 64;
    int f = (n / 7) * 8 + (n % 7) + 1;
    const float* src = &g_out[(size_t)f * 64 * HW];
    const float* off = ((KS == 3) ? g_off3 : g_off5) + (size_t)n * (2 * K2) * HW;
    int tid = threadIdx.x, lane = tid & 31, w = tid >> 5, wm = w & 1, wn = w >> 1;
    int px = tid & 63, kk0 = tid >> 6;
    int p = p0 + px, pyi = p / 28, pxi = p % 28;
    float acc[2][2][4] = {};
    float wt[4];
    int ix[4];
    auto tapcalc = [&](int k) {
        float py = -100.f, pxx = -100.f;
        if (p < HW) {
            py = (float)(pyi + k / KS - PAD) + off[(size_t)(2 * k) * HW + p];
            pxx = (float)(pxi + k % KS - PAD) + off[(size_t)(2 * k + 1) * HW + p];
        }
        float fy = floorf(py), fx = floorf(pxx);
        int y0 = (int)fy, x0 = (int)fx;
        float ly = py - fy, lx = pxx - fx;
#pragma unroll
        for (int t = 0; t < 4; t++) {
            int iy = y0 + (t >> 1), ixx = x0 + (t & 1);
            float wv = ((t >> 1) ? ly : 1.f - ly) * ((t & 1) ? lx : 1.f - lx);
            bool valid = (iy >= 0) && (iy < 28) && (ixx >= 0) && (ixx < 28);
            wt[t] = valid ? wv : 0.f;
            ix[t] = min(max(iy, 0), 27) * 28 + min(max(ixx, 0), 27);
        }
    };
    auto buildA = [&](int c, int b) {
        const float* ws = &g_wT[WOFF + (size_t)c * 32 * 64];
#pragma unroll
        for (int j = 0; j < 8; j++) { int kk = kk0 + 4 * j; As[b][kk * SP + px] = ws[kk * 64 + px]; }
    };
    auto buildB = [&](int c, int b) {
        int ci0 = (c & 1) * 32;
#pragma unroll
        for (int j = 0; j < 8; j++) {
            int kk = kk0 + 4 * j;
            const float* sc = src + (ci0 + kk) * HW;
            float v = wt[0] * sc[ix[0]] + wt[1] * sc[ix[1]] + wt[2] * sc[ix[2]] + wt[3] * sc[ix[3]];
            Bs[b][kk * SP + px] = to_tf32(v);
        }
    };
    tapcalc(0); buildA(0, 0); buildB(0, 0);
    __syncthreads();
    for (int c = 0; c < NC; c++) {
        int cb = c & 1, nb = cb ^ 1;
        if (c + 1 < NC) {
            if (((c + 1) & 1) == 0) tapcalc((c + 1) >> 1);
            buildA(c + 1, nb); buildB(c + 1, nb);
        }
        mma64(As[cb], Bs[cb], lane, wm, wn, acc);
        __syncthreads();
    }
    int g = lane >> 2, tg = lane & 3;
#pragma unroll
    for (int mt = 0; mt < 2; mt++)
#pragma unroll
        for (int nq = 0; nq < 2; nq++) {
            int pp = p0 + wn * 16 + nq * 8 + tg * 2;
            if (pp >= HW) continue;
#pragma unroll
            for (int h = 0; h < 2; h++) {
                int co = wm * 32 + mt * 16 + g + h * 8;
                size_t idx = ((size_t)n * 64 + co) * HW + pp;
                float2 v;
                v.x = acc[mt][nq][h * 2];
                v.y = acc[mt][nq][h * 2 + 1];
                if (ACC) {
                    float2 o = *(float2*)&g_d[idx];
                    v.x += o.x; v.y += o.y;
                }
                *(float2*)&g_d[idx] = v;
            }
        }
}

// ---------------- K9: maxpool + 1x1 + bn3 + |diff| reduce ----------------
__global__ void k_davg(const float* __restrict__ w1, const float* __restrict__ b1,
                       const float* __restrict__ g3, const float* __restrict__ bb3,
                       const float* __restrict__ m3, const float* __restrict__ v3) {
    __shared__ float MP[64 * 68];
    int n = blockIdx.x, p0 = blockIdx.y * 64;
    int b = n / 7, t = n % 7;
    int f = b * 8 + t + 1, fp = b * 8 + t;
    const float* src = &g_out[(size_t)f * 64 * HW];
    const float* pre = &g_out[(size_t)fp * 64 * HW];
    int tid = threadIdx.x;
    for (int i = tid; i < 4096; i += 256) {
        int ci = i >> 6, px = i & 63, p = p0 + px;
        float mv = 0.f;
        if (p < HW) {
            int y = p / 28, x = p % 28;
            const float* s = src + ci * HW;
            mv = -1e30f;
            for (int dy = -1; dy <= 1; dy++) {
                int yy = y + dy;
                if (yy < 0 || yy >= 28) continue;
                for (int dx = -1; dx <= 1; dx++) {
                    int xx = x + dx;
                    if (xx < 0 || xx >= 28) continue;
                    mv = fmaxf(mv, s[yy * 28 + xx]);
                }
            }
        }
        MP[ci * 68 + px] = mv;
    }
    __syncthreads();
    int r = tid >> 4, c = tid & 15;
    float acc[4][4] = {};
    for (int ci = 0; ci < 64; ci++) {
        float a[4], bv[4];
#pragma unroll
        for (int i = 0; i < 4; i++) a[i] = w1[(r * 4 + i) * 64 + ci];
#pragma unroll
        for (int j = 0; j < 4; j++) bv[j] = MP[ci * 68 + c * 4 + j];
#pragma unroll
        for (int i = 0; i < 4; i++)
#pragma unroll
            for (int j = 0; j < 4; j++) acc[i][j] += a[i] * bv[j];
    }
    float sums[4];
#pragma unroll
    for (int i = 0; i < 4; i++) {
        int co = r * 4 + i;
        float sc = g3[co] * rsqrtf(v3[co] + EPS);
        float sh = (b1[co] - m3[co]) * sc + bb3[co];
        float s = 0.f;
#pragma unroll
        for (int j = 0; j < 4; j++) {
            int p = p0 + c * 4 + j;
            if (p < HW) {
                float davg = acc[i][j] * sc + sh;
                s += fabsf(g_d[((size_t)n * 64 + co) * HW + p] + davg - 3.f * pre[co * HW + p]);
            }
        }
        sums[i] = s;
    }
#pragma unroll
    for (int o = 8; o; o >>= 1)
#pragma unroll
        for (int i = 0; i < 4; i++) sums[i] += __shfl_down_sync(0xffffffffu, sums[i], o);
    if (c == 0)
#pragma unroll
        for (int i = 0; i < 4; i++) atomicAdd(&g_cats[(b * 8 + t) * 64 + r * 4 + i], sums[i]);
}

// ---------------- K10: gate ----------------
__global__ void k_gate(const float* __restrict__ cw, const float* __restrict__ cb,
                       const float* __restrict__ g2, const float* __restrict__ b2,
                       const float* __restrict__ m2, const float* __restrict__ v2) {
    int nt = blockIdx.x;
    int co = threadIdx.x;
    __shared__ float mvec[64];
    if (co < 64) mvec[co] = g_cats[nt * 64 + co] * (1.f / 784.f);
    __syncthreads();
    float y = cb[co];
#pragma unroll 8
    for (int ci = 0; ci < 64; ci++) y += mvec[ci] * cw[co * 64 + ci];
    float sc = g2[co] * rsqrtf(v2[co] + EPS);
    y = (y - m2[co]) * sc + b2[co];
    float gate = 1.f / (1.f + expf(-y)) - 0.5f;
    g_gate[nt * 256 + co] = 1.f + gate;
}

// ---------------- K11: final elementwise ----------------
__global__ void k_final(const float* __restrict__ x, float* __restrict__ out) {
    int i = blockIdx.x * 256 + threadIdx.x;
    if (i >= 64 * 256 * (HW / 4)) return;
    int ch = i / (HW / 4);
    float gm = g_gate[ch];
    const float4* x4 = (const float4*)x;
    float4 v = x4[i];
    v.x *= gm; v.y *= gm; v.z *= gm; v.w *= gm;
    ((float4*)out)[i] = v;
}

// ---------------- launch ----------------
extern "C" void kernel_launch(void* const* d_in, const int* in_sizes, int n_in,
                              void* d_out, int out_size) {
    const float* x = (const float*)d_in[0];
    const float* w_down = (const float*)d_in[1];
    const float* b_down = (const float*)d_in[2];
    const float* bn1_g = (const float*)d_in[3];
    const float* bn1_b = (const float*)d_in[4];
    const float* bn1_m = (const float*)d_in[5];
    const float* bn1_v = (const float*)d_in[6];
    const float* tconv_w = (const float*)d_in[7];
    const float* tconv_b = (const float*)d_in[8];
    const float* bnt_g = (const float*)d_in[9];
    const float* bnt_b = (const float*)d_in[10];
    const float* bnt_m = (const float*)d_in[11];
    const float* bnt_v = (const float*)d_in[12];
    const float* off3_w = (const float*)d_in[13];
    const float* off3_b = (const float*)d_in[14];
    const float* def3_w = (const float*)d_in[15];
    const float* off5_w = (const float*)d_in[16];
    const float* off5_b = (const float*)d_in[17];
    const float* def5_w = (const float*)d_in[18];
    const float* conv1_w = (const float*)d_in[19];
    const float* conv1_b = (const float*)d_in[20];
    const float* bn3_g = (const float*)d_in[21];
    const float* bn3_b = (const float*)d_in[22];
    const float* bn3_m = (const float*)d_in[23];
    const float* bn3_v = (const float*)d_in[24];
    const float* conv_w = (const float*)d_in[25];
    const float* conv_b = (const float*)d_in[26];
    const float* bn2_g = (const float*)d_in[27];
    const float* bn2_b = (const float*)d_in[28];
    const float* bn2_m = (const float*)d_in[29];
    const float* bn2_v = (const float*)d_in[30];
    float* out = (float*)d_out;

    k_prep<<<(WT_TOT + 255) / 256, 256>>>(w_down, off3_w, def3_w, off5_w, def5_w);
    k_init<<<16, 256>>>();
    k_down<<<dim3(64, 13), 256>>>(x, bn1_g, bn1_b, bn1_m, bn1_v, b_down);
    k_tsum<<<(8 * 64 * HW + 255) / 256, 256>>>();
    k_tstats<<<3 * 8 * 64, 32>>>();
    k_tgate<<<8, 64>>>(tconv_w, tconv_b, bnt_g, bnt_b, bnt_m, bnt_v);
    k_off<3><<<dim3(56, 13), 256>>>(off3_b);
    k_deform<3, false><<<dim3(56, 13), 256>>>();
    k_off<5><<<dim3(56, 13), 256>>>(off5_b);
    k_deform<5, true><<<dim3(56, 13), 256>>>();
    k_davg<<<dim3(56, 13), 256>>>(conv1_w, conv1_b, bn3_g, bn3_b, bn3_m, bn3_v);
    k_gate<<<64, 256>>>(conv_w, conv_b, bn2_g, bn2_b, bn2_m, bn2_v);
    k_final<<<(64 * 256 * (HW / 4) + 255) / 256, 256>>>(x, out);
}

// round 4
// speedup vs baseline: 3.4477x; 1.0316x over previous
#include <cuda_runtime.h>
#include <cuda_bf16.h>
#include <math.h>
#include <stdint.h>

#define HW 784
#define EPS 1e-5f
#define SA 40   // bf16 smem row stride (80B: conflict-free for ldmatrix & uint4 STS)

// chunk offsets in g_wTh (each chunk = 64 m x 32 k bf16 = 2048)
#define CH_DOWN 0
#define CH_O3   8
#define CH_D3   26
#define CH_O5   44
#define CH_D5   94
#define CH_TOT  144

// ---------------- scratch (device globals; no allocation) ----------------
__device__ float g_out[64 * 64 * HW];                    // bn1 output fp32 [f][ch][p]
__device__ __nv_bfloat16 g_outT[(size_t)64 * HW * 64];   // bf16 [f][p][ch]
__device__ float g_S[8 * 64 * HW];
__device__ float g_d[56 * 64 * HW];
__device__ float g_tstats[3 * 8 * 64 * 9];
__device__ float g_cats[64 * 64];
__device__ float g_gate[64 * 256];
__device__ __nv_bfloat16 g_wTh[CH_TOT * 2048];

__device__ __forceinline__ uint32_t sptr(const void* p) {
    return (uint32_t)__cvta_generic_to_shared(p);
}
__device__ __forceinline__ __nv_bfloat162 u2b(uint32_t u) {
    __nv_bfloat162 h; *(uint32_t*)&h = u; return h;
}
__device__ __forceinline__ uint32_t b2u(__nv_bfloat162 h) {
    return *(uint32_t*)&h;
}

// ---- bf16 mma core: 64(M) x 64(N) block tile, one K-chunk of 32 ----
__device__ __forceinline__ void mma64b(const __nv_bfloat16* As, const __nv_bfloat16* Bs,
                                       int lane, int wm, int wn, float acc[2][2][4]) {
#pragma unroll
    for (int ks = 0; ks < 2; ks++) {
        int l15 = lane & 15, lhi = lane >> 4;
        uint32_t a[2][4];
#pragma unroll
        for (int mt = 0; mt < 2; mt++) {
            uint32_t ad = sptr(As + (wm * 32 + mt * 16 + l15) * SA + lhi * 8 + ks * 16);
            asm volatile("ldmatrix.sync.aligned.m8n8.x4.shared.b16 {%0,%1,%2,%3}, [%4];"
                         : "=r"(a[mt][0]), "=r"(a[mt][1]), "=r"(a[mt][2]), "=r"(a[mt][3])
                         : "r"(ad));
        }
        uint32_t b[4];
        {
            int brow = wn * 16 + (((lane >> 3) & 1) << 3) + (lane & 7);
            uint32_t bd = sptr(Bs + brow * SA + lhi * 8 + ks * 16);
            asm volatile("ldmatrix.sync.aligned.m8n8.x4.shared.b16 {%0,%1,%2,%3}, [%4];"
                         : "=r"(b[0]), "=r"(b[1]), "=r"(b[2]), "=r"(b[3])
                         : "r"(bd));
        }
#pragma unroll
        for (int mt = 0; mt < 2; mt++)
#pragma unroll
            for (int nt = 0; nt < 2; nt++)
                asm volatile(
                    "mma.sync.aligned.m16n8k16.row.col.f32.bf16.bf16.f32 "
                    "{%0,%1,%2,%3},{%4,%5,%6,%7},{%8,%9},{%0,%1,%2,%3};"
                    : "+f"(acc[mt][nt][0]), "+f"(acc[mt][nt][1]),
                      "+f"(acc[mt][nt][2]), "+f"(acc[mt][nt][3])
                    : "r"(a[mt][0]), "r"(a[mt][1]), "r"(a[mt][2]), "r"(a[mt][3]),
                      "r"(b[nt]), "r"(b[nt + 2]));
    }
}

// ---------------- K-1: weight prep -> bf16 [chunk][m][k] ----------------
__global__ void k_prep(const float* __restrict__ wd, const float* __restrict__ o3,
                       const float* __restrict__ d3, const float* __restrict__ o5,
                       const float* __restrict__ d5) {
    int i = blockIdx.x * 256 + threadIdx.x;
    if (i >= CH_TOT * 2048) return;
    int c = i >> 11, j = i & 2047, m = j >> 5, kk = j & 31;
    float v;
    if (c < CH_O3) {
        v = wd[m * 256 + (c - CH_DOWN) * 32 + kk];
    } else if (c < CH_D3) {
        int cc = c - CH_O3, tap = cc >> 1, ci = (cc & 1) * 32 + kk;
        v = (m < 18) ? o3[m * 576 + ci * 9 + tap] : 0.f;
    } else if (c < CH_O5) {
        int cc = c - CH_D3, tap = cc >> 1, ci = (cc & 1) * 32 + kk;
        v = d3[(m * 64 + ci) * 9 + tap];
    } else if (c < CH_D5) {
        int cc = c - CH_O5, tap = cc >> 1, ci = (cc & 1) * 32 + kk;
        v = (m < 50) ? o5[m * 1600 + ci * 25 + tap] : 0.f;
    } else {
        int cc = c - CH_D5, tap = cc >> 1, ci = (cc & 1) * 32 + kk;
        v = d5[(m * 64 + ci) * 25 + tap];
    }
    g_wTh[i] = __float2bfloat16(v);
}

// ---------------- K0: zero reduction buffer ----------------
__global__ void k_init() {
    int i = blockIdx.x * 256 + threadIdx.x;
    if (i < 64 * 64) g_cats[i] = 0.f;
}

// ---------------- K1: 1x1 conv 256->64 + bn1 ----------------
__global__ void k_down(const float* __restrict__ x, const float* __restrict__ g1,
                       const float* __restrict__ b1, const float* __restrict__ m1,
                       const float* __restrict__ v1, const float* __restrict__ bd) {
    __shared__ __align__(16) __nv_bfloat16 As[2][64 * SA];
    __shared__ __align__(16) __nv_bfloat16 Bs[2][64 * SA];
    int nt = blockIdx.x, p0 = blockIdx.y * 64;
    int tid = threadIdx.x, lane = tid & 31, w = tid >> 5, wm = w & 1, wn = w >> 1;
    int px = tid & 63, q = tid >> 6;
    int p = p0 + px;
    const float* xb = x + (size_t)nt * 256 * HW;
    float acc[2][2][4] = {};

    auto buildA = [&](int c, int b) {
        int m = tid >> 2, qa = tid & 3;
        *(uint4*)&As[b][m * SA + qa * 8] =
            *(const uint4*)&g_wTh[(CH_DOWN + c) * 2048 + m * 32 + qa * 8];
    };
    auto buildB = [&](int c, int b) {
        uint32_t u[4];
#pragma unroll
        for (int j = 0; j < 4; j++) {
            float v0 = (p < HW) ? xb[(c * 32 + q * 8 + 2 * j) * HW + p] : 0.f;
            float v1 = (p < HW) ? xb[(c * 32 + q * 8 + 2 * j + 1) * HW + p] : 0.f;
            u[j] = b2u(__floats2bfloat162_rn(v0, v1));
        }
        *(uint4*)&Bs[b][px * SA + q * 8] = *(uint4*)u;
    };
    buildA(0, 0); buildB(0, 0);
    __syncthreads();
    for (int c = 0; c < 8; c++) {
        int cb = c & 1, nb = cb ^ 1;
        if (c + 1 < 8) { buildA(c + 1, nb); buildB(c + 1, nb); }
        mma64b(As[cb], Bs[cb], lane, wm, wn, acc);
        __syncthreads();
    }
    int g = lane >> 2, tg = lane & 3;
#pragma unroll
    for (int mt = 0; mt < 2; mt++)
#pragma unroll
        for (int nq = 0; nq < 2; nq++) {
            int pp = p0 + wn * 16 + nq * 8 + tg * 2;
            if (pp >= HW) continue;
#pragma unroll
            for (int h = 0; h < 2; h++) {
                int co = wm * 32 + mt * 16 + g + h * 8;
                float sc = g1[co] * rsqrtf(v1[co] + EPS);
                float sh = (bd[co] - m1[co]) * sc + b1[co];
                float2 v;
                v.x = acc[mt][nq][h * 2] * sc + sh;
                v.y = acc[mt][nq][h * 2 + 1] * sc + sh;
                *(float2*)&g_out[((size_t)nt * 64 + co) * HW + pp] = v;
            }
        }
}

// ---------------- K1b: transpose g_out -> g_outT bf16 [f][p][ch] ----------------
__global__ void k_trans() {
    __shared__ float ts[64][65];
    int f = blockIdx.x, p0 = blockIdx.y * 64, tid = threadIdx.x;
    for (int i = tid; i < 4096; i += 256) {
        int ci = i >> 6, px = i & 63, p = p0 + px;
        ts[ci][px] = (p < HW) ? g_out[((size_t)f * 64 + ci) * HW + p] : 0.f;
    }
    __syncthreads();
    int px = tid >> 2, q = tid & 3, p = p0 + px;
    if (p < HW) {
        union { __nv_bfloat16 h[16]; uint4 u[2]; } tmp;
#pragma unroll
        for (int j = 0; j < 16; j++) tmp.h[j] = __float2bfloat16(ts[q * 16 + j][px]);
        uint4* dst = (uint4*)&g_outT[((size_t)f * HW + p) * 64 + q * 16];
        dst[0] = tmp.u[0];
        dst[1] = tmp.u[1];
    }
}

// ---------------- K2: sum over T frames ----------------
__global__ void k_tsum() {
    int i = blockIdx.x * 256 + threadIdx.x;
    if (i >= 8 * 64 * HW) return;
    int p = i % HW, ci = (i / HW) % 64, b = i / (HW * 64);
    float s = 0.f;
#pragma unroll
    for (int t = 0; t < 8; t++) s += g_out[((size_t)(b * 8 + t) * 64 + ci) * HW + p];
    g_S[i] = s;
}

// ---------------- K3: border stats ----------------
__global__ void k_tstats() {
    int id = blockIdx.x;
    int ci = id & 63, b = (id >> 6) & 7, s = id >> 9;
    const float* src;
    if (s == 0) src = &g_S[((size_t)b * 64 + ci) * HW];
    else src = &g_out[((size_t)(b * 8 + (s == 1 ? 0 : 7)) * 64 + ci) * HW];
    int lane = threadIdx.x;
    float t = 0, r0 = 0, r27 = 0, c0 = 0, c27 = 0;
    for (int p = lane; p < HW; p += 32) {
        float v = src[p];
        int y = p / 28, x = p % 28;
        t += v;
        if (y == 0) r0 += v;
        if (y == 27) r27 += v;
        if (x == 0) c0 += v;
        if (x == 27) c27 += v;
    }
#pragma unroll
    for (int o = 16; o; o >>= 1) {
        t += __shfl_down_sync(0xffffffffu, t, o);
        r0 += __shfl_down_sync(0xffffffffu, r0, o);
        r27 += __shfl_down_sync(0xffffffffu, r27, o);
        c0 += __shfl_down_sync(0xffffffffu, c0, o);
        c27 += __shfl_down_sync(0xffffffffu, c27, o);
    }
    if (lane == 0) {
        float* o = &g_tstats[(size_t)id * 9];
        o[0] = t; o[1] = r0; o[2] = r27; o[3] = c0; o[4] = c27;
        o[5] = src[0]; o[6] = src[27]; o[7] = src[27 * 28]; o[8] = src[27 * 28 + 27];
    }
}

// ---------------- K4: temporal branch -> gate slot 7 ----------------
__global__ void k_tgate(const float* __restrict__ tw, const float* __restrict__ tb,
                        const float* __restrict__ g, const float* __restrict__ bb,
                        const float* __restrict__ m, const float* __restrict__ v) {
    int b = blockIdx.x;
    int co = threadIdx.x;
    float acc = 0.f;
    for (int s = 0; s < 3; s++) {
        for (int ci = 0; ci < 64; ci++) {
            const float* st = &g_tstats[((size_t)(s * 8 + b) * 64 + ci) * 9];
            const float* w = &tw[((size_t)(co * 64 + ci) * 3) * 9];
#pragma unroll
            for (int k = 0; k < 9; k++) {
                int ky = k / 3, kx = k % 3;
                float rs = st[0];
                if (ky == 2) rs -= st[1];
                if (ky == 0) rs -= st[2];
                if (kx == 2) rs -= st[3];
                if (kx == 0) rs -= st[4];
                if (ky == 2 && kx == 2) rs += st[5];
                if (ky == 2 && kx == 0) rs += st[6];
                if (ky == 0 && kx == 2) rs += st[7];
                if (ky == 0 && kx == 0) rs += st[8];
                float we = (s == 0) ? (w[k] + w[9 + k] + w[18 + k])
                                    : (s == 1 ? -w[18 + k] : -w[k]);
                acc += we * rs;
            }
        }
    }
    float val = acc * (1.f / (8.f * 784.f)) + tb[co];
    float sc = g[co] * rsqrtf(v[co] + EPS);
    float tm = (val - m[co]) * sc + bb[co];
    g_cats[(b * 8 + 7) * 64 + co] = tm * 784.f;
}

// ---------------- K5/K6: fused offset-conv + deformable conv ----------------
template <int KS, bool ACC>
__global__ void k_fused(const float* __restrict__ bias) {
    constexpr int K2 = KS * KS, PAD = KS / 2, NC = K2 * 2, MCO = 2 * K2;
    constexpr int WOFF_O = (KS == 3) ? CH_O3 : CH_O5;
    constexpr int WOFF_D = (KS == 3) ? CH_D3 : CH_D5;
    __shared__ __align__(16) __nv_bfloat16 As[2][64 * SA];
    __shared__ __align__(16) __nv_bfloat16 Bs[2][64 * SA];
    __shared__ float off_s[MCO * 66];
    int n = blockIdx.x, p0 = blockIdx.y * 64;
    int f = (n / 7) * 8 + (n % 7) + 1;
    const __nv_bfloat16* srcT = g_outT + (size_t)f * HW * 64;
    int tid = threadIdx.x, lane = tid & 31, w = tid >> 5, wm = w & 1, wn = w >> 1;
    int px = tid & 63, q = tid >> 6;
    int p = p0 + px, pyi = p / 28, pxi = p % 28;
    int g = lane >> 2, tg = lane & 3;

    auto buildA = [&](int woff, int c, int b) {
        int m = tid >> 2, qa = tid & 3;
        *(uint4*)&As[b][m * SA + qa * 8] =
            *(const uint4*)&g_wTh[(woff + c) * 2048 + m * 32 + qa * 8];
    };

    // ---------- stage 1: offset-field conv ----------
    float acc[2][2][4] = {};
    {
        int si;
        auto tapcalc = [&](int k) {
            int yy = pyi + k / KS - PAD, xs = pxi + k % KS - PAD;
            si = (p < HW && yy >= 0 && yy < 28 && xs >= 0 && xs < 28) ? yy * 28 + xs : -1;
        };
        auto buildB = [&](int c, int b) {
            int ci0 = (c & 1) * 32;
            uint4 v = make_uint4(0, 0, 0, 0);
            if (si >= 0) v = *(const uint4*)(srcT + (size_t)si * 64 + ci0 + q * 8);
            *(uint4*)&Bs[b][px * SA + q * 8] = v;
        };
        tapcalc(0); buildA(WOFF_O, 0, 0); buildB(0, 0);
        __syncthreads();
        for (int c = 0; c < NC; c++) {
            int cb = c & 1, nb = cb ^ 1;
            if (c + 1 < NC) {
                if (((c + 1) & 1) == 0) tapcalc((c + 1) >> 1);
                buildA(WOFF_O, c + 1, nb); buildB(c + 1, nb);
            }
            mma64b(As[cb], Bs[cb], lane, wm, wn, acc);
            __syncthreads();
        }
#pragma unroll
        for (int mt = 0; mt < 2; mt++)
#pragma unroll
            for (int nq = 0; nq < 2; nq++) {
                int pp = wn * 16 + nq * 8 + tg * 2;
#pragma unroll
                for (int h = 0; h < 2; h++) {
                    int co = wm * 32 + mt * 16 + g + h * 8;
                    if (co < MCO) {
                        off_s[co * 66 + pp] = acc[mt][nq][h * 2] + bias[co];
                        off_s[co * 66 + pp + 1] = acc[mt][nq][h * 2 + 1] + bias[co];
                    }
                }
            }
    }
    __syncthreads();

    // ---------- stage 2: deformable conv ----------
#pragma unroll
    for (int mt = 0; mt < 2; mt++)
#pragma unroll
        for (int nt2 = 0; nt2 < 2; nt2++)
#pragma unroll
            for (int e = 0; e < 4; e++) acc[mt][nt2][e] = 0.f;
    {
        uint32_t w2[4];
        int ix[4];
        auto tapcalc = [&](int k) {
            float py = -100.f, pxx = -100.f;
            if (p < HW) {
                py = (float)(pyi + k / KS - PAD) + off_s[(2 * k) * 66 + px];
                pxx = (float)(pxi + k % KS - PAD) + off_s[(2 * k + 1) * 66 + px];
            }
            float fy = floorf(py), fx = floorf(pxx);
            int y0 = (int)fy, x0 = (int)fx;
            float ly = py - fy, lx = pxx - fx;
#pragma unroll
            for (int t = 0; t < 4; t++) {
                int iy = y0 + (t >> 1), ixx = x0 + (t & 1);
                float wv = ((t >> 1) ? ly : 1.f - ly) * ((t & 1) ? lx : 1.f - lx);
                bool valid = (iy >= 0) && (iy < 28) && (ixx >= 0) && (ixx < 28);
                float wf = valid ? wv : 0.f;
                w2[t] = b2u(__floats2bfloat162_rn(wf, wf));
                ix[t] = min(max(iy, 0), 27) * 28 + min(max(ixx, 0), 27);
            }
        };
        auto buildB = [&](int c, int b) {
            int ci0 = (c & 1) * 32;
            uint4 s0 = *(const uint4*)(srcT + (size_t)ix[0] * 64 + ci0 + q * 8);
            uint4 s1 = *(const uint4*)(srcT + (size_t)ix[1] * 64 + ci0 + q * 8);
            uint4 s2 = *(const uint4*)(srcT + (size_t)ix[2] * 64 + ci0 + q * 8);
            uint4 s3 = *(const uint4*)(srcT + (size_t)ix[3] * 64 + ci0 + q * 8);
            uint32_t* u0 = (uint32_t*)&s0;
            uint32_t* u1 = (uint32_t*)&s1;
            uint32_t* u2 = (uint32_t*)&s2;
            uint32_t* u3 = (uint32_t*)&s3;
            uint32_t o[4];
#pragma unroll
            for (int r = 0; r < 4; r++) {
                __nv_bfloat162 v = __hmul2(u2b(u0[r]), u2b(w2[0]));
                v = __hfma2(u2b(u1[r]), u2b(w2[1]), v);
                v = __hfma2(u2b(u2[r]), u2b(w2[2]), v);
                v = __hfma2(u2b(u3[r]), u2b(w2[3]), v);
                o[r] = b2u(v);
            }
            *(uint4*)&Bs[b][px * SA + q * 8] = *(uint4*)o;
        };
        tapcalc(0); buildA(WOFF_D, 0, 0); buildB(0, 0);
        __syncthreads();
        for (int c = 0; c < NC; c++) {
            int cb = c & 1, nb = cb ^ 1;
            if (c + 1 < NC) {
                if (((c + 1) & 1) == 0) tapcalc((c + 1) >> 1);
                buildA(WOFF_D, c + 1, nb); buildB(c + 1, nb);
            }
            mma64b(As[cb], Bs[cb], lane, wm, wn, acc);
            __syncthreads();
        }
#pragma unroll
        for (int mt = 0; mt < 2; mt++)
#pragma unroll
            for (int nq = 0; nq < 2; nq++) {
                int pp = p0 + wn * 16 + nq * 8 + tg * 2;
                if (pp >= HW) continue;
#pragma unroll
                for (int h = 0; h < 2; h++) {
                    int co = wm * 32 + mt * 16 + g + h * 8;
                    size_t idx = ((size_t)n * 64 + co) * HW + pp;
                    float2 v;
                    v.x = acc[mt][nq][h * 2];
                    v.y = acc[mt][nq][h * 2 + 1];
                    if (ACC) {
                        float2 o = *(float2*)&g_d[idx];
                        v.x += o.x; v.y += o.y;
                    }
                    *(float2*)&g_d[idx] = v;
                }
            }
    }
}

// ---------------- K9: maxpool + 1x1 + bn3 + |diff| reduce ----------------
__global__ void k_davg(const float* __restrict__ w1, const float* __restrict__ b1,
                       const float* __restrict__ g3, const float* __restrict__ bb3,
                       const float* __restrict__ m3, const float* __restrict__ v3) {
    __shared__ float MP[64 * 68];
    int n = blockIdx.x, p0 = blockIdx.y * 64;
    int b = n / 7, t = n % 7;
    int f = b * 8 + t + 1, fp = b * 8 + t;
    const float* src = &g_out[(size_t)f * 64 * HW];
    const float* pre = &g_out[(size_t)fp * 64 * HW];
    int tid = threadIdx.x;
    for (int i = tid; i < 4096; i += 256) {
        int ci = i >> 6, px = i & 63, p = p0 + px;
        float mv = 0.f;
        if (p < HW) {
            int y = p / 28, x = p % 28;
            const float* s = src + ci * HW;
            mv = -1e30f;
            for (int dy = -1; dy <= 1; dy++) {
                int yy = y + dy;
                if (yy < 0 || yy >= 28) continue;
                for (int dx = -1; dx <= 1; dx++) {
                    int xx = x + dx;
                    if (xx < 0 || xx >= 28) continue;
                    mv = fmaxf(mv, s[yy * 28 + xx]);
                }
            }
        }
        MP[ci * 68 + px] = mv;
    }
    __syncthreads();
    int r = tid >> 4, c = tid & 15;
    float acc[4][4] = {};
    for (int ci = 0; ci < 64; ci++) {
        float a[4], bv[4];
#pragma unroll
        for (int i = 0; i < 4; i++) a[i] = w1[(r * 4 + i) * 64 + ci];
#pragma unroll
        for (int j = 0; j < 4; j++) bv[j] = MP[ci * 68 + c * 4 + j];
#pragma unroll
        for (int i = 0; i < 4; i++)
#pragma unroll
            for (int j = 0; j < 4; j++) acc[i][j] += a[i] * bv[j];
    }
    float sums[4];
#pragma unroll
    for (int i = 0; i < 4; i++) {
        int co = r * 4 + i;
        float sc = g3[co] * rsqrtf(v3[co] + EPS);
        float sh = (b1[co] - m3[co]) * sc + bb3[co];
        float s = 0.f;
#pragma unroll
        for (int j = 0; j < 4; j++) {
            int p = p0 + c * 4 + j;
            if (p < HW) {
                float davg = acc[i][j] * sc + sh;
                s += fabsf(g_d[((size_t)n * 64 + co) * HW + p] + davg - 3.f * pre[co * HW + p]);
            }
        }
        sums[i] = s;
    }
#pragma unroll
    for (int o = 8; o; o >>= 1)
#pragma unroll
        for (int i = 0; i < 4; i++) sums[i] += __shfl_down_sync(0xffffffffu, sums[i], o);
    if (c == 0)
#pragma unroll
        for (int i = 0; i < 4; i++) atomicAdd(&g_cats[(b * 8 + t) * 64 + r * 4 + i], sums[i]);
}

// ---------------- K10: gate ----------------
__global__ void k_gate(const float* __restrict__ cw, const float* __restrict__ cb,
                       const float* __restrict__ g2, const float* __restrict__ b2,
                       const float* __restrict__ m2, const float* __restrict__ v2) {
    int nt = blockIdx.x;
    int co = threadIdx.x;
    __shared__ float mvec[64];
    if (co < 64) mvec[co] = g_cats[nt * 64 + co] * (1.f / 784.f);
    __syncthreads();
    float y = cb[co];
#pragma unroll 8
    for (int ci = 0; ci < 64; ci++) y += mvec[ci] * cw[co * 64 + ci];
    float sc = g2[co] * rsqrtf(v2[co] + EPS);
    y = (y - m2[co]) * sc + b2[co];
    float gate = 1.f / (1.f + expf(-y)) - 0.5f;
    g_gate[nt * 256 + co] = 1.f + gate;
}

// ---------------- K11: final elementwise ----------------
__global__ void k_final(const float* __restrict__ x, float* __restrict__ out) {
    int i = blockIdx.x * 256 + threadIdx.x;
    if (i >= 64 * 256 * (HW / 4)) return;
    int ch = i / (HW / 4);
    float gm = g_gate[ch];
    const float4* x4 = (const float4*)x;
    float4 v = x4[i];
    v.x *= gm; v.y *= gm; v.z *= gm; v.w *= gm;
    ((float4*)out)[i] = v;
}

// ---------------- launch ----------------
extern "C" void kernel_launch(void* const* d_in, const int* in_sizes, int n_in,
                              void* d_out, int out_size) {
    const float* x = (const float*)d_in[0];
    const float* w_down = (const float*)d_in[1];
    const float* b_down = (const float*)d_in[2];
    const float* bn1_g = (const float*)d_in[3];
    const float* bn1_b = (const float*)d_in[4];
    const float* bn1_m = (const float*)d_in[5];
    const float* bn1_v = (const float*)d_in[6];
    const float* tconv_w = (const float*)d_in[7];
    const float* tconv_b = (const float*)d_in[8];
    const float* bnt_g = (const float*)d_in[9];
    const float* bnt_b = (const float*)d_in[10];
    const float* bnt_m = (const float*)d_in[11];
    const float* bnt_v = (const float*)d_in[12];
    const float* off3_w = (const float*)d_in[13];
    const float* off3_b = (const float*)d_in[14];
    const float* def3_w = (const float*)d_in[15];
    const float* off5_w = (const float*)d_in[16];
    const float* off5_b = (const float*)d_in[17];
    const float* def5_w = (const float*)d_in[18];
    const float* conv1_w = (const float*)d_in[19];
    const float* conv1_b = (const float*)d_in[20];
    const float* bn3_g = (const float*)d_in[21];
    const float* bn3_b = (const float*)d_in[22];
    const float* bn3_m = (const float*)d_in[23];
    const float* bn3_v = (const float*)d_in[24];
    const float* conv_w = (const float*)d_in[25];
    const float* conv_b = (const float*)d_in[26];
    const float* bn2_g = (const float*)d_in[27];
    const float* bn2_b = (const float*)d_in[28];
    const float* bn2_m = (const float*)d_in[29];
    const float* bn2_v = (const float*)d_in[30];
    float* out = (float*)d_out;

    k_prep<<<(CH_TOT * 2048 + 255) / 256, 256>>>(w_down, off3_w, def3_w, off5_w, def5_w);
    k_init<<<16, 256>>>();
    k_down<<<dim3(64, 13), 256>>>(x, bn1_g, bn1_b, bn1_m, bn1_v, b_down);
    k_trans<<<dim3(64, 13), 256>>>();
    k_tsum<<<(8 * 64 * HW + 255) / 256, 256>>>();
    k_tstats<<<3 * 8 * 64, 32>>>();
    k_tgate<<<8, 64>>>(tconv_w, tconv_b, bnt_g, bnt_b, bnt_m, bnt_v);
    k_fused<3, false><<<dim3(56, 13), 256>>>(off3_b);
    k_fused<5, true><<<dim3(56, 13), 256>>>(off5_b);
    k_davg<<<dim3(56, 13), 256>>>(conv1_w, conv1_b, bn3_g, bn3_b, bn3_m, bn3_v);
    k_gate<<<64, 256>>>(conv_w, conv_b, bn2_g, bn2_b, bn2_m, bn2_v);
    k_final<<<(64 * 256 * (HW / 4) + 255) / 256, 256>>>(x, out);
}

// round 5
// speedup vs baseline: 4.9802x; 1.4445x over previous
#include <cuda_runtime.h>
#include <cuda_bf16.h>
#include <math.h>
#include <stdint.h>

#define HW 784
#define EPS 1e-5f
#define SA 40   // bf16 smem row stride (80B: conflict-free for ldmatrix & uint4 STS)

// chunk offsets in g_wTh (each chunk = 64 m x 32 k bf16 = 2048)
#define CH_DOWN 0
#define CH_O3   8
#define CH_D3   26
#define CH_O5   44
#define CH_D5   94
#define CH_TOT  144

// ---------------- scratch (device globals; no allocation) ----------------
__device__ float g_out[64 * 64 * HW];                    // bn1 output fp32 [f][ch][p]
__device__ __nv_bfloat16 g_outT[(size_t)64 * HW * 64];   // bf16 [f][p][ch]
__device__ float g_S[8 * 64 * HW];
__device__ float g_d[56 * 64 * HW];
__device__ float g_tstats[3 * 8 * 64 * 9];
__device__ float g_cats[64 * 64];
__device__ float g_gate[64 * 256];
__device__ __nv_bfloat16 g_wTh[CH_TOT * 2048];

__device__ __forceinline__ uint32_t sptr(const void* p) {
    return (uint32_t)__cvta_generic_to_shared(p);
}
__device__ __forceinline__ __nv_bfloat162 u2b(uint32_t u) {
    __nv_bfloat162 h; *(uint32_t*)&h = u; return h;
}
__device__ __forceinline__ uint32_t b2u(__nv_bfloat162 h) {
    return *(uint32_t*)&h;
}

// ---- bf16 mma core: 64(M) x 64(N) block tile, one K-chunk of 32 ----
__device__ __forceinline__ void mma64b(const __nv_bfloat16* As, const __nv_bfloat16* Bs,
                                       int lane, int wm, int wn, float acc[2][2][4]) {
#pragma unroll
    for (int ks = 0; ks < 2; ks++) {
        int l15 = lane & 15, lhi = lane >> 4;
        uint32_t a[2][4];
#pragma unroll
        for (int mt = 0; mt < 2; mt++) {
            uint32_t ad = sptr(As + (wm * 32 + mt * 16 + l15) * SA + lhi * 8 + ks * 16);
            asm volatile("ldmatrix.sync.aligned.m8n8.x4.shared.b16 {%0,%1,%2,%3}, [%4];"
                         : "=r"(a[mt][0]), "=r"(a[mt][1]), "=r"(a[mt][2]), "=r"(a[mt][3])
                         : "r"(ad));
        }
        uint32_t b[4];
        {
            int brow = wn * 16 + (((lane >> 3) & 1) << 3) + (lane & 7);
            uint32_t bd = sptr(Bs + brow * SA + lhi * 8 + ks * 16);
            asm volatile("ldmatrix.sync.aligned.m8n8.x4.shared.b16 {%0,%1,%2,%3}, [%4];"
                         : "=r"(b[0]), "=r"(b[1]), "=r"(b[2]), "=r"(b[3])
                         : "r"(bd));
        }
#pragma unroll
        for (int mt = 0; mt < 2; mt++)
#pragma unroll
            for (int nt = 0; nt < 2; nt++)
                asm volatile(
                    "mma.sync.aligned.m16n8k16.row.col.f32.bf16.bf16.f32 "
                    "{%0,%1,%2,%3},{%4,%5,%6,%7},{%8,%9},{%0,%1,%2,%3};"
                    : "+f"(acc[mt][nt][0]), "+f"(acc[mt][nt][1]),
                      "+f"(acc[mt][nt][2]), "+f"(acc[mt][nt][3])
                    : "r"(a[mt][0]), "r"(a[mt][1]), "r"(a[mt][2]), "r"(a[mt][3]),
                      "r"(b[nt]), "r"(b[nt + 2]));
    }
}

// ---------------- K-1: weight prep -> bf16 [chunk][m][k] ----------------
__global__ void k_prep(const float* __restrict__ wd, const float* __restrict__ o3,
                       const float* __restrict__ d3, const float* __restrict__ o5,
                       const float* __restrict__ d5) {
    int i = blockIdx.x * 256 + threadIdx.x;
    if (i >= CH_TOT * 2048) return;
    int c = i >> 11, j = i & 2047, m = j >> 5, kk = j & 31;
    float v;
    if (c < CH_O3) {
        v = wd[m * 256 + (c - CH_DOWN) * 32 + kk];
    } else if (c < CH_D3) {
        int cc = c - CH_O3, tap = cc >> 1, ci = (cc & 1) * 32 + kk;
        v = (m < 18) ? o3[m * 576 + ci * 9 + tap] : 0.f;
    } else if (c < CH_O5) {
        int cc = c - CH_D3, tap = cc >> 1, ci = (cc & 1) * 32 + kk;
        v = d3[(m * 64 + ci) * 9 + tap];
    } else if (c < CH_D5) {
        int cc = c - CH_O5, tap = cc >> 1, ci = (cc & 1) * 32 + kk;
        v = (m < 50) ? o5[m * 1600 + ci * 25 + tap] : 0.f;
    } else {
        int cc = c - CH_D5, tap = cc >> 1, ci = (cc & 1) * 32 + kk;
        v = d5[(m * 64 + ci) * 25 + tap];
    }
    g_wTh[i] = __float2bfloat16(v);
}

// ---------------- K0: zero reduction buffer ----------------
__global__ void k_init() {
    int i = blockIdx.x * 256 + threadIdx.x;
    if (i < 64 * 64) g_cats[i] = 0.f;
}

// ---------------- K1: 1x1 conv 256->64 + bn1 ----------------
__global__ void k_down(const float* __restrict__ x, const float* __restrict__ g1,
                       const float* __restrict__ b1, const float* __restrict__ m1,
                       const float* __restrict__ v1, const float* __restrict__ bd) {
    __shared__ __align__(16) __nv_bfloat16 As[2][64 * SA];
    __shared__ __align__(16) __nv_bfloat16 Bs[2][64 * SA];
    int nt = blockIdx.x, p0 = blockIdx.y * 64;
    int tid = threadIdx.x, lane = tid & 31, w = tid >> 5, wm = w & 1, wn = w >> 1;
    int px = tid & 63, q = tid >> 6;
    int p = p0 + px;
    const float* xb = x + (size_t)nt * 256 * HW;
    float acc[2][2][4] = {};

    auto buildA = [&](int c, int b) {
        int m = tid >> 2, qa = tid & 3;
        *(uint4*)&As[b][m * SA + qa * 8] =
            *(const uint4*)&g_wTh[(CH_DOWN + c) * 2048 + m * 32 + qa * 8];
    };
    auto buildB = [&](int c, int b) {
        uint32_t u[4];
#pragma unroll
        for (int j = 0; j < 4; j++) {
            float v0 = (p < HW) ? xb[(c * 32 + q * 8 + 2 * j) * HW + p] : 0.f;
            float v1 = (p < HW) ? xb[(c * 32 + q * 8 + 2 * j + 1) * HW + p] : 0.f;
            u[j] = b2u(__floats2bfloat162_rn(v0, v1));
        }
        *(uint4*)&Bs[b][px * SA + q * 8] = *(uint4*)u;
    };
    buildA(0, 0); buildB(0, 0);
    __syncthreads();
    for (int c = 0; c < 8; c++) {
        int cb = c & 1, nb = cb ^ 1;
        if (c + 1 < 8) { buildA(c + 1, nb); buildB(c + 1, nb); }
        mma64b(As[cb], Bs[cb], lane, wm, wn, acc);
        __syncthreads();
    }
    int g = lane >> 2, tg = lane & 3;
#pragma unroll
    for (int mt = 0; mt < 2; mt++)
#pragma unroll
        for (int nq = 0; nq < 2; nq++) {
            int pp = p0 + wn * 16 + nq * 8 + tg * 2;
            if (pp >= HW) continue;
#pragma unroll
            for (int h = 0; h < 2; h++) {
                int co = wm * 32 + mt * 16 + g + h * 8;
                float sc = g1[co] * rsqrtf(v1[co] + EPS);
                float sh = (bd[co] - m1[co]) * sc + b1[co];
                float2 v;
                v.x = acc[mt][nq][h * 2] * sc + sh;
                v.y = acc[mt][nq][h * 2 + 1] * sc + sh;
                *(float2*)&g_out[((size_t)nt * 64 + co) * HW + pp] = v;
            }
        }
}

// ---------------- K1b: transpose g_out -> g_outT bf16 [f][p][ch] ----------------
__global__ void k_trans() {
    __shared__ float ts[64][65];
    int f = blockIdx.x, p0 = blockIdx.y * 64, tid = threadIdx.x;
    for (int i = tid; i < 4096; i += 256) {
        int ci = i >> 6, px = i & 63, p = p0 + px;
        ts[ci][px] = (p < HW) ? g_out[((size_t)f * 64 + ci) * HW + p] : 0.f;
    }
    __syncthreads();
    int px = tid >> 2, q = tid & 3, p = p0 + px;
    if (p < HW) {
        union { __nv_bfloat16 h[16]; uint4 u[2]; } tmp;
#pragma unroll
        for (int j = 0; j < 16; j++) tmp.h[j] = __float2bfloat16(ts[q * 16 + j][px]);
        uint4* dst = (uint4*)&g_outT[((size_t)f * HW + p) * 64 + q * 16];
        dst[0] = tmp.u[0];
        dst[1] = tmp.u[1];
    }
}

// ---------------- K2: sum over T frames ----------------
__global__ void k_tsum() {
    int i = blockIdx.x * 256 + threadIdx.x;
    if (i >= 8 * 64 * HW) return;
    int p = i % HW, ci = (i / HW) % 64, b = i / (HW * 64);
    float s = 0.f;
#pragma unroll
    for (int t = 0; t < 8; t++) s += g_out[((size_t)(b * 8 + t) * 64 + ci) * HW + p];
    g_S[i] = s;
}

// ---------------- K3: border stats ----------------
__global__ void k_tstats() {
    int id = blockIdx.x;
    int ci = id & 63, b = (id >> 6) & 7, s = id >> 9;
    const float* src;
    if (s == 0) src = &g_S[((size_t)b * 64 + ci) * HW];
    else src = &g_out[((size_t)(b * 8 + (s == 1 ? 0 : 7)) * 64 + ci) * HW];
    int lane = threadIdx.x;
    float t = 0, r0 = 0, r27 = 0, c0 = 0, c27 = 0;
    for (int p = lane; p < HW; p += 32) {
        float v = src[p];
        int y = p / 28, x = p % 28;
        t += v;
        if (y == 0) r0 += v;
        if (y == 27) r27 += v;
        if (x == 0) c0 += v;
        if (x == 27) c27 += v;
    }
#pragma unroll
    for (int o = 16; o; o >>= 1) {
        t += __shfl_down_sync(0xffffffffu, t, o);
        r0 += __shfl_down_sync(0xffffffffu, r0, o);
        r27 += __shfl_down_sync(0xffffffffu, r27, o);
        c0 += __shfl_down_sync(0xffffffffu, c0, o);
        c27 += __shfl_down_sync(0xffffffffu, c27, o);
    }
    if (lane == 0) {
        float* o = &g_tstats[(size_t)id * 9];
        o[0] = t; o[1] = r0; o[2] = r27; o[3] = c0; o[4] = c27;
        o[5] = src[0]; o[6] = src[27]; o[7] = src[27 * 28]; o[8] = src[27 * 28 + 27];
    }
}

// ---------------- K4: temporal branch -> gate slot 7 (parallelized) --------------
__global__ void k_tgate(const float* __restrict__ tw, const float* __restrict__ tb,
                        const float* __restrict__ g, const float* __restrict__ bb,
                        const float* __restrict__ m, const float* __restrict__ v) {
    int b = blockIdx.x, co = blockIdx.y;   // grid (8, 64)
    int tid = threadIdx.x;                 // 192 threads: (s, ci)
    int s = tid / 64, ci = tid % 64;
    __shared__ float red[6];
    const float* st = &g_tstats[((size_t)(s * 8 + b) * 64 + ci) * 9];
    float s0 = st[0], s1 = st[1], s2 = st[2], s3 = st[3], s4 = st[4];
    float s5 = st[5], s6 = st[6], s7 = st[7], s8 = st[8];
    const float* w = &tw[((size_t)(co * 64 + ci) * 3) * 9];
    float acc = 0.f;
#pragma unroll
    for (int k = 0; k < 9; k++) {
        int ky = k / 3, kx = k % 3;
        float rs = s0;
        if (ky == 2) rs -= s1;
        if (ky == 0) rs -= s2;
        if (kx == 2) rs -= s3;
        if (kx == 0) rs -= s4;
        if (ky == 2 && kx == 2) rs += s5;
        if (ky == 2 && kx == 0) rs += s6;
        if (ky == 0 && kx == 2) rs += s7;
        if (ky == 0 && kx == 0) rs += s8;
        float we = (s == 0) ? (w[k] + w[9 + k] + w[18 + k])
                            : (s == 1 ? -w[18 + k] : -w[k]);
        acc += we * rs;
    }
#pragma unroll
    for (int o = 16; o; o >>= 1) acc += __shfl_down_sync(0xffffffffu, acc, o);
    if ((tid & 31) == 0) red[tid >> 5] = acc;
    __syncthreads();
    if (tid == 0) {
        float tot = red[0] + red[1] + red[2] + red[3] + red[4] + red[5];
        float val = tot * (1.f / (8.f * 784.f)) + tb[co];
        float sc = g[co] * rsqrtf(v[co] + EPS);
        float tm = (val - m[co]) * sc + bb[co];
        g_cats[(b * 8 + 7) * 64 + co] = tm * 784.f;
    }
}

// ---------------- K5/K6: fused offset-conv + deformable conv ----------------
template <int KS, bool ACC>
__global__ void k_fused(const float* __restrict__ bias) {
    constexpr int K2 = KS * KS, PAD = KS / 2, NC = K2 * 2, MCO = 2 * K2;
    constexpr int WOFF_O = (KS == 3) ? CH_O3 : CH_O5;
    constexpr int WOFF_D = (KS == 3) ? CH_D3 : CH_D5;
    __shared__ __align__(16) __nv_bfloat16 As[2][64 * SA];
    __shared__ __align__(16) __nv_bfloat16 Bs[2][64 * SA];
    __shared__ float off_s[MCO * 66];
    __shared__ int bsi[2][64];          // stage-1 shifted index tables
    __shared__ int2 bt[2][64][4];       // stage-2 bilinear tables {ix, w(bf162)}
    int n = blockIdx.x, p0 = blockIdx.y * 64;
    int f = (n / 7) * 8 + (n % 7) + 1;
    const __nv_bfloat16* srcT = g_outT + (size_t)f * HW * 64;
    int tid = threadIdx.x, lane = tid & 31, w = tid >> 5, wm = w & 1, wn = w >> 1;
    int px_b = tid >> 2, l4 = tid & 3;  // gather mapping: 4 lanes/pixel, 8ch each
    int g = lane >> 2, tg = lane & 3;

    auto buildA = [&](int woff, int c, int b) {
        *(uint4*)&As[b][px_b * SA + l4 * 8] =
            *(const uint4*)&g_wTh[(woff + c) * 2048 + px_b * 32 + l4 * 8];
    };

    // ---------- stage 1: offset-field conv ----------
    float acc[2][2][4] = {};
    {
        auto tapcalc = [&](int k, int tbuf) {
            if (tid < 64) {
                int pq = p0 + tid;
                int yy = pq / 28 + k / KS - PAD, xs = pq % 28 + k % KS - PAD;
                bsi[tbuf][tid] =
                    (pq < HW && yy >= 0 && yy < 28 && xs >= 0 && xs < 28) ? yy * 28 + xs : -1;
            }
        };
        auto buildB = [&](int c, int b, int tbuf) {
            int ci0 = (c & 1) * 32;
            int si = bsi[tbuf][px_b];
            uint4 v = make_uint4(0, 0, 0, 0);
            if (si >= 0) v = *(const uint4*)(srcT + (size_t)si * 64 + ci0 + l4 * 8);
            *(uint4*)&Bs[b][px_b * SA + l4 * 8] = v;
        };
        tapcalc(0, 0); tapcalc(1, 1);
        __syncthreads();
        buildA(WOFF_O, 0, 0); buildB(0, 0, 0);
        __syncthreads();
        for (int c = 0; c < NC; c++) {
            int cb = c & 1, nb = cb ^ 1;
            if (c + 1 < NC) {
                buildA(WOFF_O, c + 1, nb);
                buildB(c + 1, nb, ((c + 1) >> 1) & 1);
            }
            mma64b(As[cb], Bs[cb], lane, wm, wn, acc);
            if ((c & 1) == 1) {
                int t2 = (c >> 1) + 2;
                if (t2 < K2) tapcalc(t2, t2 & 1);
            }
            __syncthreads();
        }
#pragma unroll
        for (int mt = 0; mt < 2; mt++)
#pragma unroll
            for (int nq = 0; nq < 2; nq++) {
                int pp = wn * 16 + nq * 8 + tg * 2;
#pragma unroll
                for (int h = 0; h < 2; h++) {
                    int co = wm * 32 + mt * 16 + g + h * 8;
                    if (co < MCO) {
                        off_s[co * 66 + pp] = acc[mt][nq][h * 2] + bias[co];
                        off_s[co * 66 + pp + 1] = acc[mt][nq][h * 2 + 1] + bias[co];
                    }
                }
            }
    }
    __syncthreads();

    // ---------- stage 2: deformable conv ----------
#pragma unroll
    for (int mt = 0; mt < 2; mt++)
#pragma unroll
        for (int nt2 = 0; nt2 < 2; nt2++)
#pragma unroll
            for (int e = 0; e < 4; e++) acc[mt][nt2][e] = 0.f;
    {
        auto tapcalc = [&](int k, int tbuf) {
            if (tid < 64) {
                int pq = p0 + tid, pyq = pq / 28, pxq = pq % 28;
                float py = -100.f, pxx = -100.f;
                if (pq < HW) {
                    py = (float)(pyq + k / KS - PAD) + off_s[(2 * k) * 66 + tid];
                    pxx = (float)(pxq + k % KS - PAD) + off_s[(2 * k + 1) * 66 + tid];
                }
                float fy = floorf(py), fx = floorf(pxx);
                int y0 = (int)fy, x0 = (int)fx;
                float ly = py - fy, lx = pxx - fx;
#pragma unroll
                for (int t = 0; t < 4; t++) {
                    int iy = y0 + (t >> 1), ixx = x0 + (t & 1);
                    float wv = ((t >> 1) ? ly : 1.f - ly) * ((t & 1) ? lx : 1.f - lx);
                    bool valid = (iy >= 0) && (iy < 28) && (ixx >= 0) && (ixx < 28);
                    float wf = valid ? wv : 0.f;
                    int2 e;
                    e.x = min(max(iy, 0), 27) * 28 + min(max(ixx, 0), 27);
                    e.y = (int)b2u(__floats2bfloat162_rn(wf, wf));
                    bt[tbuf][tid][t] = e;
                }
            }
        };
        auto buildB = [&](int c, int b, int tbuf) {
            int ci0 = (c & 1) * 32;
            const __nv_bfloat16* base = srcT + ci0 + l4 * 8;
            int2 t0 = bt[tbuf][px_b][0], t1 = bt[tbuf][px_b][1];
            int2 t2 = bt[tbuf][px_b][2], t3 = bt[tbuf][px_b][3];
            uint4 s0 = *(const uint4*)(base + (size_t)t0.x * 64);
            uint4 s1 = *(const uint4*)(base + (size_t)t1.x * 64);
            uint4 s2 = *(const uint4*)(base + (size_t)t2.x * 64);
            uint4 s3 = *(const uint4*)(base + (size_t)t3.x * 64);
            uint32_t* u0 = (uint32_t*)&s0;
            uint32_t* u1 = (uint32_t*)&s1;
            uint32_t* u2 = (uint32_t*)&s2;
            uint32_t* u3 = (uint32_t*)&s3;
            uint32_t o[4];
#pragma unroll
            for (int r = 0; r < 4; r++) {
                __nv_bfloat162 v = __hmul2(u2b(u0[r]), u2b((uint32_t)t0.y));
                v = __hfma2(u2b(u1[r]), u2b((uint32_t)t1.y), v);
                v = __hfma2(u2b(u2[r]), u2b((uint32_t)t2.y), v);
                v = __hfma2(u2b(u3[r]), u2b((uint32_t)t3.y), v);
                o[r] = b2u(v);
            }
            *(uint4*)&Bs[b][px_b * SA + l4 * 8] = *(uint4*)o;
        };
        tapcalc(0, 0); tapcalc(1, 1);
        __syncthreads();
        buildA(WOFF_D, 0, 0); buildB(0, 0, 0);
        __syncthreads();
        for (int c = 0; c < NC; c++) {
            int cb = c & 1, nb = cb ^ 1;
            if (c + 1 < NC) {
                buildA(WOFF_D, c + 1, nb);
                buildB(c + 1, nb, ((c + 1) >> 1) & 1);
            }
            mma64b(As[cb], Bs[cb], lane, wm, wn, acc);
            if ((c & 1) == 1) {
                int t2 = (c >> 1) + 2;
                if (t2 < K2) tapcalc(t2, t2 & 1);
            }
            __syncthreads();
        }
#pragma unroll
        for (int mt = 0; mt < 2; mt++)
#pragma unroll
            for (int nq = 0; nq < 2; nq++) {
                int pp = p0 + wn * 16 + nq * 8 + tg * 2;
                if (pp >= HW) continue;
#pragma unroll
                for (int h = 0; h < 2; h++) {
                    int co = wm * 32 + mt * 16 + g + h * 8;
                    size_t idx = ((size_t)n * 64 + co) * HW + pp;
                    float2 v;
                    v.x = acc[mt][nq][h * 2];
                    v.y = acc[mt][nq][h * 2 + 1];
                    if (ACC) {
                        float2 o = *(float2*)&g_d[idx];
                        v.x += o.x; v.y += o.y;
                    }
                    *(float2*)&g_d[idx] = v;
                }
            }
    }
}

// ---------------- K9: maxpool + 1x1 + bn3 + |diff| reduce ----------------
__global__ void k_davg(const float* __restrict__ w1, const float* __restrict__ b1,
                       const float* __restrict__ g3, const float* __restrict__ bb3,
                       const float* __restrict__ m3, const float* __restrict__ v3) {
    __shared__ float MP[64 * 68];
    int n = blockIdx.x, p0 = blockIdx.y * 64;
    int b = n / 7, t = n % 7;
    int f = b * 8 + t + 1, fp = b * 8 + t;
    const float* src = &g_out[(size_t)f * 64 * HW];
    const float* pre = &g_out[(size_t)fp * 64 * HW];
    int tid = threadIdx.x;
    for (int i = tid; i < 4096; i += 256) {
        int ci = i >> 6, px = i & 63, p = p0 + px;
        float mv = 0.f;
        if (p < HW) {
            int y = p / 28, x = p % 28;
            const float* s = src + ci * HW;
            mv = -1e30f;
            for (int dy = -1; dy <= 1; dy++) {
                int yy = y + dy;
                if (yy < 0 || yy >= 28) continue;
                for (int dx = -1; dx <= 1; dx++) {
                    int xx = x + dx;
                    if (xx < 0 || xx >= 28) continue;
                    mv = fmaxf(mv, s[yy * 28 + xx]);
                }
            }
        }
        MP[ci * 68 + px] = mv;
    }
    __syncthreads();
    int r = tid >> 4, c = tid & 15;
    float acc[4][4] = {};
    for (int ci = 0; ci < 64; ci++) {
        float a[4], bv[4];
#pragma unroll
        for (int i = 0; i < 4; i++) a[i] = w1[(r * 4 + i) * 64 + ci];
#pragma unroll
        for (int j = 0; j < 4; j++) bv[j] = MP[ci * 68 + c * 4 + j];
#pragma unroll
        for (int i = 0; i < 4; i++)
#pragma unroll
            for (int j = 0; j < 4; j++) acc[i][j] += a[i] * bv[j];
    }
    float sums[4];
#pragma unroll
    for (int i = 0; i < 4; i++) {
        int co = r * 4 + i;
        float sc = g3[co] * rsqrtf(v3[co] + EPS);
        float sh = (b1[co] - m3[co]) * sc + bb3[co];
        float s = 0.f;
#pragma unroll
        for (int j = 0; j < 4; j++) {
            int p = p0 + c * 4 + j;
            if (p < HW) {
                float davg = acc[i][j] * sc + sh;
                s += fabsf(g_d[((size_t)n * 64 + co) * HW + p] + davg - 3.f * pre[co * HW + p]);
            }
        }
        sums[i] = s;
    }
#pragma unroll
    for (int o = 8; o; o >>= 1)
#pragma unroll
        for (int i = 0; i < 4; i++) sums[i] += __shfl_down_sync(0xffffffffu, sums[i], o);
    if (c == 0)
#pragma unroll
        for (int i = 0; i < 4; i++) atomicAdd(&g_cats[(b * 8 + t) * 64 + r * 4 + i], sums[i]);
}

// ---------------- K10: gate ----------------
__global__ void k_gate(const float* __restrict__ cw, const float* __restrict__ cb,
                       const float* __restrict__ g2, const float* __restrict__ b2,
                       const float* __restrict__ m2, const float* __restrict__ v2) {
    int nt = blockIdx.x;
    int co = threadIdx.x;
    __shared__ float mvec[64];
    if (co < 64) mvec[co] = g_cats[nt * 64 + co] * (1.f / 784.f);
    __syncthreads();
    float y = cb[co];
#pragma unroll 8
    for (int ci = 0; ci < 64; ci++) y += mvec[ci] * cw[co * 64 + ci];
    float sc = g2[co] * rsqrtf(v2[co] + EPS);
    y = (y - m2[co]) * sc + b2[co];
    float gate = 1.f / (1.f + expf(-y)) - 0.5f;
    g_gate[nt * 256 + co] = 1.f + gate;
}

// ---------------- K11: final elementwise ----------------
__global__ void k_final(const float* __restrict__ x, float* __restrict__ out) {
    int i = blockIdx.x * 256 + threadIdx.x;
    if (i >= 64 * 256 * (HW / 4)) return;
    int ch = i / (HW / 4);
    float gm = g_gate[ch];
    const float4* x4 = (const float4*)x;
    float4 v = x4[i];
    v.x *= gm; v.y *= gm; v.z *= gm; v.w *= gm;
    ((float4*)out)[i] = v;
}

// ---------------- launch ----------------
extern "C" void kernel_launch(void* const* d_in, const int* in_sizes, int n_in,
                              void* d_out, int out_size) {
    const float* x = (const float*)d_in[0];
    const float* w_down = (const float*)d_in[1];
    const float* b_down = (const float*)d_in[2];
    const float* bn1_g = (const float*)d_in[3];
    const float* bn1_b = (const float*)d_in[4];
    const float* bn1_m = (const float*)d_in[5];
    const float* bn1_v = (const float*)d_in[6];
    const float* tconv_w = (const float*)d_in[7];
    const float* tconv_b = (const float*)d_in[8];
    const float* bnt_g = (const float*)d_in[9];
    const float* bnt_b = (const float*)d_in[10];
    const float* bnt_m = (const float*)d_in[11];
    const float* bnt_v = (const float*)d_in[12];
    const float* off3_w = (const float*)d_in[13];
    const float* off3_b = (const float*)d_in[14];
    const float* def3_w = (const float*)d_in[15];
    const float* off5_w = (const float*)d_in[16];
    const float* off5_b = (const float*)d_in[17];
    const float* def5_w = (const float*)d_in[18];
    const float* conv1_w = (const float*)d_in[19];
    const float* conv1_b = (const float*)d_in[20];
    const float* bn3_g = (const float*)d_in[21];
    const float* bn3_b = (const float*)d_in[22];
    const float* bn3_m = (const float*)d_in[23];
    const float* bn3_v = (const float*)d_in[24];
    const float* conv_w = (const float*)d_in[25];
    const float* conv_b = (const float*)d_in[26];
    const float* bn2_g = (const float*)d_in[27];
    const float* bn2_b = (const float*)d_in[28];
    const float* bn2_m = (const float*)d_in[29];
    const float* bn2_v = (const float*)d_in[30];
    float* out = (float*)d_out;

    k_prep<<<(CH_TOT * 2048 + 255) / 256, 256>>>(w_down, off3_w, def3_w, off5_w, def5_w);
    k_init<<<16, 256>>>();
    k_down<<<dim3(64, 13), 256>>>(x, bn1_g, bn1_b, bn1_m, bn1_v, b_down);
    k_trans<<<dim3(64, 13), 256>>>();
    k_tsum<<<(8 * 64 * HW + 255) / 256, 256>>>();
    k_tstats<<<3 * 8 * 64, 32>>>();
    k_tgate<<<dim3(8, 64), 192>>>(tconv_w, tconv_b, bnt_g, bnt_b, bnt_m, bnt_v);
    k_fused<3, false><<<dim3(56, 13), 256>>>(off3_b);
    k_fused<5, true><<<dim3(56, 13), 256>>>(off5_b);
    k_davg<<<dim3(56, 13), 256>>>(conv1_w, conv1_b, bn3_g, bn3_b, bn3_m, bn3_v);
    k_gate<<<64, 256>>>(conv_w, conv_b, bn2_g, bn2_b, bn2_m, bn2_v);
    k_final<<<(64 * 256 * (HW / 4) + 255) / 256, 256>>>(x, out);
}

// round 6
// speedup vs baseline: 6.6122x; 1.3277x over previous
#include <cuda_runtime.h>
#include <cuda_bf16.h>
#include <math.h>
#include <stdint.h>

#define HW 784
#define EPS 1e-5f
#define SA 72      // bf16 smem row stride for K=64 tiles (144B; mod 32==8)
#define ROWSZ 4608 // 64*72

// chunk offsets in g_wTh (each chunk = 64 m x 64 k bf16 = 4096)
#define CH_DOWN 0
#define CH_O3   4
#define CH_D3   13
#define CH_O5   22
#define CH_D5   47
#define CH_TOT  72

// ---------------- scratch (device globals; no allocation) ----------------
__device__ float g_out[64 * 64 * HW];                    // bn1 output fp32 [f][ch][p]
__device__ __nv_bfloat16 g_outT[(size_t)64 * HW * 64];   // bf16 [f][p][ch]
__device__ float g_d[56 * 64 * HW];                      // deform3 result
__device__ float g_d2[56 * 64 * HW];                     // deform5 result
__device__ float g_tstats[3 * 8 * 64 * 9];
__device__ float g_cats[64 * 64];
__device__ float g_gate[64 * 256];
__device__ __nv_bfloat16 g_wTh[CH_TOT * 4096];

__device__ __forceinline__ uint32_t sptr(const void* p) {
    return (uint32_t)__cvta_generic_to_shared(p);
}
__device__ __forceinline__ __nv_bfloat162 u2b(uint32_t u) {
    __nv_bfloat162 h; *(uint32_t*)&h = u; return h;
}
__device__ __forceinline__ uint32_t b2u(__nv_bfloat162 h) {
    return *(uint32_t*)&h;
}

// ---- bf16 mma core: 64(M) x 64(N) tile, one K-chunk of 64 ----
__device__ __forceinline__ void mma64k(const __nv_bfloat16* As, const __nv_bfloat16* Bs,
                                       int lane, int wm, int wn, float acc[2][2][4]) {
    int l15 = lane & 15, lhi = lane >> 4;
    int brow = wn * 16 + (((lane >> 3) & 1) << 3) + (lane & 7);
#pragma unroll
    for (int ks = 0; ks < 4; ks++) {
        uint32_t a[2][4];
#pragma unroll
        for (int mt = 0; mt < 2; mt++) {
            uint32_t ad = sptr(As + (wm * 32 + mt * 16 + l15) * SA + lhi * 8 + ks * 16);
            asm volatile("ldmatrix.sync.aligned.m8n8.x4.shared.b16 {%0,%1,%2,%3}, [%4];"
                         : "=r"(a[mt][0]), "=r"(a[mt][1]), "=r"(a[mt][2]), "=r"(a[mt][3])
                         : "r"(ad));
        }
        uint32_t b[4];
        {
            uint32_t bd = sptr(Bs + brow * SA + lhi * 8 + ks * 16);
            asm volatile("ldmatrix.sync.aligned.m8n8.x4.shared.b16 {%0,%1,%2,%3}, [%4];"
                         : "=r"(b[0]), "=r"(b[1]), "=r"(b[2]), "=r"(b[3])
                         : "r"(bd));
        }
#pragma unroll
        for (int mt = 0; mt < 2; mt++)
#pragma unroll
            for (int nt = 0; nt < 2; nt++)
                asm volatile(
                    "mma.sync.aligned.m16n8k16.row.col.f32.bf16.bf16.f32 "
                    "{%0,%1,%2,%3},{%4,%5,%6,%7},{%8,%9},{%0,%1,%2,%3};"
                    : "+f"(acc[mt][nt][0]), "+f"(acc[mt][nt][1]),
                      "+f"(acc[mt][nt][2]), "+f"(acc[mt][nt][3])
                    : "r"(a[mt][0]), "r"(a[mt][1]), "r"(a[mt][2]), "r"(a[mt][3]),
                      "r"(b[nt]), "r"(b[nt + 2]));
    }
}

// ---------------- K-1: weight prep -> bf16 [chunk64][m][k] ----------------
__global__ void k_prep(const float* __restrict__ wd, const float* __restrict__ o3,
                       const float* __restrict__ d3, const float* __restrict__ o5,
                       const float* __restrict__ d5) {
    int i = blockIdx.x * 256 + threadIdx.x;
    if (i >= CH_TOT * 4096) return;
    int c = i >> 12, j = i & 4095, m = j >> 6, kk = j & 63;
    float v;
    if (c < CH_O3) {
        v = wd[m * 256 + (c - CH_DOWN) * 64 + kk];
    } else if (c < CH_D3) {
        int tap = c - CH_O3;
        v = (m < 18) ? o3[m * 576 + kk * 9 + tap] : 0.f;
    } else if (c < CH_O5) {
        int tap = c - CH_D3;
        v = d3[(m * 64 + kk) * 9 + tap];
    } else if (c < CH_D5) {
        int tap = c - CH_O5;
        v = (m < 50) ? o5[m * 1600 + kk * 25 + tap] : 0.f;
    } else {
        int tap = c - CH_D5;
        v = d5[(m * 64 + kk) * 25 + tap];
    }
    g_wTh[i] = __float2bfloat16(v);
}

// ---------------- K0: zero reduction buffer ----------------
__global__ void k_init() {
    int i = blockIdx.x * 256 + threadIdx.x;
    if (i < 64 * 64) g_cats[i] = 0.f;
}

// ---------------- K1: 1x1 conv 256->64 + bn1 (K=64 chunks) ----------------
__global__ void k_down(const float* __restrict__ x, const float* __restrict__ g1,
                       const float* __restrict__ b1, const float* __restrict__ m1,
                       const float* __restrict__ v1, const float* __restrict__ bd) {
    __shared__ __align__(16) __nv_bfloat16 As[2 * ROWSZ];
    __shared__ __align__(16) __nv_bfloat16 Bs[2 * ROWSZ];
    int nt = blockIdx.x, p0 = blockIdx.y * 64;
    int tid = threadIdx.x, lane = tid & 31, w = tid >> 5, wm = w & 1, wn = w >> 1;
    int px_b = tid >> 2, l4 = tid & 3;
    int p = p0 + px_b;
    const float* xb = x + (size_t)nt * 256 * HW;
    float acc[2][2][4] = {};

    auto buildA = [&](int c, int b) {
        const uint4* src = (const uint4*)&g_wTh[(CH_DOWN + c) * 4096 + px_b * 64 + l4 * 16];
        uint4* d = (uint4*)&As[b * ROWSZ + px_b * SA + l4 * 16];
        d[0] = src[0]; d[1] = src[1];
    };
    auto buildB = [&](int c, int b) {
        uint32_t u[8];
#pragma unroll
        for (int j = 0; j < 8; j++) {
            int ch = c * 64 + l4 * 16 + 2 * j;
            float v0 = (p < HW) ? xb[(size_t)ch * HW + p] : 0.f;
            float v1 = (p < HW) ? xb[(size_t)(ch + 1) * HW + p] : 0.f;
            u[j] = b2u(__floats2bfloat162_rn(v0, v1));
        }
        uint4* d = (uint4*)&Bs[b * ROWSZ + px_b * SA + l4 * 16];
        d[0] = *(uint4*)&u[0]; d[1] = *(uint4*)&u[4];
    };
    buildA(0, 0); buildB(0, 0);
    __syncthreads();
    for (int c = 0; c < 4; c++) {
        int cb = c & 1, nb = cb ^ 1;
        if (c + 1 < 4) { buildA(c + 1, nb); buildB(c + 1, nb); }
        mma64k(&As[cb * ROWSZ], &Bs[cb * ROWSZ], lane, wm, wn, acc);
        __syncthreads();
    }
    int g = lane >> 2, tg = lane & 3;
#pragma unroll
    for (int mt = 0; mt < 2; mt++)
#pragma unroll
        for (int nq = 0; nq < 2; nq++) {
            int pp = p0 + wn * 16 + nq * 8 + tg * 2;
            if (pp >= HW) continue;
#pragma unroll
            for (int h = 0; h < 2; h++) {
                int co = wm * 32 + mt * 16 + g + h * 8;
                float sc = g1[co] * rsqrtf(v1[co] + EPS);
                float sh = (bd[co] - m1[co]) * sc + b1[co];
                float2 v;
                v.x = acc[mt][nq][h * 2] * sc + sh;
                v.y = acc[mt][nq][h * 2 + 1] * sc + sh;
                *(float2*)&g_out[((size_t)nt * 64 + co) * HW + pp] = v;
            }
        }
}

// ---------------- K1b: transpose g_out -> g_outT bf16 [f][p][ch] ----------------
__global__ void k_trans() {
    __shared__ float ts[64][65];
    int f = blockIdx.x, p0 = blockIdx.y * 64, tid = threadIdx.x;
    for (int i = tid; i < 4096; i += 256) {
        int ci = i >> 6, px = i & 63, p = p0 + px;
        ts[ci][px] = (p < HW) ? g_out[((size_t)f * 64 + ci) * HW + p] : 0.f;
    }
    __syncthreads();
    int px = tid >> 2, q = tid & 3, p = p0 + px;
    if (p < HW) {
        union { __nv_bfloat16 h[16]; uint4 u[2]; } tmp;
#pragma unroll
        for (int j = 0; j < 16; j++) tmp.h[j] = __float2bfloat16(ts[q * 16 + j][px]);
        uint4* dst = (uint4*)&g_outT[((size_t)f * HW + p) * 64 + q * 16];
        dst[0] = tmp.u[0];
        dst[1] = tmp.u[1];
    }
}

// ---------------- K3: border stats (T-sum inlined) ----------------
__global__ void k_tstats() {
    int id = blockIdx.x;
    int ci = id & 63, b = (id >> 6) & 7, s = id >> 9;
    int lane = threadIdx.x;
    float t = 0, r0 = 0, r27 = 0, c0 = 0, c27 = 0, cval = 0.f;
    for (int p = lane; p < HW; p += 32) {
        float v;
        if (s == 0) {
            const float* base = &g_out[((size_t)(b * 8) * 64 + ci) * HW + p];
            v = 0.f;
#pragma unroll
            for (int tt = 0; tt < 8; tt++) v += base[(size_t)tt * 64 * HW];
        } else {
            v = g_out[((size_t)(b * 8 + (s == 1 ? 0 : 7)) * 64 + ci) * HW + p];
        }
        int y = p / 28, x = p % 28;
        t += v;
        if (y == 0) r0 += v;
        if (y == 27) r27 += v;
        if (x == 0) c0 += v;
        if (x == 27) c27 += v;
        if (p == 0 || p == 27 || p == 756 || p == 783) cval = v;
    }
#pragma unroll
    for (int o = 16; o; o >>= 1) {
        t += __shfl_down_sync(0xffffffffu, t, o);
        r0 += __shfl_down_sync(0xffffffffu, r0, o);
        r27 += __shfl_down_sync(0xffffffffu, r27, o);
        c0 += __shfl_down_sync(0xffffffffu, c0, o);
        c27 += __shfl_down_sync(0xffffffffu, c27, o);
    }
    float o5v = __shfl_sync(0xffffffffu, cval, 0);
    float o6v = __shfl_sync(0xffffffffu, cval, 27);
    float o7v = __shfl_sync(0xffffffffu, cval, 20);
    float o8v = __shfl_sync(0xffffffffu, cval, 15);
    if (lane == 0) {
        float* o = &g_tstats[(size_t)id * 9];
        o[0] = t; o[1] = r0; o[2] = r27; o[3] = c0; o[4] = c27;
        o[5] = o5v; o[6] = o6v; o[7] = o7v; o[8] = o8v;
    }
}

// ---------------- K4: temporal branch -> gate slot 7 ----------------
__global__ void k_tgate(const float* __restrict__ tw, const float* __restrict__ tb,
                        const float* __restrict__ g, const float* __restrict__ bb,
                        const float* __restrict__ m, const float* __restrict__ v) {
    int b = blockIdx.x, co = blockIdx.y;
    int tid = threadIdx.x;
    int s = tid / 64, ci = tid % 64;
    __shared__ float red[6];
    const float* st = &g_tstats[((size_t)(s * 8 + b) * 64 + ci) * 9];
    float s0 = st[0], s1 = st[1], s2 = st[2], s3 = st[3], s4 = st[4];
    float s5 = st[5], s6 = st[6], s7 = st[7], s8 = st[8];
    const float* w = &tw[((size_t)(co * 64 + ci) * 3) * 9];
    float acc = 0.f;
#pragma unroll
    for (int k = 0; k < 9; k++) {
        int ky = k / 3, kx = k % 3;
        float rs = s0;
        if (ky == 2) rs -= s1;
        if (ky == 0) rs -= s2;
        if (kx == 2) rs -= s3;
        if (kx == 0) rs -= s4;
        if (ky == 2 && kx == 2) rs += s5;
        if (ky == 2 && kx == 0) rs += s6;
        if (ky == 0 && kx == 2) rs += s7;
        if (ky == 0 && kx == 0) rs += s8;
        float we = (s == 0) ? (w[k] + w[9 + k] + w[18 + k])
                            : (s == 1 ? -w[18 + k] : -w[k]);
        acc += we * rs;
    }
#pragma unroll
    for (int o = 16; o; o >>= 1) acc += __shfl_down_sync(0xffffffffu, acc, o);
    if ((tid & 31) == 0) red[tid >> 5] = acc;
    __syncthreads();
    if (tid == 0) {
        float tot = red[0] + red[1] + red[2] + red[3] + red[4] + red[5];
        float val = tot * (1.f / (8.f * 784.f)) + tb[co];
        float sc = g[co] * rsqrtf(v[co] + EPS);
        float tm = (val - m[co]) * sc + bb[co];
        g_cats[(b * 8 + 7) * 64 + co] = tm * 784.f;
    }
}

// ---------------- fused offset-conv + deformable conv body ----------------
template <int KS>
__device__ __forceinline__ void fused_body(const float* __restrict__ bias,
                                           float* __restrict__ dst,
                                           __nv_bfloat16* As, __nv_bfloat16* Bs,
                                           float* off_s, int* bsi, int2* bt) {
    constexpr int K2 = KS * KS, PAD = KS / 2, MCO = 2 * K2;
    constexpr int WOFF_O = (KS == 3) ? CH_O3 : CH_O5;
    constexpr int WOFF_D = (KS == 3) ? CH_D3 : CH_D5;
    int n = blockIdx.x, p0 = blockIdx.y * 64;
    int f = (n / 7) * 8 + (n % 7) + 1;
    const __nv_bfloat16* srcT = g_outT + (size_t)f * HW * 64;
    int tid = threadIdx.x, lane = tid & 31, w = tid >> 5, wm = w & 1, wn = w >> 1;
    int px_b = tid >> 2, l4 = tid & 3;
    int g = lane >> 2, tg = lane & 3;

    auto buildA = [&](int woff, int c, int b) {
        const uint4* src = (const uint4*)&g_wTh[(woff + c) * 4096 + px_b * 64 + l4 * 16];
        uint4* d = (uint4*)&As[b * ROWSZ + px_b * SA + l4 * 16];
        d[0] = src[0]; d[1] = src[1];
    };

    // ---------- stage 1: offset-field conv ----------
    float acc[2][2][4] = {};
    {
        auto tapcalc = [&](int k, int tbuf) {
            if (tid < 64) {
                int pq = p0 + tid;
                int yy = pq / 28 + k / KS - PAD, xs = pq % 28 + k % KS - PAD;
                bsi[tbuf * 64 + tid] =
                    (pq < HW && yy >= 0 && yy < 28 && xs >= 0 && xs < 28) ? yy * 28 + xs : -1;
            }
        };
        auto buildB = [&](int c, int b) {
            int si = bsi[(c & 1) * 64 + px_b];
            uint4 v0 = make_uint4(0, 0, 0, 0), v1 = make_uint4(0, 0, 0, 0);
            if (si >= 0) {
                const uint4* s = (const uint4*)(srcT + (size_t)si * 64 + l4 * 16);
                v0 = s[0]; v1 = s[1];
            }
            uint4* d = (uint4*)&Bs[b * ROWSZ + px_b * SA + l4 * 16];
            d[0] = v0; d[1] = v1;
        };
        tapcalc(0, 0);
        if (K2 > 1) tapcalc(1, 1);
        __syncthreads();
        buildA(WOFF_O, 0, 0); buildB(0, 0);
        __syncthreads();
        for (int c = 0; c < K2; c++) {
            int cb = c & 1, nb = cb ^ 1;
            if (c + 1 < K2) { buildA(WOFF_O, c + 1, nb); buildB(c + 1, nb); }
            mma64k(&As[cb * ROWSZ], &Bs[cb * ROWSZ], lane, wm, wn, acc);
            if (c + 2 < K2) tapcalc(c + 2, c & 1);
            __syncthreads();
        }
#pragma unroll
        for (int mt = 0; mt < 2; mt++)
#pragma unroll
            for (int nq = 0; nq < 2; nq++) {
                int pp = wn * 16 + nq * 8 + tg * 2;
#pragma unroll
                for (int h = 0; h < 2; h++) {
                    int co = wm * 32 + mt * 16 + g + h * 8;
                    if (co < MCO) {
                        off_s[co * 66 + pp] = acc[mt][nq][h * 2] + bias[co];
                        off_s[co * 66 + pp + 1] = acc[mt][nq][h * 2 + 1] + bias[co];
                    }
                }
            }
    }
    __syncthreads();

    // ---------- stage 2: deformable conv ----------
#pragma unroll
    for (int mt = 0; mt < 2; mt++)
#pragma unroll
        for (int nt2 = 0; nt2 < 2; nt2++)
#pragma unroll
            for (int e = 0; e < 4; e++) acc[mt][nt2][e] = 0.f;
    {
        auto tapcalc = [&](int k, int tbuf) {
            if (tid < 64) {
                int pq = p0 + tid, pyq = pq / 28, pxq = pq % 28;
                float py = -100.f, pxx = -100.f;
                if (pq < HW) {
                    py = (float)(pyq + k / KS - PAD) + off_s[(2 * k) * 66 + tid];
                    pxx = (float)(pxq + k % KS - PAD) + off_s[(2 * k + 1) * 66 + tid];
                }
                float fy = floorf(py), fx = floorf(pxx);
                int y0 = (int)fy, x0 = (int)fx;
                float ly = py - fy, lx = pxx - fx;
#pragma unroll
                for (int t = 0; t < 4; t++) {
                    int iy = y0 + (t >> 1), ixx = x0 + (t & 1);
                    float wv = ((t >> 1) ? ly : 1.f - ly) * ((t & 1) ? lx : 1.f - lx);
                    bool valid = (iy >= 0) && (iy < 28) && (ixx >= 0) && (ixx < 28);
                    float wf = valid ? wv : 0.f;
                    int2 e;
                    e.x = min(max(iy, 0), 27) * 28 + min(max(ixx, 0), 27);
                    e.y = (int)b2u(__floats2bfloat162_rn(wf, wf));
                    bt[(tbuf * 64 + tid) * 4 + t] = e;
                }
            }
        };
        auto buildB = [&](int c, int b) {
            const int2* tp = &bt[((c & 1) * 64 + px_b) * 4];
            int2 t0 = tp[0], t1 = tp[1], t2 = tp[2], t3 = tp[3];
            const __nv_bfloat16* base = srcT + l4 * 16;
            uint4 s00 = ((const uint4*)(base + (size_t)t0.x * 64))[0];
            uint4 s01 = ((const uint4*)(base + (size_t)t0.x * 64))[1];
            uint4 s10 = ((const uint4*)(base + (size_t)t1.x * 64))[0];
            uint4 s11 = ((const uint4*)(base + (size_t)t1.x * 64))[1];
            uint4 s20 = ((const uint4*)(base + (size_t)t2.x * 64))[0];
            uint4 s21 = ((const uint4*)(base + (size_t)t2.x * 64))[1];
            uint4 s30 = ((const uint4*)(base + (size_t)t3.x * 64))[0];
            uint4 s31 = ((const uint4*)(base + (size_t)t3.x * 64))[1];
            uint32_t o[8];
            uint32_t* u0 = (uint32_t*)&s00;
            uint32_t* u1 = (uint32_t*)&s10;
            uint32_t* u2 = (uint32_t*)&s20;
            uint32_t* u3 = (uint32_t*)&s30;
#pragma unroll
            for (int r = 0; r < 4; r++) {
                __nv_bfloat162 v = __hmul2(u2b(u0[r]), u2b((uint32_t)t0.y));
                v = __hfma2(u2b(u1[r]), u2b((uint32_t)t1.y), v);
                v = __hfma2(u2b(u2[r]), u2b((uint32_t)t2.y), v);
                v = __hfma2(u2b(u3[r]), u2b((uint32_t)t3.y), v);
                o[r] = b2u(v);
            }
            u0 = (uint32_t*)&s01; u1 = (uint32_t*)&s11; u2 = (uint32_t*)&s21; u3 = (uint32_t*)&s31;
#pragma unroll
            for (int r = 0; r < 4; r++) {
                __nv_bfloat162 v = __hmul2(u2b(u0[r]), u2b((uint32_t)t0.y));
                v = __hfma2(u2b(u1[r]), u2b((uint32_t)t1.y), v);
                v = __hfma2(u2b(u2[r]), u2b((uint32_t)t2.y), v);
                v = __hfma2(u2b(u3[r]), u2b((uint32_t)t3.y), v);
                o[4 + r] = b2u(v);
            }
            uint4* d = (uint4*)&Bs[b * ROWSZ + px_b * SA + l4 * 16];
            d[0] = *(uint4*)&o[0]; d[1] = *(uint4*)&o[4];
        };
        tapcalc(0, 0);
        if (K2 > 1) tapcalc(1, 1);
        __syncthreads();
        buildA(WOFF_D, 0, 0); buildB(0, 0);
        __syncthreads();
        for (int c = 0; c < K2; c++) {
            int cb = c & 1, nb = cb ^ 1;
            if (c + 1 < K2) { buildA(WOFF_D, c + 1, nb); buildB(c + 1, nb); }
            mma64k(&As[cb * ROWSZ], &Bs[cb * ROWSZ], lane, wm, wn, acc);
            if (c + 2 < K2) tapcalc(c + 2, c & 1);
            __syncthreads();
        }
#pragma unroll
        for (int mt = 0; mt < 2; mt++)
#pragma unroll
            for (int nq = 0; nq < 2; nq++) {
                int pp = p0 + wn * 16 + nq * 8 + tg * 2;
                if (pp >= HW) continue;
#pragma unroll
                for (int h = 0; h < 2; h++) {
                    int co = wm * 32 + mt * 16 + g + h * 8;
                    size_t idx = ((size_t)n * 64 + co) * HW + pp;
                    float2 v;
                    v.x = acc[mt][nq][h * 2];
                    v.y = acc[mt][nq][h * 2 + 1];
                    *(float2*)&dst[idx] = v;
                }
            }
    }
}

// ---------------- K5: combined fused kernel (z selects 3x3 / 5x5) --------------
__global__ void k_fused_all(const float* __restrict__ bias3, const float* __restrict__ bias5) {
    extern __shared__ __align__(16) char smem_raw[];
    __nv_bfloat16* As = (__nv_bfloat16*)smem_raw;                 // 2*ROWSZ bf16
    __nv_bfloat16* Bs = As + 2 * ROWSZ;                           // 2*ROWSZ bf16
    float* off_s = (float*)(Bs + 2 * ROWSZ);                      // 50*66 floats
    int* bsi = (int*)(off_s + 50 * 66);                           // 128 ints
    int2* bt = (int2*)(bsi + 128);                                // 512 int2
    if (blockIdx.z == 0) fused_body<3>(bias3, g_d, As, Bs, off_s, bsi, bt);
    else                 fused_body<5>(bias5, g_d2, As, Bs, off_s, bsi, bt);
}
#define FUSED_SMEM (4 * ROWSZ * 2 + 50 * 66 * 4 + 128 * 4 + 512 * 8)

// ---------------- K9: maxpool + 1x1 + bn3 + |diff| reduce ----------------
__global__ void k_davg(const float* __restrict__ w1, const float* __restrict__ b1,
                       const float* __restrict__ g3, const float* __restrict__ bb3,
                       const float* __restrict__ m3, const float* __restrict__ v3) {
    __shared__ float MP[64 * 68];
    int n = blockIdx.x, p0 = blockIdx.y * 64;
    int b = n / 7, t = n % 7;
    int f = b * 8 + t + 1, fp = b * 8 + t;
    const float* src = &g_out[(size_t)f * 64 * HW];
    const float* pre = &g_out[(size_t)fp * 64 * HW];
    int tid = threadIdx.x;
    for (int i = tid; i < 4096; i += 256) {
        int ci = i >> 6, px = i & 63, p = p0 + px;
        float mv = 0.f;
        if (p < HW) {
            int y = p / 28, x = p % 28;
            const float* s = src + ci * HW;
            mv = -1e30f;
            for (int dy = -1; dy <= 1; dy++) {
                int yy = y + dy;
                if (yy < 0 || yy >= 28) continue;
                for (int dx = -1; dx <= 1; dx++) {
                    int xx = x + dx;
                    if (xx < 0 || xx >= 28) continue;
                    mv = fmaxf(mv, s[yy * 28 + xx]);
                }
            }
        }
        MP[ci * 68 + px] = mv;
    }
    __syncthreads();
    int r = tid >> 4, c = tid & 15;
    float acc[4][4] = {};
    for (int ci = 0; ci < 64; ci++) {
        float a[4], bv[4];
#pragma unroll
        for (int i = 0; i < 4; i++) a[i] = w1[(r * 4 + i) * 64 + ci];
#pragma unroll
        for (int j = 0; j < 4; j++) bv[j] = MP[ci * 68 + c * 4 + j];
#pragma unroll
        for (int i = 0; i < 4; i++)
#pragma unroll
            for (int j = 0; j < 4; j++) acc[i][j] += a[i] * bv[j];
    }
    float sums[4];
#pragma unroll
    for (int i = 0; i < 4; i++) {
        int co = r * 4 + i;
        float sc = g3[co] * rsqrtf(v3[co] + EPS);
        float sh = (b1[co] - m3[co]) * sc + bb3[co];
        float s = 0.f;
#pragma unroll
        for (int j = 0; j < 4; j++) {
            int p = p0 + c * 4 + j;
            if (p < HW) {
                float davg = acc[i][j] * sc + sh;
                size_t idx = ((size_t)n * 64 + co) * HW + p;
                s += fabsf(g_d[idx] + g_d2[idx] + davg - 3.f * pre[co * HW + p]);
            }
        }
        sums[i] = s;
    }
#pragma unroll
    for (int o = 8; o; o >>= 1)
#pragma unroll
        for (int i = 0; i < 4; i++) sums[i] += __shfl_down_sync(0xffffffffu, sums[i], o);
    if (c == 0)
#pragma unroll
        for (int i = 0; i < 4; i++) atomicAdd(&g_cats[(b * 8 + t) * 64 + r * 4 + i], sums[i]);
}

// ---------------- K10: gate ----------------
__global__ void k_gate(const float* __restrict__ cw, const float* __restrict__ cb,
                       const float* __restrict__ g2, const float* __restrict__ b2,
                       const float* __restrict__ m2, const float* __restrict__ v2) {
    int nt = blockIdx.x;
    int co = threadIdx.x;
    __shared__ float mvec[64];
    if (co < 64) mvec[co] = g_cats[nt * 64 + co] * (1.f / 784.f);
    __syncthreads();
    float y = cb[co];
#pragma unroll 8
    for (int ci = 0; ci < 64; ci++) y += mvec[ci] * cw[co * 64 + ci];
    float sc = g2[co] * rsqrtf(v2[co] + EPS);
    y = (y - m2[co]) * sc + b2[co];
    float gate = 1.f / (1.f + expf(-y)) - 0.5f;
    g_gate[nt * 256 + co] = 1.f + gate;
}

// ---------------- K11: final elementwise ----------------
__global__ void k_final(const float* __restrict__ x, float* __restrict__ out) {
    int i = blockIdx.x * 256 + threadIdx.x;
    if (i >= 64 * 256 * (HW / 4)) return;
    int ch = i / (HW / 4);
    float gm = g_gate[ch];
    const float4* x4 = (const float4*)x;
    float4 v = x4[i];
    v.x *= gm; v.y *= gm; v.z *= gm; v.w *= gm;
    ((float4*)out)[i] = v;
}

// ---------------- launch ----------------
extern "C" void kernel_launch(void* const* d_in, const int* in_sizes, int n_in,
                              void* d_out, int out_size) {
    const float* x = (const float*)d_in[0];
    const float* w_down = (const float*)d_in[1];
    const float* b_down = (const float*)d_in[2];
    const float* bn1_g = (const float*)d_in[3];
    const float* bn1_b = (const float*)d_in[4];
    const float* bn1_m = (const float*)d_in[5];
    const float* bn1_v = (const float*)d_in[6];
    const float* tconv_w = (const float*)d_in[7];
    const float* tconv_b = (const float*)d_in[8];
    const float* bnt_g = (const float*)d_in[9];
    const float* bnt_b = (const float*)d_in[10];
    const float* bnt_m = (const float*)d_in[11];
    const float* bnt_v = (const float*)d_in[12];
    const float* off3_w = (const float*)d_in[13];
    const float* off3_b = (const float*)d_in[14];
    const float* def3_w = (const float*)d_in[15];
    const float* off5_w = (const float*)d_in[16];
    const float* off5_b = (const float*)d_in[17];
    const float* def5_w = (const float*)d_in[18];
    const float* conv1_w = (const float*)d_in[19];
    const float* conv1_b = (const float*)d_in[20];
    const float* bn3_g = (const float*)d_in[21];
    const float* bn3_b = (const float*)d_in[22];
    const float* bn3_m = (const float*)d_in[23];
    const float* bn3_v = (const float*)d_in[24];
    const float* conv_w = (const float*)d_in[25];
    const float* conv_b = (const float*)d_in[26];
    const float* bn2_g = (const float*)d_in[27];
    const float* bn2_b = (const float*)d_in[28];
    const float* bn2_m = (const float*)d_in[29];
    const float* bn2_v = (const float*)d_in[30];
    float* out = (float*)d_out;

    static int smem_set = 0;
    if (!smem_set) {
        cudaFuncSetAttribute(k_fused_all, cudaFuncAttributeMaxDynamicSharedMemorySize,
                             FUSED_SMEM);
        smem_set = 1;
    }

    k_prep<<<(CH_TOT * 4096 + 255) / 256, 256>>>(w_down, off3_w, def3_w, off5_w, def5_w);
    k_init<<<16, 256>>>();
    k_down<<<dim3(64, 13), 256>>>(x, bn1_g, bn1_b, bn1_m, bn1_v, b_down);
    k_trans<<<dim3(64, 13), 256>>>();
    k_tstats<<<3 * 8 * 64, 32>>>();
    k_tgate<<<dim3(8, 64), 192>>>(tconv_w, tconv_b, bnt_g, bnt_b, bnt_m, bnt_v);
    k_fused_all<<<dim3(56, 13, 2), 256, FUSED_SMEM>>>(off3_b, off5_b);
    k_davg<<<dim3(56, 13), 256>>>(conv1_w, conv1_b, bn3_g, bn3_b, bn3_m, bn3_v);
    k_gate<<<64, 256>>>(conv_w, conv_b, bn2_g, bn2_b, bn2_m, bn2_v);
    k_final<<<(64 * 256 * (HW / 4) + 255) / 256, 256>>>(x, out);
}

// round 7
// speedup vs baseline: 7.6949x; 1.1637x over previous
#include <cuda_runtime.h>
#include <cuda_bf16.h>
#include <math.h>
#include <stdint.h>

#define HW 784
#define EPS 1e-5f
#define SA 72      // bf16 smem row stride for K=64 tiles (144B; mod 32==8)
#define ROWSZ 4608 // 64*72

// chunk offsets in g_wTh (each chunk = 64 m x 64 k bf16 = 4096)
#define CH_DOWN 0
#define CH_O3   4
#define CH_D3   13
#define CH_O5   22
#define CH_D5   47
#define CH_TOT  72

// ---------------- scratch (device globals; no allocation) ----------------
__device__ float g_out[64 * 64 * HW];                    // bn1 output fp32 [f][ch][p]
__device__ __nv_bfloat16 g_outT[(size_t)64 * HW * 64];   // bf16 [f][p][ch]
__device__ float g_d[56 * 64 * HW];                      // deform3 result
__device__ float g_d2[56 * 64 * HW];                     // deform5 result
__device__ float g_tstats[3 * 8 * 64 * 9];
__device__ float g_cats[64 * 64];
__device__ float g_gate[64 * 256];
__device__ __nv_bfloat16 g_wTh[CH_TOT * 4096];

__device__ __forceinline__ uint32_t sptr(const void* p) {
    return (uint32_t)__cvta_generic_to_shared(p);
}
__device__ __forceinline__ __nv_bfloat162 u2b(uint32_t u) {
    __nv_bfloat162 h; *(uint32_t*)&h = u; return h;
}
__device__ __forceinline__ uint32_t b2u(__nv_bfloat162 h) {
    return *(uint32_t*)&h;
}

// ---- bf16 mma core: 64(M) x 64(N) tile, one K-chunk of 64 ----
__device__ __forceinline__ void mma64k(const __nv_bfloat16* As, const __nv_bfloat16* Bs,
                                       int lane, int wm, int wn, float acc[2][2][4]) {
    int l15 = lane & 15, lhi = lane >> 4;
    int brow = wn * 16 + (((lane >> 3) & 1) << 3) + (lane & 7);
#pragma unroll
    for (int ks = 0; ks < 4; ks++) {
        uint32_t a[2][4];
#pragma unroll
        for (int mt = 0; mt < 2; mt++) {
            uint32_t ad = sptr(As + (wm * 32 + mt * 16 + l15) * SA + lhi * 8 + ks * 16);
            asm volatile("ldmatrix.sync.aligned.m8n8.x4.shared.b16 {%0,%1,%2,%3}, [%4];"
                         : "=r"(a[mt][0]), "=r"(a[mt][1]), "=r"(a[mt][2]), "=r"(a[mt][3])
                         : "r"(ad));
        }
        uint32_t b[4];
        {
            uint32_t bd = sptr(Bs + brow * SA + lhi * 8 + ks * 16);
            asm volatile("ldmatrix.sync.aligned.m8n8.x4.shared.b16 {%0,%1,%2,%3}, [%4];"
                         : "=r"(b[0]), "=r"(b[1]), "=r"(b[2]), "=r"(b[3])
                         : "r"(bd));
        }
#pragma unroll
        for (int mt = 0; mt < 2; mt++)
#pragma unroll
            for (int nt = 0; nt < 2; nt++)
                asm volatile(
                    "mma.sync.aligned.m16n8k16.row.col.f32.bf16.bf16.f32 "
                    "{%0,%1,%2,%3},{%4,%5,%6,%7},{%8,%9},{%0,%1,%2,%3};"
                    : "+f"(acc[mt][nt][0]), "+f"(acc[mt][nt][1]),
                      "+f"(acc[mt][nt][2]), "+f"(acc[mt][nt][3])
                    : "r"(a[mt][0]), "r"(a[mt][1]), "r"(a[mt][2]), "r"(a[mt][3]),
                      "r"(b[nt]), "r"(b[nt + 2]));
    }
}

// ---------------- K-1: weight prep + zero g_cats ----------------
__global__ void k_prep(const float* __restrict__ wd, const float* __restrict__ o3,
                       const float* __restrict__ d3, const float* __restrict__ o5,
                       const float* __restrict__ d5) {
    int i = blockIdx.x * 256 + threadIdx.x;
    if (i >= CH_TOT * 4096) return;
    if (i < 64 * 64) g_cats[i] = 0.f;
    int c = i >> 12, j = i & 4095, m = j >> 6, kk = j & 63;
    float v;
    if (c < CH_O3) {
        v = wd[m * 256 + (c - CH_DOWN) * 64 + kk];
    } else if (c < CH_D3) {
        int tap = c - CH_O3;
        v = (m < 18) ? o3[m * 576 + kk * 9 + tap] : 0.f;
    } else if (c < CH_O5) {
        int tap = c - CH_D3;
        v = d3[(m * 64 + kk) * 9 + tap];
    } else if (c < CH_D5) {
        int tap = c - CH_O5;
        v = (m < 50) ? o5[m * 1600 + kk * 25 + tap] : 0.f;
    } else {
        int tap = c - CH_D5;
        v = d5[(m * 64 + kk) * 25 + tap];
    }
    g_wTh[i] = __float2bfloat16(v);
}

// ---------------- K1: 1x1 conv 256->64 + bn1 + inline transpose ----------------
__global__ void k_down(const float* __restrict__ x, const float* __restrict__ g1,
                       const float* __restrict__ b1, const float* __restrict__ m1,
                       const float* __restrict__ v1, const float* __restrict__ bd) {
    __shared__ __align__(16) __nv_bfloat16 As[2 * ROWSZ];
    __shared__ __align__(16) __nv_bfloat16 Bs[2 * ROWSZ];
    int nt = blockIdx.x, p0 = blockIdx.y * 64;
    int tid = threadIdx.x, lane = tid & 31, w = tid >> 5, wm = w & 1, wn = w >> 1;
    int px_b = tid >> 2, l4 = tid & 3;
    int p = p0 + px_b;
    const float* xb = x + (size_t)nt * 256 * HW;
    float acc[2][2][4] = {};

    auto buildA = [&](int c, int b) {
        const uint4* src = (const uint4*)&g_wTh[(CH_DOWN + c) * 4096 + px_b * 64 + l4 * 16];
        uint4* d = (uint4*)&As[b * ROWSZ + px_b * SA + l4 * 16];
        d[0] = src[0]; d[1] = src[1];
    };
    auto buildB = [&](int c, int b) {
        uint32_t u[8];
#pragma unroll
        for (int j = 0; j < 8; j++) {
            int ch = c * 64 + l4 * 16 + 2 * j;
            float v0 = (p < HW) ? xb[(size_t)ch * HW + p] : 0.f;
            float v1 = (p < HW) ? xb[(size_t)(ch + 1) * HW + p] : 0.f;
            u[j] = b2u(__floats2bfloat162_rn(v0, v1));
        }
        uint4* d = (uint4*)&Bs[b * ROWSZ + px_b * SA + l4 * 16];
        d[0] = *(uint4*)&u[0]; d[1] = *(uint4*)&u[4];
    };
    buildA(0, 0); buildB(0, 0);
    __syncthreads();
    for (int c = 0; c < 4; c++) {
        int cb = c & 1, nb = cb ^ 1;
        if (c + 1 < 4) { buildA(c + 1, nb); buildB(c + 1, nb); }
        mma64k(&As[cb * ROWSZ], &Bs[cb * ROWSZ], lane, wm, wn, acc);
        __syncthreads();
    }
    int g = lane >> 2, tg = lane & 3;
    __nv_bfloat16* st = As;   // staging tile [px][ch], stride SA
#pragma unroll
    for (int mt = 0; mt < 2; mt++)
#pragma unroll
        for (int nq = 0; nq < 2; nq++) {
            int ppl = wn * 16 + nq * 8 + tg * 2;
            int pp = p0 + ppl;
#pragma unroll
            for (int h = 0; h < 2; h++) {
                int co = wm * 32 + mt * 16 + g + h * 8;
                float sc = g1[co] * rsqrtf(v1[co] + EPS);
                float sh = (bd[co] - m1[co]) * sc + b1[co];
                float vx = acc[mt][nq][h * 2] * sc + sh;
                float vy = acc[mt][nq][h * 2 + 1] * sc + sh;
                if (pp < HW) {
                    float2 v; v.x = vx; v.y = vy;
                    *(float2*)&g_out[((size_t)nt * 64 + co) * HW + pp] = v;
                }
                st[ppl * SA + co] = __float2bfloat16(vx);
                st[(ppl + 1) * SA + co] = __float2bfloat16(vy);
            }
        }
    __syncthreads();
    if (p < HW) {
        uint4 a0 = *(uint4*)&st[px_b * SA + l4 * 16];
        uint4 a1 = *(uint4*)&st[px_b * SA + l4 * 16 + 8];
        uint4* dst = (uint4*)&g_outT[((size_t)nt * HW + p) * 64 + l4 * 16];
        dst[0] = a0; dst[1] = a1;
    }
}

// ---------------- K3: border stats (T-sum inlined) ----------------
__global__ void k_tstats() {
    int id = blockIdx.x;
    int ci = id & 63, b = (id >> 6) & 7, s = id >> 9;
    int lane = threadIdx.x;
    float t = 0, r0 = 0, r27 = 0, c0 = 0, c27 = 0, cval = 0.f;
    for (int p = lane; p < HW; p += 32) {
        float v;
        if (s == 0) {
            const float* base = &g_out[((size_t)(b * 8) * 64 + ci) * HW + p];
            v = 0.f;
#pragma unroll
            for (int tt = 0; tt < 8; tt++) v += base[(size_t)tt * 64 * HW];
        } else {
            v = g_out[((size_t)(b * 8 + (s == 1 ? 0 : 7)) * 64 + ci) * HW + p];
        }
        int y = p / 28, x = p % 28;
        t += v;
        if (y == 0) r0 += v;
        if (y == 27) r27 += v;
        if (x == 0) c0 += v;
        if (x == 27) c27 += v;
        if (p == 0 || p == 27 || p == 756 || p == 783) cval = v;
    }
#pragma unroll
    for (int o = 16; o; o >>= 1) {
        t += __shfl_down_sync(0xffffffffu, t, o);
        r0 += __shfl_down_sync(0xffffffffu, r0, o);
        r27 += __shfl_down_sync(0xffffffffu, r27, o);
        c0 += __shfl_down_sync(0xffffffffu, c0, o);
        c27 += __shfl_down_sync(0xffffffffu, c27, o);
    }
    float o5v = __shfl_sync(0xffffffffu, cval, 0);
    float o6v = __shfl_sync(0xffffffffu, cval, 27);
    float o7v = __shfl_sync(0xffffffffu, cval, 20);
    float o8v = __shfl_sync(0xffffffffu, cval, 15);
    if (lane == 0) {
        float* o = &g_tstats[(size_t)id * 9];
        o[0] = t; o[1] = r0; o[2] = r27; o[3] = c0; o[4] = c27;
        o[5] = o5v; o[6] = o6v; o[7] = o7v; o[8] = o8v;
    }
}

// ---------------- K4: temporal branch -> gate slot 7 ----------------
__global__ void k_tgate(const float* __restrict__ tw, const float* __restrict__ tb,
                        const float* __restrict__ g, const float* __restrict__ bb,
                        const float* __restrict__ m, const float* __restrict__ v) {
    int b = blockIdx.x, co = blockIdx.y;
    int tid = threadIdx.x;
    int s = tid / 64, ci = tid % 64;
    __shared__ float red[6];
    const float* st = &g_tstats[((size_t)(s * 8 + b) * 64 + ci) * 9];
    float s0 = st[0], s1 = st[1], s2 = st[2], s3 = st[3], s4 = st[4];
    float s5 = st[5], s6 = st[6], s7 = st[7], s8 = st[8];
    const float* w = &tw[((size_t)(co * 64 + ci) * 3) * 9];
    float acc = 0.f;
#pragma unroll
    for (int k = 0; k < 9; k++) {
        int ky = k / 3, kx = k % 3;
        float rs = s0;
        if (ky == 2) rs -= s1;
        if (ky == 0) rs -= s2;
        if (kx == 2) rs -= s3;
        if (kx == 0) rs -= s4;
        if (ky == 2 && kx == 2) rs += s5;
        if (ky == 2 && kx == 0) rs += s6;
        if (ky == 0 && kx == 2) rs += s7;
        if (ky == 0 && kx == 0) rs += s8;
        float we = (s == 0) ? (w[k] + w[9 + k] + w[18 + k])
                            : (s == 1 ? -w[18 + k] : -w[k]);
        acc += we * rs;
    }
#pragma unroll
    for (int o = 16; o; o >>= 1) acc += __shfl_down_sync(0xffffffffu, acc, o);
    if ((tid & 31) == 0) red[tid >> 5] = acc;
    __syncthreads();
    if (tid == 0) {
        float tot = red[0] + red[1] + red[2] + red[3] + red[4] + red[5];
        float val = tot * (1.f / (8.f * 784.f)) + tb[co];
        float sc = g[co] * rsqrtf(v[co] + EPS);
        float tm = (val - m[co]) * sc + bb[co];
        g_cats[(b * 8 + 7) * 64 + co] = tm * 784.f;
    }
}

// ---------------- fused offset-conv + deformable conv body ----------------
template <int KS>
__device__ __forceinline__ void fused_body(const float* __restrict__ bias,
                                           float* __restrict__ dst,
                                           __nv_bfloat16* As, __nv_bfloat16* Bs,
                                           float* off_s, int* bsi, int2* bt) {
    constexpr int K2 = KS * KS, PAD = KS / 2, MCO = 2 * K2;
    constexpr int WOFF_O = (KS == 3) ? CH_O3 : CH_O5;
    constexpr int WOFF_D = (KS == 3) ? CH_D3 : CH_D5;
    int n = blockIdx.x, p0 = blockIdx.y * 64;
    int f = (n / 7) * 8 + (n % 7) + 1;
    const __nv_bfloat16* srcT = g_outT + (size_t)f * HW * 64;
    int tid = threadIdx.x, lane = tid & 31, w = tid >> 5, wm = w & 1, wn = w >> 1;
    int px_b = tid >> 2, l4 = tid & 3;       // for buildA (weights)
    int px8 = tid >> 3, l8 = tid & 7;        // for gathers: 8 lanes x 16B = 1 full row
    int g = lane >> 2, tg = lane & 3;

    auto buildA = [&](int woff, int c, int b) {
        const uint4* src = (const uint4*)&g_wTh[(woff + c) * 4096 + px_b * 64 + l4 * 16];
        uint4* d = (uint4*)&As[b * ROWSZ + px_b * SA + l4 * 16];
        d[0] = src[0]; d[1] = src[1];
    };

    // ---------- stage 1: offset-field conv ----------
    float acc[2][2][4] = {};
    {
        auto tapcalc = [&](int k, int tbuf) {
            if (tid < 64) {
                int pq = p0 + tid;
                int yy = pq / 28 + k / KS - PAD, xs = pq % 28 + k % KS - PAD;
                bsi[tbuf * 64 + tid] =
                    (pq < HW && yy >= 0 && yy < 28 && xs >= 0 && xs < 28) ? yy * 28 + xs : -1;
            }
        };
        auto buildB = [&](int c, int b) {
            int buf = c & 1;
#pragma unroll
            for (int half = 0; half < 2; half++) {
                int px = px8 + half * 32;
                int si = bsi[buf * 64 + px];
                uint4 v = make_uint4(0, 0, 0, 0);
                if (si >= 0) v = *(const uint4*)(srcT + (size_t)si * 64 + l8 * 8);
                *(uint4*)&Bs[b * ROWSZ + px * SA + l8 * 8] = v;
            }
        };
        tapcalc(0, 0);
        if (K2 > 1) tapcalc(1, 1);
        __syncthreads();
        buildA(WOFF_O, 0, 0); buildB(0, 0);
        __syncthreads();
        for (int c = 0; c < K2; c++) {
            int cb = c & 1, nb = cb ^ 1;
            if (c + 1 < K2) { buildA(WOFF_O, c + 1, nb); buildB(c + 1, nb); }
            mma64k(&As[cb * ROWSZ], &Bs[cb * ROWSZ], lane, wm, wn, acc);
            if (c + 2 < K2) tapcalc(c + 2, c & 1);
            __syncthreads();
        }
#pragma unroll
        for (int mt = 0; mt < 2; mt++)
#pragma unroll
            for (int nq = 0; nq < 2; nq++) {
                int pp = wn * 16 + nq * 8 + tg * 2;
#pragma unroll
                for (int h = 0; h < 2; h++) {
                    int co = wm * 32 + mt * 16 + g + h * 8;
                    if (co < MCO) {
                        off_s[co * 66 + pp] = acc[mt][nq][h * 2] + bias[co];
                        off_s[co * 66 + pp + 1] = acc[mt][nq][h * 2 + 1] + bias[co];
                    }
                }
            }
    }
    __syncthreads();

    // ---------- stage 2: deformable conv ----------
#pragma unroll
    for (int mt = 0; mt < 2; mt++)
#pragma unroll
        for (int nt2 = 0; nt2 < 2; nt2++)
#pragma unroll
            for (int e = 0; e < 4; e++) acc[mt][nt2][e] = 0.f;
    {
        auto tapcalc = [&](int k, int tbuf) {
            if (tid < 64) {
                int pq = p0 + tid, pyq = pq / 28, pxq = pq % 28;
                float py = -100.f, pxx = -100.f;
                if (pq < HW) {
                    py = (float)(pyq + k / KS - PAD) + off_s[(2 * k) * 66 + tid];
                    pxx = (float)(pxq + k % KS - PAD) + off_s[(2 * k + 1) * 66 + tid];
                }
                float fy = floorf(py), fx = floorf(pxx);
                int y0 = (int)fy, x0 = (int)fx;
                float ly = py - fy, lx = pxx - fx;
#pragma unroll
                for (int t = 0; t < 4; t++) {
                    int iy = y0 + (t >> 1), ixx = x0 + (t & 1);
                    float wv = ((t >> 1) ? ly : 1.f - ly) * ((t & 1) ? lx : 1.f - lx);
                    bool valid = (iy >= 0) && (iy < 28) && (ixx >= 0) && (ixx < 28);
                    float wf = valid ? wv : 0.f;
                    int2 e;
                    e.x = min(max(iy, 0), 27) * 28 + min(max(ixx, 0), 27);
                    e.y = (int)b2u(__floats2bfloat162_rn(wf, wf));
                    bt[(tbuf * 64 + tid) * 4 + t] = e;
                }
            }
        };
        auto buildB = [&](int c, int b) {
            int buf = c & 1;
#pragma unroll
            for (int half = 0; half < 2; half++) {
                int px = px8 + half * 32;
                const int2* tp = &bt[(buf * 64 + px) * 4];
                int2 t0 = tp[0], t1 = tp[1], t2 = tp[2], t3 = tp[3];
                const __nv_bfloat16* base = srcT + l8 * 8;
                uint4 s0 = *(const uint4*)(base + (size_t)t0.x * 64);
                uint4 s1 = *(const uint4*)(base + (size_t)t1.x * 64);
                uint4 s2 = *(const uint4*)(base + (size_t)t2.x * 64);
                uint4 s3 = *(const uint4*)(base + (size_t)t3.x * 64);
                uint32_t* u0 = (uint32_t*)&s0;
                uint32_t* u1 = (uint32_t*)&s1;
                uint32_t* u2 = (uint32_t*)&s2;
                uint32_t* u3 = (uint32_t*)&s3;
                uint32_t o[4];
#pragma unroll
                for (int r = 0; r < 4; r++) {
                    __nv_bfloat162 v = __hmul2(u2b(u0[r]), u2b((uint32_t)t0.y));
                    v = __hfma2(u2b(u1[r]), u2b((uint32_t)t1.y), v);
                    v = __hfma2(u2b(u2[r]), u2b((uint32_t)t2.y), v);
                    v = __hfma2(u2b(u3[r]), u2b((uint32_t)t3.y), v);
                    o[r] = b2u(v);
                }
                *(uint4*)&Bs[b * ROWSZ + px * SA + l8 * 8] = *(uint4*)o;
            }
        };
        tapcalc(0, 0);
        if (K2 > 1) tapcalc(1, 1);
        __syncthreads();
        buildA(WOFF_D, 0, 0); buildB(0, 0);
        __syncthreads();
        for (int c = 0; c < K2; c++) {
            int cb = c & 1, nb = cb ^ 1;
            if (c + 1 < K2) { buildA(WOFF_D, c + 1, nb); buildB(c + 1, nb); }
            mma64k(&As[cb * ROWSZ], &Bs[cb * ROWSZ], lane, wm, wn, acc);
            if (c + 2 < K2) tapcalc(c + 2, c & 1);
            __syncthreads();
        }
#pragma unroll
        for (int mt = 0; mt < 2; mt++)
#pragma unroll
            for (int nq = 0; nq < 2; nq++) {
                int pp = p0 + wn * 16 + nq * 8 + tg * 2;
                if (pp >= HW) continue;
#pragma unroll
                for (int h = 0; h < 2; h++) {
                    int co = wm * 32 + mt * 16 + g + h * 8;
                    size_t idx = ((size_t)n * 64 + co) * HW + pp;
                    float2 v;
                    v.x = acc[mt][nq][h * 2];
                    v.y = acc[mt][nq][h * 2 + 1];
                    *(float2*)&dst[idx] = v;
                }
            }
    }
}

// ---------------- K5: combined fused kernel (z=0 -> 5x5 first) ----------------
__global__ void k_fused_all(const float* __restrict__ bias3, const float* __restrict__ bias5) {
    extern __shared__ __align__(16) char smem_raw[];
    __nv_bfloat16* As = (__nv_bfloat16*)smem_raw;                 // 2*ROWSZ bf16
    __nv_bfloat16* Bs = As + 2 * ROWSZ;                           // 2*ROWSZ bf16
    float* off_s = (float*)(Bs + 2 * ROWSZ);                      // 50*66 floats
    int* bsi = (int*)(off_s + 50 * 66);                           // 128 ints
    int2* bt = (int2*)(bsi + 128);                                // 512 int2
    if (blockIdx.z == 0) fused_body<5>(bias5, g_d2, As, Bs, off_s, bsi, bt);
    else                 fused_body<3>(bias3, g_d, As, Bs, off_s, bsi, bt);
}
#define FUSED_SMEM (4 * ROWSZ * 2 + 50 * 66 * 4 + 128 * 4 + 512 * 8)

// ---------------- K9: maxpool + 1x1 + bn3 + |diff| reduce ----------------
__global__ void k_davg(const float* __restrict__ w1, const float* __restrict__ b1,
                       const float* __restrict__ g3, const float* __restrict__ bb3,
                       const float* __restrict__ m3, const float* __restrict__ v3) {
    __shared__ float MP[64 * 68];
    int n = blockIdx.x, p0 = blockIdx.y * 64;
    int b = n / 7, t = n % 7;
    int f = b * 8 + t + 1, fp = b * 8 + t;
    const float* src = &g_out[(size_t)f * 64 * HW];
    const float* pre = &g_out[(size_t)fp * 64 * HW];
    int tid = threadIdx.x;
    for (int i = tid; i < 4096; i += 256) {
        int ci = i >> 6, px = i & 63, p = p0 + px;
        float mv = 0.f;
        if (p < HW) {
            int y = p / 28, x = p % 28;
            const float* s = src + ci * HW;
            mv = -1e30f;
            for (int dy = -1; dy <= 1; dy++) {
                int yy = y + dy;
                if (yy < 0 || yy >= 28) continue;
                for (int dx = -1; dx <= 1; dx++) {
                    int xx = x + dx;
                    if (xx < 0 || xx >= 28) continue;
                    mv = fmaxf(mv, s[yy * 28 + xx]);
                }
            }
        }
        MP[ci * 68 + px] = mv;
    }
    __syncthreads();
    int r = tid >> 4, c = tid & 15;
    float acc[4][4] = {};
    for (int ci = 0; ci < 64; ci++) {
        float a[4], bv[4];
#pragma unroll
        for (int i = 0; i < 4; i++) a[i] = w1[(r * 4 + i) * 64 + ci];
#pragma unroll
        for (int j = 0; j < 4; j++) bv[j] = MP[ci * 68 + c * 4 + j];
#pragma unroll
        for (int i = 0; i < 4; i++)
#pragma unroll
            for (int j = 0; j < 4; j++) acc[i][j] += a[i] * bv[j];
    }
    float sums[4];
#pragma unroll
    for (int i = 0; i < 4; i++) {
        int co = r * 4 + i;
        float sc = g3[co] * rsqrtf(v3[co] + EPS);
        float sh = (b1[co] - m3[co]) * sc + bb3[co];
        float s = 0.f;
#pragma unroll
        for (int j = 0; j < 4; j++) {
            int p = p0 + c * 4 + j;
            if (p < HW) {
                float davg = acc[i][j] * sc + sh;
                size_t idx = ((size_t)n * 64 + co) * HW + p;
                s += fabsf(g_d[idx] + g_d2[idx] + davg - 3.f * pre[co * HW + p]);
            }
        }
        sums[i] = s;
    }
#pragma unroll
    for (int o = 8; o; o >>= 1)
#pragma unroll
        for (int i = 0; i < 4; i++) sums[i] += __shfl_down_sync(0xffffffffu, sums[i], o);
    if (c == 0)
#pragma unroll
        for (int i = 0; i < 4; i++) atomicAdd(&g_cats[(b * 8 + t) * 64 + r * 4 + i], sums[i]);
}

// ---------------- K10: gate ----------------
__global__ void k_gate(const float* __restrict__ cw, const float* __restrict__ cb,
                       const float* __restrict__ g2, const float* __restrict__ b2,
                       const float* __restrict__ m2, const float* __restrict__ v2) {
    int nt = blockIdx.x;
    int co = threadIdx.x;
    __shared__ float mvec[64];
    if (co < 64) mvec[co] = g_cats[nt * 64 + co] * (1.f / 784.f);
    __syncthreads();
    float y = cb[co];
#pragma unroll 8
    for (int ci = 0; ci < 64; ci++) y += mvec[ci] * cw[co * 64 + ci];
    float sc = g2[co] * rsqrtf(v2[co] + EPS);
    y = (y - m2[co]) * sc + b2[co];
    float gate = 1.f / (1.f + expf(-y)) - 0.5f;
    g_gate[nt * 256 + co] = 1.f + gate;
}

// ---------------- K11: final elementwise ----------------
__global__ void k_final(const float* __restrict__ x, float* __restrict__ out) {
    int i = blockIdx.x * 256 + threadIdx.x;
    if (i >= 64 * 256 * (HW / 4)) return;
    int ch = i / (HW / 4);
    float gm = g_gate[ch];
    const float4* x4 = (const float4*)x;
    float4 v = x4[i];
    v.x *= gm; v.y *= gm; v.z *= gm; v.w *= gm;
    ((float4*)out)[i] = v;
}

// ---------------- launch ----------------
extern "C" void kernel_launch(void* const* d_in, const int* in_sizes, int n_in,
                              void* d_out, int out_size) {
    const float* x = (const float*)d_in[0];
    const float* w_down = (const float*)d_in[1];
    const float* b_down = (const float*)d_in[2];
    const float* bn1_g = (const float*)d_in[3];
    const float* bn1_b = (const float*)d_in[4];
    const float* bn1_m = (const float*)d_in[5];
    const float* bn1_v = (const float*)d_in[6];
    const float* tconv_w = (const float*)d_in[7];
    const float* tconv_b = (const float*)d_in[8];
    const float* bnt_g = (const float*)d_in[9];
    const float* bnt_b = (const float*)d_in[10];
    const float* bnt_m = (const float*)d_in[11];
    const float* bnt_v = (const float*)d_in[12];
    const float* off3_w = (const float*)d_in[13];
    const float* off3_b = (const float*)d_in[14];
    const float* def3_w = (const float*)d_in[15];
    const float* off5_w = (const float*)d_in[16];
    const float* off5_b = (const float*)d_in[17];
    const float* def5_w = (const float*)d_in[18];
    const float* conv1_w = (const float*)d_in[19];
    const float* conv1_b = (const float*)d_in[20];
    const float* bn3_g = (const float*)d_in[21];
    const float* bn3_b = (const float*)d_in[22];
    const float* bn3_m = (const float*)d_in[23];
    const float* bn3_v = (const float*)d_in[24];
    const float* conv_w = (const float*)d_in[25];
    const float* conv_b = (const float*)d_in[26];
    const float* bn2_g = (const float*)d_in[27];
    const float* bn2_b = (const float*)d_in[28];
    const float* bn2_m = (const float*)d_in[29];
    const float* bn2_v = (const float*)d_in[30];
    float* out = (float*)d_out;

    static int smem_set = 0;
    if (!smem_set) {
        cudaFuncSetAttribute(k_fused_all, cudaFuncAttributeMaxDynamicSharedMemorySize,
                             FUSED_SMEM);
        smem_set = 1;
    }

    k_prep<<<(CH_TOT * 4096 + 255) / 256, 256>>>(w_down, off3_w, def3_w, off5_w, def5_w);
    k_down<<<dim3(64, 13), 256>>>(x, bn1_g, bn1_b, bn1_m, bn1_v, b_down);
    k_tstats<<<3 * 8 * 64, 32>>>();
    k_tgate<<<dim3(8, 64), 192>>>(tconv_w, tconv_b, bnt_g, bnt_b, bnt_m, bnt_v);
    k_fused_all<<<dim3(56, 13, 2), 256, FUSED_SMEM>>>(off3_b, off5_b);
    k_davg<<<dim3(56, 13), 256>>>(conv1_w, conv1_b, bn3_g, bn3_b, bn3_m, bn3_v);
    k_gate<<<64, 256>>>(conv_w, conv_b, bn2_g, bn2_b, bn2_m, bn2_v);
    k_final<<<(64 * 256 * (HW / 4) + 255) / 256, 256>>>(x, out);
}

// round 11
// speedup vs baseline: 8.7390x; 1.1357x over previous
#include <cuda_runtime.h>
#include <cuda_bf16.h>
#include <math.h>
#include <stdint.h>

#define HW 784
#define EPS 1e-5f
#define SA 72      // bf16 smem row stride for K=64 tiles (144B; mod 32==8)
#define ROWSZ 4608 // 64*72

// chunk offsets in g_wTh (each chunk = 64 m x 64 k bf16 = 4096)
#define CH_DOWN 0
#define CH_O3   4
#define CH_D3   13
#define CH_O5   22
#define CH_D5   47
#define CH_TOT  72

// ---------------- scratch (device globals; no allocation) ----------------
__device__ float g_out[64 * 64 * HW];                    // bn1 output fp32 [f][ch][p]
__device__ __nv_bfloat16 g_outT[(size_t)64 * HW * 64];   // bf16 [f][p][ch]
__device__ float g_d[56 * 64 * HW];                      // deform3 result
__device__ float g_d2[56 * 64 * HW];                     // deform5 result
__device__ float g_tstats[3 * 8 * 64 * 9];
__device__ float g_cats[64 * 64];
__device__ float g_gate[64 * 256];
__device__ __nv_bfloat16 g_wTh[CH_TOT * 4096];

__device__ __forceinline__ uint32_t sptr(const void* p) {
    return (uint32_t)__cvta_generic_to_shared(p);
}
__device__ __forceinline__ __nv_bfloat162 u2b(uint32_t u) {
    __nv_bfloat162 h; *(uint32_t*)&h = u; return h;
}
__device__ __forceinline__ uint32_t b2u(__nv_bfloat162 h) {
    return *(uint32_t*)&h;
}
__device__ __forceinline__ void cpa16(uint32_t d, const void* s, int sz) {
    asm volatile("cp.async.cg.shared.global [%0], [%1], 16, %2;" :: "r"(d), "l"(s), "r"(sz));
}
#define CP_COMMIT() asm volatile("cp.async.commit_group;")
#define CP_WAIT0()  asm volatile("cp.async.wait_group 0;" ::: "memory")

// ---- bf16 mma core: 64(M) x 64(N) tile, one K-chunk of 64 ----
__device__ __forceinline__ void mma64k(const __nv_bfloat16* As, const __nv_bfloat16* Bs,
                                       int lane, int wm, int wn, float acc[2][2][4]) {
    int l15 = lane & 15, lhi = lane >> 4;
    int brow = wn * 16 + (((lane >> 3) & 1) << 3) + (lane & 7);
#pragma unroll
    for (int ks = 0; ks < 4; ks++) {
        uint32_t a[2][4];
#pragma unroll
        for (int mt = 0; mt < 2; mt++) {
            uint32_t ad = sptr(As + (wm * 32 + mt * 16 + l15) * SA + lhi * 8 + ks * 16);
            asm volatile("ldmatrix.sync.aligned.m8n8.x4.shared.b16 {%0,%1,%2,%3}, [%4];"
                         : "=r"(a[mt][0]), "=r"(a[mt][1]), "=r"(a[mt][2]), "=r"(a[mt][3])
                         : "r"(ad));
        }
        uint32_t b[4];
        {
            uint32_t bd = sptr(Bs + brow * SA + lhi * 8 + ks * 16);
            asm volatile("ldmatrix.sync.aligned.m8n8.x4.shared.b16 {%0,%1,%2,%3}, [%4];"
                         : "=r"(b[0]), "=r"(b[1]), "=r"(b[2]), "=r"(b[3])
                         : "r"(bd));
        }
#pragma unroll
        for (int mt = 0; mt < 2; mt++)
#pragma unroll
            for (int nt = 0; nt < 2; nt++)
                asm volatile(
                    "mma.sync.aligned.m16n8k16.row.col.f32.bf16.bf16.f32 "
                    "{%0,%1,%2,%3},{%4,%5,%6,%7},{%8,%9},{%0,%1,%2,%3};"
                    : "+f"(acc[mt][nt][0]), "+f"(acc[mt][nt][1]),
                      "+f"(acc[mt][nt][2]), "+f"(acc[mt][nt][3])
                    : "r"(a[mt][0]), "r"(a[mt][1]), "r"(a[mt][2]), "r"(a[mt][3]),
                      "r"(b[nt]), "r"(b[nt + 2]));
    }
}

// ---------------- K-1: weight prep + zero g_cats ----------------
__global__ void k_prep(const float* __restrict__ wd, const float* __restrict__ o3,
                       const float* __restrict__ d3, const float* __restrict__ o5,
                       const float* __restrict__ d5) {
    int i = blockIdx.x * 256 + threadIdx.x;
    if (i >= CH_TOT * 4096) return;
    if (i < 64 * 64) g_cats[i] = 0.f;
    int c = i >> 12, j = i & 4095, m = j >> 6, kk = j & 63;
    float v;
    if (c < CH_O3) {
        v = wd[m * 256 + (c - CH_DOWN) * 64 + kk];
    } else if (c < CH_D3) {
        int tap = c - CH_O3;
        v = (m < 18) ? o3[m * 576 + kk * 9 + tap] : 0.f;
    } else if (c < CH_O5) {
        int tap = c - CH_D3;
        v = d3[(m * 64 + kk) * 9 + tap];
    } else if (c < CH_D5) {
        int tap = c - CH_O5;
        v = (m < 50) ? o5[m * 1600 + kk * 25 + tap] : 0.f;
    } else {
        int tap = c - CH_D5;
        v = d5[(m * 64 + kk) * 25 + tap];
    }
    g_wTh[i] = __float2bfloat16(v);
}

// ---------------- K1: 1x1 conv 256->64 + bn1 + inline transpose ----------------
__global__ void k_down(const float* __restrict__ x, const float* __restrict__ g1,
                       const float* __restrict__ b1, const float* __restrict__ m1,
                       const float* __restrict__ v1, const float* __restrict__ bd) {
    __shared__ __align__(16) __nv_bfloat16 As[2 * ROWSZ];
    __shared__ __align__(16) __nv_bfloat16 Bs[2 * ROWSZ];
    int nt = blockIdx.x, p0 = blockIdx.y * 64;
    int tid = threadIdx.x, lane = tid & 31, w = tid >> 5, wm = w & 1, wn = w >> 1;
    int px_b = tid >> 2, l4 = tid & 3;
    int p = p0 + px_b;
    const float* xb = x + (size_t)nt * 256 * HW;
    float acc[2][2][4] = {};

    auto buildA = [&](int c, int b) {
        const char* src = (const char*)&g_wTh[(CH_DOWN + c) * 4096 + px_b * 64 + l4 * 16];
        uint32_t d = sptr(&As[b * ROWSZ + px_b * SA + l4 * 16]);
        cpa16(d, src, 16); cpa16(d + 16, src + 16, 16);
    };
    auto buildB = [&](int c, int b) {
        uint32_t u[8];
#pragma unroll
        for (int j = 0; j < 8; j++) {
            int ch = c * 64 + l4 * 16 + 2 * j;
            float v0 = (p < HW) ? xb[(size_t)ch * HW + p] : 0.f;
            float v1 = (p < HW) ? xb[(size_t)(ch + 1) * HW + p] : 0.f;
            u[j] = b2u(__floats2bfloat162_rn(v0, v1));
        }
        uint4* d = (uint4*)&Bs[b * ROWSZ + px_b * SA + l4 * 16];
        d[0] = *(uint4*)&u[0]; d[1] = *(uint4*)&u[4];
    };
    buildA(0, 0); CP_COMMIT(); buildB(0, 0);
    CP_WAIT0();
    __syncthreads();
    for (int c = 0; c < 4; c++) {
        int cb = c & 1, nb = cb ^ 1;
        if (c + 1 < 4) { buildA(c + 1, nb); CP_COMMIT(); buildB(c + 1, nb); }
        mma64k(&As[cb * ROWSZ], &Bs[cb * ROWSZ], lane, wm, wn, acc);
        CP_WAIT0();
        __syncthreads();
    }
    int g = lane >> 2, tg = lane & 3;
    __nv_bfloat16* st = As;   // staging tile [px][ch], stride SA
#pragma unroll
    for (int mt = 0; mt < 2; mt++)
#pragma unroll
        for (int nq = 0; nq < 2; nq++) {
            int ppl = wn * 16 + nq * 8 + tg * 2;
            int pp = p0 + ppl;
#pragma unroll
            for (int h = 0; h < 2; h++) {
                int co = wm * 32 + mt * 16 + g + h * 8;
                float sc = g1[co] * rsqrtf(v1[co] + EPS);
                float sh = (bd[co] - m1[co]) * sc + b1[co];
                float vx = acc[mt][nq][h * 2] * sc + sh;
                float vy = acc[mt][nq][h * 2 + 1] * sc + sh;
                if (pp < HW) {
                    float2 v; v.x = vx; v.y = vy;
                    *(float2*)&g_out[((size_t)nt * 64 + co) * HW + pp] = v;
                }
                st[ppl * SA + co] = __float2bfloat16(vx);
                st[(ppl + 1) * SA + co] = __float2bfloat16(vy);
            }
        }
    __syncthreads();
    if (p < HW) {
        uint4 a0 = *(uint4*)&st[px_b * SA + l4 * 16];
        uint4 a1 = *(uint4*)&st[px_b * SA + l4 * 16 + 8];
        uint4* dst = (uint4*)&g_outT[((size_t)nt * HW + p) * 64 + l4 * 16];
        dst[0] = a0; dst[1] = a1;
    }
}

// ---------------- K3: border stats (T-sum inlined) ----------------
__global__ void k_tstats() {
    int id = blockIdx.x;
    int ci = id & 63, b = (id >> 6) & 7, s = id >> 9;
    int lane = threadIdx.x;
    float t = 0, r0 = 0, r27 = 0, c0 = 0, c27 = 0, cval = 0.f;
    for (int p = lane; p < HW; p += 32) {
        float v;
        if (s == 0) {
            const float* base = &g_out[((size_t)(b * 8) * 64 + ci) * HW + p];
            v = 0.f;
#pragma unroll
            for (int tt = 0; tt < 8; tt++) v += base[(size_t)tt * 64 * HW];
        } else {
            v = g_out[((size_t)(b * 8 + (s == 1 ? 0 : 7)) * 64 + ci) * HW + p];
        }
        int y = p / 28, x = p % 28;
        t += v;
        if (y == 0) r0 += v;
        if (y == 27) r27 += v;
        if (x == 0) c0 += v;
        if (x == 27) c27 += v;
        if (p == 0 || p == 27 || p == 756 || p == 783) cval = v;
    }
#pragma unroll
    for (int o = 16; o; o >>= 1) {
        t += __shfl_down_sync(0xffffffffu, t, o);
        r0 += __shfl_down_sync(0xffffffffu, r0, o);
        r27 += __shfl_down_sync(0xffffffffu, r27, o);
        c0 += __shfl_down_sync(0xffffffffu, c0, o);
        c27 += __shfl_down_sync(0xffffffffu, c27, o);
    }
    float o5v = __shfl_sync(0xffffffffu, cval, 0);
    float o6v = __shfl_sync(0xffffffffu, cval, 27);
    float o7v = __shfl_sync(0xffffffffu, cval, 20);
    float o8v = __shfl_sync(0xffffffffu, cval, 15);
    if (lane == 0) {
        float* o = &g_tstats[(size_t)id * 9];
        o[0] = t; o[1] = r0; o[2] = r27; o[3] = c0; o[4] = c27;
        o[5] = o5v; o[6] = o6v; o[7] = o7v; o[8] = o8v;
    }
}

// ---------------- K4: temporal branch -> gate slot 7 ----------------
__global__ void k_tgate(const float* __restrict__ tw, const float* __restrict__ tb,
                        const float* __restrict__ g, const float* __restrict__ bb,
                        const float* __restrict__ m, const float* __restrict__ v) {
    int b = blockIdx.x, co = blockIdx.y;
    int tid = threadIdx.x;
    int s = tid / 64, ci = tid % 64;
    __shared__ float red[6];
    const float* st = &g_tstats[((size_t)(s * 8 + b) * 64 + ci) * 9];
    float s0 = st[0], s1 = st[1], s2 = st[2], s3 = st[3], s4 = st[4];
    float s5 = st[5], s6 = st[6], s7 = st[7], s8 = st[8];
    const float* w = &tw[((size_t)(co * 64 + ci) * 3) * 9];
    float acc = 0.f;
#pragma unroll
    for (int k = 0; k < 9; k++) {
        int ky = k / 3, kx = k % 3;
        float rs = s0;
        if (ky == 2) rs -= s1;
        if (ky == 0) rs -= s2;
        if (kx == 2) rs -= s3;
        if (kx == 0) rs -= s4;
        if (ky == 2 && kx == 2) rs += s5;
        if (ky == 2 && kx == 0) rs += s6;
        if (ky == 0 && kx == 2) rs += s7;
        if (ky == 0 && kx == 0) rs += s8;
        float we = (s == 0) ? (w[k] + w[9 + k] + w[18 + k])
                            : (s == 1 ? -w[18 + k] : -w[k]);
        acc += we * rs;
    }
#pragma unroll
    for (int o = 16; o; o >>= 1) acc += __shfl_down_sync(0xffffffffu, acc, o);
    if ((tid & 31) == 0) red[tid >> 5] = acc;
    __syncthreads();
    if (tid == 0) {
        float tot = red[0] + red[1] + red[2] + red[3] + red[4] + red[5];
        float val = tot * (1.f / (8.f * 784.f)) + tb[co];
        float sc = g[co] * rsqrtf(v[co] + EPS);
        float tm = (val - m[co]) * sc + bb[co];
        g_cats[(b * 8 + 7) * 64 + co] = tm * 784.f;
    }
}

// ---------------- fused offset-conv + deformable conv body ----------------
template <int KS>
__device__ __forceinline__ void fused_body(const float* __restrict__ bias,
                                           float* __restrict__ dst,
                                           __nv_bfloat16* As, __nv_bfloat16* Bs,
                                           float* off_s, int* bsi, int2* bt) {
    constexpr int K2 = KS * KS, PAD = KS / 2, MCO = 2 * K2;
    constexpr int WOFF_O = (KS == 3) ? CH_O3 : CH_O5;
    constexpr int WOFF_D = (KS == 3) ? CH_D3 : CH_D5;
    int n = blockIdx.x, p0 = blockIdx.y * 64;
    int f = (n / 7) * 8 + (n % 7) + 1;
    const __nv_bfloat16* srcT = g_outT + (size_t)f * HW * 64;
    int tid = threadIdx.x, lane = tid & 31, w = tid >> 5, wm = w & 1, wn = w >> 1;
    int px_b = tid >> 2, l4 = tid & 3;       // for buildA (weights)
    int px8 = tid >> 3, l8 = tid & 7;        // for gathers: 8 lanes x 16B = 1 full row
    int g = lane >> 2, tg = lane & 3;

    auto buildA = [&](int woff, int c, int b) {
        const char* src = (const char*)&g_wTh[(woff + c) * 4096 + px_b * 64 + l4 * 16];
        uint32_t d = sptr(&As[b * ROWSZ + px_b * SA + l4 * 16]);
        cpa16(d, src, 16); cpa16(d + 16, src + 16, 16);
    };

    // ---------- stage 1: offset-field conv ----------
    float acc[2][2][4] = {};
    {
        auto tapcalc = [&](int k, int tbuf) {
            if (tid < 64) {
                int pq = p0 + tid;
                int yy = pq / 28 + k / KS - PAD, xs = pq % 28 + k % KS - PAD;
                bsi[tbuf * 64 + tid] =
                    (pq < HW && yy >= 0 && yy < 28 && xs >= 0 && xs < 28) ? yy * 28 + xs : -1;
            }
        };
        auto buildB = [&](int c, int b) {
            int buf = c & 1;
#pragma unroll
            for (int half = 0; half < 2; half++) {
                int px = px8 + half * 32;
                int si = bsi[buf * 64 + px];
                const void* s = srcT + (size_t)(si < 0 ? 0 : si) * 64 + l8 * 8;
                cpa16(sptr(&Bs[b * ROWSZ + px * SA + l8 * 8]), s, si >= 0 ? 16 : 0);
            }
        };
        tapcalc(0, 0);
        if (K2 > 1) tapcalc(1, 1);
        __syncthreads();
        buildA(WOFF_O, 0, 0); buildB(0, 0); CP_COMMIT();
        CP_WAIT0();
        __syncthreads();
        for (int c = 0; c < K2; c++) {
            int cb = c & 1, nb = cb ^ 1;
            if (c + 1 < K2) { buildA(WOFF_O, c + 1, nb); buildB(c + 1, nb); CP_COMMIT(); }
            mma64k(&As[cb * ROWSZ], &Bs[cb * ROWSZ], lane, wm, wn, acc);
            if (c + 2 < K2) tapcalc(c + 2, c & 1);
            CP_WAIT0();
            __syncthreads();
        }
#pragma unroll
        for (int mt = 0; mt < 2; mt++)
#pragma unroll
            for (int nq = 0; nq < 2; nq++) {
                int pp = wn * 16 + nq * 8 + tg * 2;
#pragma unroll
                for (int h = 0; h < 2; h++) {
                    int co = wm * 32 + mt * 16 + g + h * 8;
                    if (co < MCO) {
                        off_s[co * 66 + pp] = acc[mt][nq][h * 2] + bias[co];
                        off_s[co * 66 + pp + 1] = acc[mt][nq][h * 2 + 1] + bias[co];
                    }
                }
            }
    }
    __syncthreads();

    // ---------- stage 2: deformable conv ----------
#pragma unroll
    for (int mt = 0; mt < 2; mt++)
#pragma unroll
        for (int nt2 = 0; nt2 < 2; nt2++)
#pragma unroll
            for (int e = 0; e < 4; e++) acc[mt][nt2][e] = 0.f;
    {
        auto tapcalc = [&](int k, int tbuf) {
            if (tid < 64) {
                int pq = p0 + tid, pyq = pq / 28, pxq = pq % 28;
                float py = -100.f, pxx = -100.f;
                if (pq < HW) {
                    py = (float)(pyq + k / KS - PAD) + off_s[(2 * k) * 66 + tid];
                    pxx = (float)(pxq + k % KS - PAD) + off_s[(2 * k + 1) * 66 + tid];
                }
                float fy = floorf(py), fx = floorf(pxx);
                int y0 = (int)fy, x0 = (int)fx;
                float ly = py - fy, lx = pxx - fx;
#pragma unroll
                for (int t = 0; t < 4; t++) {
                    int iy = y0 + (t >> 1), ixx = x0 + (t & 1);
                    float wv = ((t >> 1) ? ly : 1.f - ly) * ((t & 1) ? lx : 1.f - lx);
                    bool valid = (iy >= 0) && (iy < 28) && (ixx >= 0) && (ixx < 28);
                    float wf = valid ? wv : 0.f;
                    int2 e;
                    e.x = min(max(iy, 0), 27) * 28 + min(max(ixx, 0), 27);
                    e.y = (int)b2u(__floats2bfloat162_rn(wf, wf));
                    bt[(tbuf * 64 + tid) * 4 + t] = e;
                }
            }
        };
        auto buildB = [&](int c, int b) {
            int buf = c & 1;
#pragma unroll
            for (int half = 0; half < 2; half++) {
                int px = px8 + half * 32;
                const int2* tp = &bt[(buf * 64 + px) * 4];
                int2 t0 = tp[0], t1 = tp[1], t2 = tp[2], t3 = tp[3];
                const __nv_bfloat16* base = srcT + l8 * 8;
                uint4 s0 = *(const uint4*)(base + (size_t)t0.x * 64);
                uint4 s1 = *(const uint4*)(base + (size_t)t1.x * 64);
                uint4 s2 = *(const uint4*)(base + (size_t)t2.x * 64);
                uint4 s3 = *(const uint4*)(base + (size_t)t3.x * 64);
                uint32_t* u0 = (uint32_t*)&s0;
                uint32_t* u1 = (uint32_t*)&s1;
                uint32_t* u2 = (uint32_t*)&s2;
                uint32_t* u3 = (uint32_t*)&s3;
                uint32_t o[4];
#pragma unroll
                for (int r = 0; r < 4; r++) {
                    __nv_bfloat162 v = __hmul2(u2b(u0[r]), u2b((uint32_t)t0.y));
                    v = __hfma2(u2b(u1[r]), u2b((uint32_t)t1.y), v);
                    v = __hfma2(u2b(u2[r]), u2b((uint32_t)t2.y), v);
                    v = __hfma2(u2b(u3[r]), u2b((uint32_t)t3.y), v);
                    o[r] = b2u(v);
                }
                *(uint4*)&Bs[b * ROWSZ + px * SA + l8 * 8] = *(uint4*)o;
            }
        };
        tapcalc(0, 0);
        if (K2 > 1) tapcalc(1, 1);
        __syncthreads();
        buildA(WOFF_D, 0, 0); CP_COMMIT(); buildB(0, 0);
        CP_WAIT0();
        __syncthreads();
        for (int c = 0; c < K2; c++) {
            int cb = c & 1, nb = cb ^ 1;
            if (c + 1 < K2) { buildA(WOFF_D, c + 1, nb); CP_COMMIT(); buildB(c + 1, nb); }
            mma64k(&As[cb * ROWSZ], &Bs[cb * ROWSZ], lane, wm, wn, acc);
            if (c + 2 < K2) tapcalc(c + 2, c & 1);
            CP_WAIT0();
            __syncthreads();
        }
#pragma unroll
        for (int mt = 0; mt < 2; mt++)
#pragma unroll
            for (int nq = 0; nq < 2; nq++) {
                int pp = p0 + wn * 16 + nq * 8 + tg * 2;
                if (pp >= HW) continue;
#pragma unroll
                for (int h = 0; h < 2; h++) {
                    int co = wm * 32 + mt * 16 + g + h * 8;
                    size_t idx = ((size_t)n * 64 + co) * HW + pp;
                    float2 v;
                    v.x = acc[mt][nq][h * 2];
                    v.y = acc[mt][nq][h * 2 + 1];
                    *(float2*)&dst[idx] = v;
                }
            }
    }
}

// ---------------- K5: combined fused kernel (z=0 -> 5x5 first) ----------------
__global__ void k_fused_all(const float* __restrict__ bias3, const float* __restrict__ bias5) {
    extern __shared__ __align__(16) char smem_raw[];
    __nv_bfloat16* As = (__nv_bfloat16*)smem_raw;                 // 2*ROWSZ bf16
    __nv_bfloat16* Bs = As + 2 * ROWSZ;                           // 2*ROWSZ bf16
    float* off_s = (float*)(Bs + 2 * ROWSZ);                      // 50*66 floats
    int* bsi = (int*)(off_s + 50 * 66);                           // 128 ints
    int2* bt = (int2*)(bsi + 128);                                // 512 int2
    if (blockIdx.z == 0) fused_body<5>(bias5, g_d2, As, Bs, off_s, bsi, bt);
    else                 fused_body<3>(bias3, g_d, As, Bs, off_s, bsi, bt);
}
#define FUSED_SMEM (4 * ROWSZ * 2 + 50 * 66 * 4 + 128 * 4 + 512 * 8)

// ---------------- K9: maxpool + 1x1 + bn3 + |diff| reduce ----------------
__global__ void k_davg(const float* __restrict__ w1, const float* __restrict__ b1,
                       const float* __restrict__ g3, const float* __restrict__ bb3,
                       const float* __restrict__ m3, const float* __restrict__ v3) {
    __shared__ float MP[64 * 68];
    int n = blockIdx.x, p0 = blockIdx.y * 64;
    int b = n / 7, t = n % 7;
    int f = b * 8 + t + 1, fp = b * 8 + t;
    const float* src = &g_out[(size_t)f * 64 * HW];
    const float* pre = &g_out[(size_t)fp * 64 * HW];
    int tid = threadIdx.x;
    for (int i = tid; i < 4096; i += 256) {
        int ci = i >> 6, px = i & 63, p = p0 + px;
        float mv = 0.f;
        if (p < HW) {
            int y = p / 28, x = p % 28;
            const float* s = src + ci * HW;
            mv = -1e30f;
            for (int dy = -1; dy <= 1; dy++) {
                int yy = y + dy;
                if (yy < 0 || yy >= 28) continue;
                for (int dx = -1; dx <= 1; dx++) {
                    int xx = x + dx;
                    if (xx < 0 || xx >= 28) continue;
                    mv = fmaxf(mv, s[yy * 28 + xx]);
                }
            }
        }
        MP[ci * 68 + px] = mv;
    }
    __syncthreads();
    int r = tid >> 4, c = tid & 15;
    float acc[4][4] = {};
    for (int ci = 0; ci < 64; ci++) {
        float a[4], bv[4];
#pragma unroll
        for (int i = 0; i < 4; i++) a[i] = w1[(r * 4 + i) * 64 + ci];
#pragma unroll
        for (int j = 0; j < 4; j++) bv[j] = MP[ci * 68 + c * 4 + j];
#pragma unroll
        for (int i = 0; i < 4; i++)
#pragma unroll
            for (int j = 0; j < 4; j++) acc[i][j] += a[i] * bv[j];
    }
    float sums[4];
#pragma unroll
    for (int i = 0; i < 4; i++) {
        int co = r * 4 + i;
        float sc = g3[co] * rsqrtf(v3[co] + EPS);
        float sh = (b1[co] - m3[co]) * sc + bb3[co];
        float s = 0.f;
#pragma unroll
        for (int j = 0; j < 4; j++) {
            int p = p0 + c * 4 + j;
            if (p < HW) {
                float davg = acc[i][j] * sc + sh;
                size_t idx = ((size_t)n * 64 + co) * HW + p;
                s += fabsf(g_d[idx] + g_d2[idx] + davg - 3.f * pre[co * HW + p]);
            }
        }
        sums[i] = s;
    }
#pragma unroll
    for (int o = 8; o; o >>= 1)
#pragma unroll
        for (int i = 0; i < 4; i++) sums[i] += __shfl_down_sync(0xffffffffu, sums[i], o);
    if (c == 0)
#pragma unroll
        for (int i = 0; i < 4; i++) atomicAdd(&g_cats[(b * 8 + t) * 64 + r * 4 + i], sums[i]);
}

// ---------------- K10: gate ----------------
__global__ void k_gate(const float* __restrict__ cw, const float* __restrict__ cb,
                       const float* __restrict__ g2, const float* __restrict__ b2,
                       const float* __restrict__ m2, const float* __restrict__ v2) {
    int nt = blockIdx.x;
    int co = threadIdx.x;
    __shared__ float mvec[64];
    if (co < 64) mvec[co] = g_cats[nt * 64 + co] * (1.f / 784.f);
    __syncthreads();
    float y = cb[co];
#pragma unroll 8
    for (int ci = 0; ci < 64; ci++) y += mvec[ci] * cw[co * 64 + ci];
    float sc = g2[co] * rsqrtf(v2[co] + EPS);
    y = (y - m2[co]) * sc + b2[co];
    float gate = 1.f / (1.f + expf(-y)) - 0.5f;
    g_gate[nt * 256 + co] = 1.f + gate;
}

// ---------------- K11: final elementwise ----------------
__global__ void k_final(const float* __restrict__ x, float* __restrict__ out) {
    int i = blockIdx.x * 256 + threadIdx.x;
    if (i >= 64 * 256 * (HW / 4)) return;
    int ch = i / (HW / 4);
    float gm = g_gate[ch];
    const float4* x4 = (const float4*)x;
    float4 v = x4[i];
    v.x *= gm; v.y *= gm; v.z *= gm; v.w *= gm;
    ((float4*)out)[i] = v;
}

// ---------------- launch ----------------
extern "C" void kernel_launch(void* const* d_in, const int* in_sizes, int n_in,
                              void* d_out, int out_size) {
    const float* x = (const float*)d_in[0];
    const float* w_down = (const float*)d_in[1];
    const float* b_down = (const float*)d_in[2];
    const float* bn1_g = (const float*)d_in[3];
    const float* bn1_b = (const float*)d_in[4];
    const float* bn1_m = (const float*)d_in[5];
    const float* bn1_v = (const float*)d_in[6];
    const float* tconv_w = (const float*)d_in[7];
    const float* tconv_b = (const float*)d_in[8];
    const float* bnt_g = (const float*)d_in[9];
    const float* bnt_b = (const float*)d_in[10];
    const float* bnt_m = (const float*)d_in[11];
    const float* bnt_v = (const float*)d_in[12];
    const float* off3_w = (const float*)d_in[13];
    const float* off3_b = (const float*)d_in[14];
    const float* def3_w = (const float*)d_in[15];
    const float* off5_w = (const float*)d_in[16];
    const float* off5_b = (const float*)d_in[17];
    const float* def5_w = (const float*)d_in[18];
    const float* conv1_w = (const float*)d_in[19];
    const float* conv1_b = (const float*)d_in[20];
    const float* bn3_g = (const float*)d_in[21];
    const float* bn3_b = (const float*)d_in[22];
    const float* bn3_m = (const float*)d_in[23];
    const float* bn3_v = (const float*)d_in[24];
    const float* conv_w = (const float*)d_in[25];
    const float* conv_b = (const float*)d_in[26];
    const float* bn2_g = (const float*)d_in[27];
    const float* bn2_b = (const float*)d_in[28];
    const float* bn2_m = (const float*)d_in[29];
    const float* bn2_v = (const float*)d_in[30];
    float* out = (float*)d_out;

    static int smem_set = 0;
    if (!smem_set) {
        cudaFuncSetAttribute(k_fused_all, cudaFuncAttributeMaxDynamicSharedMemorySize,
                             FUSED_SMEM);
        smem_set = 1;
    }

    k_prep<<<(CH_TOT * 4096 + 255) / 256, 256>>>(w_down, off3_w, def3_w, off5_w, def5_w);
    k_down<<<dim3(64, 13), 256>>>(x, bn1_g, bn1_b, bn1_m, bn1_v, b_down);
    k_tstats<<<3 * 8 * 64, 32>>>();
    k_fused_all<<<dim3(56, 13, 2), 256, FUSED_SMEM>>>(off3_b, off5_b);
    k_tgate<<<dim3(8, 64), 192>>>(tconv_w, tconv_b, bnt_g, bnt_b, bnt_m, bnt_v);
    k_davg<<<dim3(56, 13), 256>>>(conv1_w, conv1_b, bn3_g, bn3_b, bn3_m, bn3_v);
    k_gate<<<64, 256>>>(conv_w, conv_b, bn2_g, bn2_b, bn2_m, bn2_v);
    k_final<<<(64 * 256 * (HW / 4) + 255) / 256, 256>>>(x, out);
}

// round 14
// speedup vs baseline: 8.7633x; 1.0028x over previous
#include <cuda_runtime.h>
#include <cuda_bf16.h>
#include <math.h>
#include <stdint.h>

#define HW 784
#define EPS 1e-5f
#define SA 72        // bf16 smem row stride (144B; mod 32==8)
#define ROWSZ 4608   // 64*72  (A tile)
#define BROWSZ 9216  // 128*72 (B tile, 128 rows)

// chunk offsets in g_wTh (each chunk = 64 m x 64 k bf16 = 4096)
#define CH_DOWN 0
#define CH_O3   4
#define CH_D3   13
#define CH_O5   22
#define CH_D5   47
#define CH_TOT  72

// ---------------- scratch (device globals; no allocation) ----------------
__device__ float g_out[64 * 64 * HW];                    // bn1 output fp32 [f][ch][p]
__device__ __nv_bfloat16 g_outT[(size_t)64 * HW * 64];   // bf16 [f][p][ch]
__device__ float g_d[56 * 64 * HW];                      // deform3 result
__device__ float g_d2[56 * 64 * HW];                     // deform5 result
__device__ float g_tstats[3 * 8 * 64 * 9];
__device__ float g_cats[64 * 64];
__device__ float g_gate[64 * 256];
__device__ __nv_bfloat16 g_wTh[CH_TOT * 4096];

__device__ __forceinline__ uint32_t sptr(const void* p) {
    return (uint32_t)__cvta_generic_to_shared(p);
}
__device__ __forceinline__ __nv_bfloat162 u2b(uint32_t u) {
    __nv_bfloat162 h; *(uint32_t*)&h = u; return h;
}
__device__ __forceinline__ uint32_t b2u(__nv_bfloat162 h) {
    return *(uint32_t*)&h;
}
__device__ __forceinline__ void cpa16(uint32_t d, const void* s, int sz) {
    asm volatile("cp.async.cg.shared.global [%0], [%1], 16, %2;" :: "r"(d), "l"(s), "r"(sz));
}
#define CP_COMMIT() asm volatile("cp.async.commit_group;")
#define CP_WAIT0()  asm volatile("cp.async.wait_group 0;" ::: "memory")

// ---- bf16 mma core: 64(M) x 64(N) tile (N=64 variant, k_down) ----
__device__ __forceinline__ void mma64k(const __nv_bfloat16* As, const __nv_bfloat16* Bs,
                                       int lane, int wm, int wn, float acc[2][2][4]) {
    int l15 = lane & 15, lhi = lane >> 4;
    int brow = wn * 16 + (((lane >> 3) & 1) << 3) + (lane & 7);
#pragma unroll
    for (int ks = 0; ks < 4; ks++) {
        uint32_t a[2][4];
#pragma unroll
        for (int mt = 0; mt < 2; mt++) {
            uint32_t ad = sptr(As + (wm * 32 + mt * 16 + l15) * SA + lhi * 8 + ks * 16);
            asm volatile("ldmatrix.sync.aligned.m8n8.x4.shared.b16 {%0,%1,%2,%3}, [%4];"
                         : "=r"(a[mt][0]), "=r"(a[mt][1]), "=r"(a[mt][2]), "=r"(a[mt][3])
                         : "r"(ad));
        }
        uint32_t b[4];
        {
            uint32_t bd = sptr(Bs + brow * SA + lhi * 8 + ks * 16);
            asm volatile("ldmatrix.sync.aligned.m8n8.x4.shared.b16 {%0,%1,%2,%3}, [%4];"
                         : "=r"(b[0]), "=r"(b[1]), "=r"(b[2]), "=r"(b[3])
                         : "r"(bd));
        }
#pragma unroll
        for (int mt = 0; mt < 2; mt++)
#pragma unroll
            for (int nt = 0; nt < 2; nt++)
                asm volatile(
                    "mma.sync.aligned.m16n8k16.row.col.f32.bf16.bf16.f32 "
                    "{%0,%1,%2,%3},{%4,%5,%6,%7},{%8,%9},{%0,%1,%2,%3};"
                    : "+f"(acc[mt][nt][0]), "+f"(acc[mt][nt][1]),
                      "+f"(acc[mt][nt][2]), "+f"(acc[mt][nt][3])
                    : "r"(a[mt][0]), "r"(a[mt][1]), "r"(a[mt][2]), "r"(a[mt][3]),
                      "r"(b[nt]), "r"(b[nt + 2]));
    }
}

// ---- bf16 mma core: 64(M) x 128(N) tile (fused kernel) ----
__device__ __forceinline__ void mma128k(const __nv_bfloat16* As, const __nv_bfloat16* Bs,
                                        int lane, int wm, int wn, float acc[2][4][4]) {
    int l15 = lane & 15, lhi = lane >> 4;
    int brow0 = wn * 32 + (((lane >> 3) & 1) << 3) + (lane & 7);
#pragma unroll
    for (int ks = 0; ks < 4; ks++) {
        uint32_t a[2][4];
#pragma unroll
        for (int mt = 0; mt < 2; mt++) {
            uint32_t ad = sptr(As + (wm * 32 + mt * 16 + l15) * SA + lhi * 8 + ks * 16);
            asm volatile("ldmatrix.sync.aligned.m8n8.x4.shared.b16 {%0,%1,%2,%3}, [%4];"
                         : "=r"(a[mt][0]), "=r"(a[mt][1]), "=r"(a[mt][2]), "=r"(a[mt][3])
                         : "r"(ad));
        }
        uint32_t b[2][4];
#pragma unroll
        for (int bq = 0; bq < 2; bq++) {
            uint32_t bd = sptr(Bs + (brow0 + bq * 16) * SA + lhi * 8 + ks * 16);
            asm volatile("ldmatrix.sync.aligned.m8n8.x4.shared.b16 {%0,%1,%2,%3}, [%4];"
                         : "=r"(b[bq][0]), "=r"(b[bq][1]), "=r"(b[bq][2]), "=r"(b[bq][3])
                         : "r"(bd));
        }
#pragma unroll
        for (int mt = 0; mt < 2; mt++)
#pragma unroll
            for (int bq = 0; bq < 2; bq++)
#pragma unroll
                for (int j = 0; j < 2; j++) {
                    int nt = bq * 2 + j;
                    asm volatile(
                        "mma.sync.aligned.m16n8k16.row.col.f32.bf16.bf16.f32 "
                        "{%0,%1,%2,%3},{%4,%5,%6,%7},{%8,%9},{%0,%1,%2,%3};"
                        : "+f"(acc[mt][nt][0]), "+f"(acc[mt][nt][1]),
                          "+f"(acc[mt][nt][2]), "+f"(acc[mt][nt][3])
                        : "r"(a[mt][0]), "r"(a[mt][1]), "r"(a[mt][2]), "r"(a[mt][3]),
                          "r"(b[bq][j]), "r"(b[bq][j + 2]));
                }
    }
}

// ---------------- K-1: weight prep + zero g_cats ----------------
__global__ void k_prep(const float* __restrict__ wd, const float* __restrict__ o3,
                       const float* __restrict__ d3, const float* __restrict__ o5,
                       const float* __restrict__ d5) {
    int i = blockIdx.x * 256 + threadIdx.x;
    if (i >= CH_TOT * 4096) return;
    if (i < 64 * 64) g_cats[i] = 0.f;
    int c = i >> 12, j = i & 4095, m = j >> 6, kk = j & 63;
    float v;
    if (c < CH_O3) {
        v = wd[m * 256 + (c - CH_DOWN) * 64 + kk];
    } else if (c < CH_D3) {
        int tap = c - CH_O3;
        v = (m < 18) ? o3[m * 576 + kk * 9 + tap] : 0.f;
    } else if (c < CH_O5) {
        int tap = c - CH_D3;
        v = d3[(m * 64 + kk) * 9 + tap];
    } else if (c < CH_D5) {
        int tap = c - CH_O5;
        v = (m < 50) ? o5[m * 1600 + kk * 25 + tap] : 0.f;
    } else {
        int tap = c - CH_D5;
        v = d5[(m * 64 + kk) * 25 + tap];
    }
    g_wTh[i] = __float2bfloat16(v);
}

// ---------------- K1: 1x1 conv 256->64 + bn1 + inline transpose ----------------
__global__ void k_down(const float* __restrict__ x, const float* __restrict__ g1,
                       const float* __restrict__ b1, const float* __restrict__ m1,
                       const float* __restrict__ v1, const float* __restrict__ bd) {
    __shared__ __align__(16) __nv_bfloat16 As[2 * ROWSZ];
    __shared__ __align__(16) __nv_bfloat16 Bs[2 * ROWSZ];
    int nt = blockIdx.x, p0 = blockIdx.y * 64;
    int tid = threadIdx.x, lane = tid & 31, w = tid >> 5, wm = w & 1, wn = w >> 1;
    int px_b = tid >> 2, l4 = tid & 3;
    int p = p0 + px_b;
    const float* xb = x + (size_t)nt * 256 * HW;
    float acc[2][2][4] = {};

    auto buildA = [&](int c, int b) {
        const char* src = (const char*)&g_wTh[(CH_DOWN + c) * 4096 + px_b * 64 + l4 * 16];
        uint32_t d = sptr(&As[b * ROWSZ + px_b * SA + l4 * 16]);
        cpa16(d, src, 16); cpa16(d + 16, src + 16, 16);
    };
    auto buildB = [&](int c, int b) {
        uint32_t u[8];
#pragma unroll
        for (int j = 0; j < 8; j++) {
            int ch = c * 64 + l4 * 16 + 2 * j;
            float v0 = (p < HW) ? xb[(size_t)ch * HW + p] : 0.f;
            float v1 = (p < HW) ? xb[(size_t)(ch + 1) * HW + p] : 0.f;
            u[j] = b2u(__floats2bfloat162_rn(v0, v1));
        }
        uint4* d = (uint4*)&Bs[b * ROWSZ + px_b * SA + l4 * 16];
        d[0] = *(uint4*)&u[0]; d[1] = *(uint4*)&u[4];
    };
    buildA(0, 0); CP_COMMIT(); buildB(0, 0);
    CP_WAIT0();
    __syncthreads();
    for (int c = 0; c < 4; c++) {
        int cb = c & 1, nb = cb ^ 1;
        if (c + 1 < 4) { buildA(c + 1, nb); CP_COMMIT(); buildB(c + 1, nb); }
        mma64k(&As[cb * ROWSZ], &Bs[cb * ROWSZ], lane, wm, wn, acc);
        CP_WAIT0();
        __syncthreads();
    }
    int g = lane >> 2, tg = lane & 3;
    __nv_bfloat16* st = As;   // staging tile [px][ch], stride SA
#pragma unroll
    for (int mt = 0; mt < 2; mt++)
#pragma unroll
        for (int nq = 0; nq < 2; nq++) {
            int ppl = wn * 16 + nq * 8 + tg * 2;
            int pp = p0 + ppl;
#pragma unroll
            for (int h = 0; h < 2; h++) {
                int co = wm * 32 + mt * 16 + g + h * 8;
                float sc = g1[co] * rsqrtf(v1[co] + EPS);
                float sh = (bd[co] - m1[co]) * sc + b1[co];
                float vx = acc[mt][nq][h * 2] * sc + sh;
                float vy = acc[mt][nq][h * 2 + 1] * sc + sh;
                if (pp < HW) {
                    float2 v; v.x = vx; v.y = vy;
                    *(float2*)&g_out[((size_t)nt * 64 + co) * HW + pp] = v;
                }
                st[ppl * SA + co] = __float2bfloat16(vx);
                st[(ppl + 1) * SA + co] = __float2bfloat16(vy);
            }
        }
    __syncthreads();
    if (p < HW) {
        uint4 a0 = *(uint4*)&st[px_b * SA + l4 * 16];
        uint4 a1 = *(uint4*)&st[px_b * SA + l4 * 16 + 8];
        uint4* dst = (uint4*)&g_outT[((size_t)nt * HW + p) * 64 + l4 * 16];
        dst[0] = a0; dst[1] = a1;
    }
}

// ---------------- K3: border stats (T-sum inlined) ----------------
__global__ void k_tstats() {
    int id = blockIdx.x;
    int ci = id & 63, b = (id >> 6) & 7, s = id >> 9;
    int lane = threadIdx.x;
    float t = 0, r0 = 0, r27 = 0, c0 = 0, c27 = 0, cval = 0.f;
    for (int p = lane; p < HW; p += 32) {
        float v;
        if (s == 0) {
            const float* base = &g_out[((size_t)(b * 8) * 64 + ci) * HW + p];
            v = 0.f;
#pragma unroll
            for (int tt = 0; tt < 8; tt++) v += base[(size_t)tt * 64 * HW];
        } else {
            v = g_out[((size_t)(b * 8 + (s == 1 ? 0 : 7)) * 64 + ci) * HW + p];
        }
        int y = p / 28, x = p % 28;
        t += v;
        if (y == 0) r0 += v;
        if (y == 27) r27 += v;
        if (x == 0) c0 += v;
        if (x == 27) c27 += v;
        if (p == 0 || p == 27 || p == 756 || p == 783) cval = v;
    }
#pragma unroll
    for (int o = 16; o; o >>= 1) {
        t += __shfl_down_sync(0xffffffffu, t, o);
        r0 += __shfl_down_sync(0xffffffffu, r0, o);
        r27 += __shfl_down_sync(0xffffffffu, r27, o);
        c0 += __shfl_down_sync(0xffffffffu, c0, o);
        c27 += __shfl_down_sync(0xffffffffu, c27, o);
    }
    float o5v = __shfl_sync(0xffffffffu, cval, 0);
    float o6v = __shfl_sync(0xffffffffu, cval, 27);
    float o7v = __shfl_sync(0xffffffffu, cval, 20);
    float o8v = __shfl_sync(0xffffffffu, cval, 15);
    if (lane == 0) {
        float* o = &g_tstats[(size_t)id * 9];
        o[0] = t; o[1] = r0; o[2] = r27; o[3] = c0; o[4] = c27;
        o[5] = o5v; o[6] = o6v; o[7] = o7v; o[8] = o8v;
    }
}

// ---------------- K4: temporal branch -> gate slot 7 ----------------
__global__ void k_tgate(const float* __restrict__ tw, const float* __restrict__ tb,
                        const float* __restrict__ g, const float* __restrict__ bb,
                        const float* __restrict__ m, const float* __restrict__ v) {
    int b = blockIdx.x, co = blockIdx.y;
    int tid = threadIdx.x;
    int s = tid / 64, ci = tid % 64;
    __shared__ float red[6];
    const float* st = &g_tstats[((size_t)(s * 8 + b) * 64 + ci) * 9];
    float s0 = st[0], s1 = st[1], s2 = st[2], s3 = st[3], s4 = st[4];
    float s5 = st[5], s6 = st[6], s7 = st[7], s8 = st[8];
    const float* w = &tw[((size_t)(co * 64 + ci) * 3) * 9];
    float acc = 0.f;
#pragma unroll
    for (int k = 0; k < 9; k++) {
        int ky = k / 3, kx = k % 3;
        float rs = s0;
        if (ky == 2) rs -= s1;
        if (ky == 0) rs -= s2;
        if (kx == 2) rs -= s3;
        if (kx == 0) rs -= s4;
        if (ky == 2 && kx == 2) rs += s5;
        if (ky == 2 && kx == 0) rs += s6;
        if (ky == 0 && kx == 2) rs += s7;
        if (ky == 0 && kx == 0) rs += s8;
        float we = (s == 0) ? (w[k] + w[9 + k] + w[18 + k])
                            : (s == 1 ? -w[18 + k] : -w[k]);
        acc += we * rs;
    }
#pragma unroll
    for (int o = 16; o; o >>= 1) acc += __shfl_down_sync(0xffffffffu, acc, o);
    if ((tid & 31) == 0) red[tid >> 5] = acc;
    __syncthreads();
    if (tid == 0) {
        float tot = red[0] + red[1] + red[2] + red[3] + red[4] + red[5];
        float val = tot * (1.f / (8.f * 784.f)) + tb[co];
        float sc = g[co] * rsqrtf(v[co] + EPS);
        float tm = (val - m[co]) * sc + bb[co];
        g_cats[(b * 8 + 7) * 64 + co] = tm * 784.f;
    }
}

// ---------------- fused offset-conv + deform, TWO FRAMES per block ----------------
template <int KS>
__device__ __forceinline__ void fused_body(const float* __restrict__ bias,
                                           float* __restrict__ dst,
                                           __nv_bfloat16* As, __nv_bfloat16* Bs,
                                           float* off_s, int* bsi, int2* bt) {
    constexpr int K2 = KS * KS, PAD = KS / 2, MCO = 2 * K2;
    constexpr int WOFF_O = (KS == 3) ? CH_O3 : CH_O5;
    constexpr int WOFF_D = (KS == 3) ? CH_D3 : CH_D5;
    int bx = blockIdx.x, p0 = blockIdx.y * 64;
    int n0 = bx * 2, n1 = bx * 2 + 1;
    int f0 = (n0 / 7) * 8 + (n0 % 7) + 1;
    int f1 = (n1 / 7) * 8 + (n1 % 7) + 1;
    const __nv_bfloat16* srcT0 = g_outT + (size_t)f0 * HW * 64;
    const __nv_bfloat16* srcT1 = g_outT + (size_t)f1 * HW * 64;
    int tid = threadIdx.x, lane = tid & 31, w = tid >> 5, wm = w & 1, wn = w >> 1;
    int px_b = tid >> 2, l4 = tid & 3;       // buildA (weights, 64 rows)
    int px8 = tid >> 3, l8 = tid & 7;        // gathers: 8 lanes x 16B = full row
    int g = lane >> 2, tg = lane & 3;

    auto buildA = [&](int woff, int c, int b) {
        const char* src = (const char*)&g_wTh[(woff + c) * 4096 + px_b * 64 + l4 * 16];
        uint32_t d = sptr(&As[b * ROWSZ + px_b * SA + l4 * 16]);
        cpa16(d, src, 16); cpa16(d + 16, src + 16, 16);
    };

    // ---------- stage 1: offset-field conv (shared geometry, per-frame gather) ------
    float acc[2][4][4] = {};
    {
        auto tapcalc = [&](int k, int tbuf) {
            if (tid < 64) {
                int pq = p0 + tid;
                int yy = pq / 28 + k / KS - PAD, xs = pq % 28 + k % KS - PAD;
                bsi[tbuf * 64 + tid] =
                    (pq < HW && yy >= 0 && yy < 28 && xs >= 0 && xs < 28) ? yy * 28 + xs : -1;
            }
        };
        auto buildB = [&](int c, int b) {
            int buf = c & 1;
#pragma unroll
            for (int q = 0; q < 4; q++) {
                int px = px8 + q * 32;
                int si = bsi[buf * 64 + (px & 63)];
                const __nv_bfloat16* sT = (px >> 6) ? srcT1 : srcT0;
                const void* s = sT + (size_t)(si < 0 ? 0 : si) * 64 + l8 * 8;
                cpa16(sptr(&Bs[b * BROWSZ + px * SA + l8 * 8]), s, si >= 0 ? 16 : 0);
            }
        };
        tapcalc(0, 0);
        if (K2 > 1) tapcalc(1, 1);
        __syncthreads();
        buildA(WOFF_O, 0, 0); buildB(0, 0); CP_COMMIT();
        CP_WAIT0();
        __syncthreads();
        for (int c = 0; c < K2; c++) {
            int cb = c & 1, nb = cb ^ 1;
            if (c + 1 < K2) { buildA(WOFF_O, c + 1, nb); buildB(c + 1, nb); CP_COMMIT(); }
            mma128k(&As[cb * ROWSZ], &Bs[cb * BROWSZ], lane, wm, wn, acc);
            if (c + 2 < K2) tapcalc(c + 2, c & 1);
            CP_WAIT0();
            __syncthreads();
        }
#pragma unroll
        for (int mt = 0; mt < 2; mt++)
#pragma unroll
            for (int nq = 0; nq < 4; nq++) {
                int pp = wn * 32 + nq * 8 + tg * 2;
#pragma unroll
                for (int h = 0; h < 2; h++) {
                    int co = wm * 32 + mt * 16 + g + h * 8;
                    if (co < MCO) {
                        off_s[co * 130 + pp] = acc[mt][nq][h * 2] + bias[co];
                        off_s[co * 130 + pp + 1] = acc[mt][nq][h * 2 + 1] + bias[co];
                    }
                }
            }
    }
    __syncthreads();

    // ---------- stage 2: deformable conv ----------
#pragma unroll
    for (int mt = 0; mt < 2; mt++)
#pragma unroll
        for (int nt2 = 0; nt2 < 4; nt2++)
#pragma unroll
            for (int e = 0; e < 4; e++) acc[mt][nt2][e] = 0.f;
    {
        auto tapcalc = [&](int k, int tbuf) {
            if (tid < 128) {
                int pl = tid & 63;
                int pq = p0 + pl, pyq = pq / 28, pxq = pq % 28;
                float py = -100.f, pxx = -100.f;
                if (pq < HW) {
                    py = (float)(pyq + k / KS - PAD) + off_s[(2 * k) * 130 + tid];
                    pxx = (float)(pxq + k % KS - PAD) + off_s[(2 * k + 1) * 130 + tid];
                }
                float fy = floorf(py), fx = floorf(pxx);
                int y0 = (int)fy, x0 = (int)fx;
                float ly = py - fy, lx = pxx - fx;
#pragma unroll
                for (int t = 0; t < 4; t++) {
                    int iy = y0 + (t >> 1), ixx = x0 + (t & 1);
                    float wv = ((t >> 1) ? ly : 1.f - ly) * ((t & 1) ? lx : 1.f - lx);
                    bool valid = (iy >= 0) && (iy < 28) && (ixx >= 0) && (ixx < 28);
                    float wf = valid ? wv : 0.f;
                    int2 e;
                    e.x = min(max(iy, 0), 27) * 28 + min(max(ixx, 0), 27);
                    e.y = (int)b2u(__floats2bfloat162_rn(wf, wf));
                    bt[(tbuf * 128 + tid) * 4 + t] = e;
                }
            }
        };
        auto buildB = [&](int c, int b) {
            int buf = c & 1;
#pragma unroll
            for (int q = 0; q < 4; q++) {
                int px = px8 + q * 32;
                const int2* tp = &bt[(buf * 128 + px) * 4];
                int2 t0 = tp[0], t1 = tp[1], t2 = tp[2], t3 = tp[3];
                const __nv_bfloat16* base = ((px >> 6) ? srcT1 : srcT0) + l8 * 8;
                uint4 s0 = *(const uint4*)(base + (size_t)t0.x * 64);
                uint4 s1 = *(const uint4*)(base + (size_t)t1.x * 64);
                uint4 s2 = *(const uint4*)(base + (size_t)t2.x * 64);
                uint4 s3 = *(const uint4*)(base + (size_t)t3.x * 64);
                uint32_t* u0 = (uint32_t*)&s0;
                uint32_t* u1 = (uint32_t*)&s1;
                uint32_t* u2 = (uint32_t*)&s2;
                uint32_t* u3 = (uint32_t*)&s3;
                uint32_t o[4];
#pragma unroll
                for (int r = 0; r < 4; r++) {
                    __nv_bfloat162 v = __hmul2(u2b(u0[r]), u2b((uint32_t)t0.y));
                    v = __hfma2(u2b(u1[r]), u2b((uint32_t)t1.y), v);
                    v = __hfma2(u2b(u2[r]), u2b((uint32_t)t2.y), v);
                    v = __hfma2(u2b(u3[r]), u2b((uint32_t)t3.y), v);
                    o[r] = b2u(v);
                }
                *(uint4*)&Bs[b * BROWSZ + px * SA + l8 * 8] = *(uint4*)o;
            }
        };
        tapcalc(0, 0);
        if (K2 > 1) tapcalc(1, 1);
        __syncthreads();
        buildA(WOFF_D, 0, 0); CP_COMMIT(); buildB(0, 0);
        CP_WAIT0();
        __syncthreads();
        for (int c = 0; c < K2; c++) {
            int cb = c & 1, nb = cb ^ 1;
            if (c + 1 < K2) { buildA(WOFF_D, c + 1, nb); CP_COMMIT(); buildB(c + 1, nb); }
            mma128k(&As[cb * ROWSZ], &Bs[cb * BROWSZ], lane, wm, wn, acc);
            if (c + 2 < K2) tapcalc(c + 2, c & 1);
            CP_WAIT0();
            __syncthreads();
        }
#pragma unroll
        for (int mt = 0; mt < 2; mt++)
#pragma unroll
            for (int nq = 0; nq < 4; nq++) {
                int local = wn * 32 + nq * 8 + tg * 2;
                int half = local >> 6, pl = local & 63;
                int pp = p0 + pl;
                if (pp >= HW) continue;
                int nfr = bx * 2 + half;
#pragma unroll
                for (int h = 0; h < 2; h++) {
                    int co = wm * 32 + mt * 16 + g + h * 8;
                    size_t idx = ((size_t)nfr * 64 + co) * HW + pp;
                    float2 v;
                    v.x = acc[mt][nq][h * 2];
                    v.y = acc[mt][nq][h * 2 + 1];
                    *(float2*)&dst[idx] = v;
                }
            }
    }
}

// ---------------- K5: combined fused kernel (z=0 -> 5x5 first) ----------------
__global__ __launch_bounds__(256)
void k_fused_all(const float* __restrict__ bias3, const float* __restrict__ bias5) {
    extern __shared__ __align__(16) char smem_raw[];
    __nv_bfloat16* As = (__nv_bfloat16*)smem_raw;                 // 2*ROWSZ bf16
    __nv_bfloat16* Bs = As + 2 * ROWSZ;                           // 2*BROWSZ bf16
    float* off_s = (float*)(Bs + 2 * BROWSZ);                     // 50*130 floats
    int* bsi = (int*)(off_s + 50 * 130);                          // 128 ints
    int2* bt = (int2*)(bsi + 128);                                // 1024 int2
    if (blockIdx.z == 0) fused_body<5>(bias5, g_d2, As, Bs, off_s, bsi, bt);
    else                 fused_body<3>(bias3, g_d, As, Bs, off_s, bsi, bt);
}
#define FUSED_SMEM (2 * ROWSZ * 2 + 2 * BROWSZ * 2 + 50 * 130 * 4 + 128 * 4 + 1024 * 8)

// ---------------- K9: maxpool + 1x1 + bn3 + |diff| reduce ----------------
__global__ void k_davg(const float* __restrict__ w1, const float* __restrict__ b1,
                       const float* __restrict__ g3, const float* __restrict__ bb3,
                       const float* __restrict__ m3, const float* __restrict__ v3) {
    __shared__ float MP[64 * 68];
    int n = blockIdx.x, p0 = blockIdx.y * 64;
    int b = n / 7, t = n % 7;
    int f = b * 8 + t + 1, fp = b * 8 + t;
    const float* src = &g_out[(size_t)f * 64 * HW];
    const float* pre = &g_out[(size_t)fp * 64 * HW];
    int tid = threadIdx.x;
    for (int i = tid; i < 4096; i += 256) {
        int ci = i >> 6, px = i & 63, p = p0 + px;
        float mv = 0.f;
        if (p < HW) {
            int y = p / 28, x = p % 28;
            const float* s = src + ci * HW;
            mv = -1e30f;
            for (int dy = -1; dy <= 1; dy++) {
                int yy = y + dy;
                if (yy < 0 || yy >= 28) continue;
                for (int dx = -1; dx <= 1; dx++) {
                    int xx = x + dx;
                    if (xx < 0 || xx >= 28) continue;
                    mv = fmaxf(mv, s[yy * 28 + xx]);
                }
            }
        }
        MP[ci * 68 + px] = mv;
    }
    __syncthreads();
    int r = tid >> 4, c = tid & 15;
    float acc[4][4] = {};
    for (int ci = 0; ci < 64; ci++) {
        float a[4], bv[4];
#pragma unroll
        for (int i = 0; i < 4; i++) a[i] = w1[(r * 4 + i) * 64 + ci];
#pragma unroll
        for (int j = 0; j < 4; j++) bv[j] = MP[ci * 68 + c * 4 + j];
#pragma unroll
        for (int i = 0; i < 4; i++)
#pragma unroll
            for (int j = 0; j < 4; j++) acc[i][j] += a[i] * bv[j];
    }
    float sums[4];
#pragma unroll
    for (int i = 0; i < 4; i++) {
        int co = r * 4 + i;
        float sc = g3[co] * rsqrtf(v3[co] + EPS);
        float sh = (b1[co] - m3[co]) * sc + bb3[co];
        float s = 0.f;
#pragma unroll
        for (int j = 0; j < 4; j++) {
            int p = p0 + c * 4 + j;
            if (p < HW) {
                float davg = acc[i][j] * sc + sh;
                size_t idx = ((size_t)n * 64 + co) * HW + p;
                s += fabsf(g_d[idx] + g_d2[idx] + davg - 3.f * pre[co * HW + p]);
            }
        }
        sums[i] = s;
    }
#pragma unroll
    for (int o = 8; o; o >>= 1)
#pragma unroll
        for (int i = 0; i < 4; i++) sums[i] += __shfl_down_sync(0xffffffffu, sums[i], o);
    if (c == 0)
#pragma unroll
        for (int i = 0; i < 4; i++) atomicAdd(&g_cats[(b * 8 + t) * 64 + r * 4 + i], sums[i]);
}

// ---------------- K10: gate ----------------
__global__ void k_gate(const float* __restrict__ cw, const float* __restrict__ cb,
                       const float* __restrict__ g2, const float* __restrict__ b2,
                       const float* __restrict__ m2, const float* __restrict__ v2) {
    int nt = blockIdx.x;
    int co = threadIdx.x;
    __shared__ float mvec[64];
    if (co < 64) mvec[co] = g_cats[nt * 64 + co] * (1.f / 784.f);
    __syncthreads();
    float y = cb[co];
#pragma unroll 8
    for (int ci = 0; ci < 64; ci++) y += mvec[ci] * cw[co * 64 + ci];
    float sc = g2[co] * rsqrtf(v2[co] + EPS);
    y = (y - m2[co]) * sc + b2[co];
    float gate = 1.f / (1.f + expf(-y)) - 0.5f;
    g_gate[nt * 256 + co] = 1.f + gate;
}

// ---------------- K11: final elementwise ----------------
__global__ void k_final(const float* __restrict__ x, float* __restrict__ out) {
    int i = blockIdx.x * 256 + threadIdx.x;
    if (i >= 64 * 256 * (HW / 4)) return;
    int ch = i / (HW / 4);
    float gm = g_gate[ch];
    const float4* x4 = (const float4*)x;
    float4 v = x4[i];
    v.x *= gm; v.y *= gm; v.z *= gm; v.w *= gm;
    ((float4*)out)[i] = v;
}

// ---------------- launch ----------------
extern "C" void kernel_launch(void* const* d_in, const int* in_sizes, int n_in,
                              void* d_out, int out_size) {
    const float* x = (const float*)d_in[0];
    const float* w_down = (const float*)d_in[1];
    const float* b_down = (const float*)d_in[2];
    const float* bn1_g = (const float*)d_in[3];
    const float* bn1_b = (const float*)d_in[4];
    const float* bn1_m = (const float*)d_in[5];
    const float* bn1_v = (const float*)d_in[6];
    const float* tconv_w = (const float*)d_in[7];
    const float* tconv_b = (const float*)d_in[8];
    const float* bnt_g = (const float*)d_in[9];
    const float* bnt_b = (const float*)d_in[10];
    const float* bnt_m = (const float*)d_in[11];
    const float* bnt_v = (const float*)d_in[12];
    const float* off3_w = (const float*)d_in[13];
    const float* off3_b = (const float*)d_in[14];
    const float* def3_w = (const float*)d_in[15];
    const float* off5_w = (const float*)d_in[16];
    const float* off5_b = (const float*)d_in[17];
    const float* def5_w = (const float*)d_in[18];
    const float* conv1_w = (const float*)d_in[19];
    const float* conv1_b = (const float*)d_in[20];
    const float* bn3_g = (const float*)d_in[21];
    const float* bn3_b = (const float*)d_in[22];
    const float* bn3_m = (const float*)d_in[23];
    const float* bn3_v = (const float*)d_in[24];
    const float* conv_w = (const float*)d_in[25];
    const float* conv_b = (const float*)d_in[26];
    const float* bn2_g = (const float*)d_in[27];
    const float* bn2_b = (const float*)d_in[28];
    const float* bn2_m = (const float*)d_in[29];
    const float* bn2_v = (const float*)d_in[30];
    float* out = (float*)d_out;

    static int smem_set = 0;
    if (!smem_set) {
        cudaFuncSetAttribute(k_fused_all, cudaFuncAttributeMaxDynamicSharedMemorySize,
                             FUSED_SMEM);
        smem_set = 1;
    }

    k_prep<<<(CH_TOT * 4096 + 255) / 256, 256>>>(w_down, off3_w, def3_w, off5_w, def5_w);
    k_down<<<dim3(64, 13), 256>>>(x, bn1_g, bn1_b, bn1_m, bn1_v, b_down);
    k_tstats<<<3 * 8 * 64, 32>>>();
    k_fused_all<<<dim3(28, 13, 2), 256, FUSED_SMEM>>>(off3_b, off5_b);
    k_tgate<<<dim3(8, 64), 192>>>(tconv_w, tconv_b, bnt_g, bnt_b, bnt_m, bnt_v);
    k_davg<<<dim3(56, 13), 256>>>(conv1_w, conv1_b, bn3_g, bn3_b, bn3_m, bn3_v);
    k_gate<<<64, 256>>>(conv_w, conv_b, bn2_g, bn2_b, bn2_m, bn2_v);
    k_final<<<(64 * 256 * (HW / 4) + 255) / 256, 256>>>(x, out);
}